// round 8
// baseline (speedup 1.0000x reference)
#include <cuda_runtime.h>
#include <cuda_bf16.h>
#include <cstdint>

// Problem constants
#define BLROWS 4096   // B*L = 2*2048
#define LSEQ   2048
#define DMODEL 1024
#define DINNER 2048
#define DSTATE 16
#define DTRANK 64

typedef __nv_bfloat16 bf16;

// ---------------------------------------------------------------------------
// Scratch (device globals)
// ---------------------------------------------------------------------------
__device__ bf16  g_xsh[(size_t)BLROWS * DINNER];     // xs split (from GEMM1)
__device__ bf16  g_xsl[(size_t)BLROWS * DINNER];
__device__ float g_sres[(size_t)BLROWS * DINNER];    // silu(res)
__device__ float g_u  [(size_t)BLROWS * DINNER];     // silu(conv)
__device__ float g_dbc[(size_t)BLROWS * 96];
__device__ float g_dbc_part[(size_t)8 * BLROWS * 96];   // split-K partials
__device__ float g_delta[(size_t)BLROWS * DINNER];
__device__ float g_y [(size_t)BLROWS * DINNER];      // gated y (fp32)
// Transposed weights
__device__ float g_WinT [(size_t)4096 * 1024];                       // fp32
__device__ bf16  g_convTh[(size_t)4 * 2048 * 1024], g_convTl[(size_t)4 * 2048 * 1024];
__device__ float g_WoutT[(size_t)1024 * 2048];                       // fp32
__device__ float g_WdtT [(size_t)2048 * 64];                         // fp32

// ---------------------------------------------------------------------------
// PTX helpers
// ---------------------------------------------------------------------------
__device__ __forceinline__ uint32_t smem_u32(const void* p) {
    uint32_t a;
    asm("{ .reg .u64 t; cvta.to.shared.u64 t, %1; cvt.u32.u64 %0, t; }"
        : "=r"(a) : "l"(p));
    return a;
}
__device__ __forceinline__ void ldsm4(uint32_t* r, uint32_t addr) {
    asm volatile("ldmatrix.sync.aligned.m8n8.x4.shared.b16 {%0,%1,%2,%3}, [%4];"
        : "=r"(r[0]), "=r"(r[1]), "=r"(r[2]), "=r"(r[3]) : "r"(addr));
}
__device__ __forceinline__ void mma16816(
    float& d0, float& d1, float& d2, float& d3,
    uint32_t a0, uint32_t a1, uint32_t a2, uint32_t a3,
    uint32_t b0, uint32_t b1)
{
    asm volatile(
        "mma.sync.aligned.m16n8k16.row.col.f32.bf16.bf16.f32 "
        "{%0,%1,%2,%3}, {%4,%5,%6,%7}, {%8,%9}, {%0,%1,%2,%3};"
        : "+f"(d0), "+f"(d1), "+f"(d2), "+f"(d3)
        : "r"(a0), "r"(a1), "r"(a2), "r"(a3), "r"(b0), "r"(b1));
}
// bf16 2-way split of a pair of floats -> packed bf16x2 (hi, lo)
__device__ __forceinline__ void split2(float x, float y, uint32_t& hi, uint32_t& lo) {
    bf16 hx = __float2bfloat16_rn(x);
    bf16 hy = __float2bfloat16_rn(y);
    __nv_bfloat162 h; h.x = hx; h.y = hy;
    __nv_bfloat162 l = __floats2bfloat162_rn(x - __bfloat162float(hx),
                                             y - __bfloat162float(hy));
    hi = *reinterpret_cast<uint32_t*>(&h);
    lo = *reinterpret_cast<uint32_t*>(&l);
}
// SMEM tile row = 64B (32 bf16) in 4x16B chunks, xor-swizzled
__device__ __forceinline__ uint32_t swz(int row, int chunk) {
    return (uint32_t)((row << 6) + (((chunk ^ ((row >> 1) & 3)) & 3) << 4));
}
__device__ __forceinline__ float silu(float v) { return v / (1.f + __expf(-v)); }

// ---------------------------------------------------------------------------
// R3-proven bf16x3 mma GEMM (fp32 inputs, in-kernel split, single buffer,
// register prefetch, 2 syncs/iter).  C-tile[128,128] = A[M,K] @ Bt[N,K]^T.
// EPI: 0 fp32 store; 1 softplus+clip(+bias); 3 GEMM1 dual output.
// ---------------------------------------------------------------------------
template <int EPI>
__global__ __launch_bounds__(256) void mma_gemm(
    const float* __restrict__ A, int lda,
    const float* __restrict__ Bt, int ldb,
    float* __restrict__ C, int ldc,
    int K, const float* __restrict__ bias,
    bf16* __restrict__ xsh, bf16* __restrict__ xsl)
{
    __shared__ __align__(16) char sAhi[8192], sAlo[8192], sBhi[8192], sBlo[8192];

    const int tid  = threadIdx.x;
    const int lane = tid & 31;
    const int wid  = tid >> 5;
    const int wm   = wid & 1;
    const int wn   = wid >> 1;
    const int m0   = blockIdx.y * 128;
    const int n0   = blockIdx.x * 128;
    const int TOT  = K >> 5;

    const uint32_t aHiB = smem_u32(sAhi), aLoB = smem_u32(sAlo);
    const uint32_t bHiB = smem_u32(sBhi), bLoB = smem_u32(sBlo);

    const int a_r  = lane & 15;
    const int a_cx = lane >> 4;
    const int b_r  = (lane & 7) + ((lane >> 4) << 3);
    const int b_cx = (lane >> 3) & 1;

    float acc[4][4][4];
#pragma unroll
    for (int i = 0; i < 4; i++)
#pragma unroll
        for (int j = 0; j < 4; j++)
#pragma unroll
            for (int k = 0; k < 4; k++) acc[i][j][k] = 0.f;

    float4 pa[4], pb[4];

    auto load = [&](int kb) {
#pragma unroll
        for (int i = 0; i < 4; i++) {
            int idx = tid + i * 256;
            int row = idx >> 3, seg = idx & 7;
            pa[i] = *(const float4*)(A + (size_t)(m0 + row) * lda + kb * 32 + seg * 4);
            pb[i] = *(const float4*)(Bt + (size_t)(n0 + row) * ldb + kb * 32 + seg * 4);
        }
    };

    auto store = [&]() {
#pragma unroll
        for (int i = 0; i < 4; i++) {
            int idx = tid + i * 256;
            int row = idx >> 3, seg = idx & 7;
            uint32_t off = swz(row, seg >> 1) + (seg & 1) * 8;
            uint2 h, l;
            split2(pa[i].x, pa[i].y, h.x, l.x);
            split2(pa[i].z, pa[i].w, h.y, l.y);
            *(uint2*)(sAhi + off) = h;
            *(uint2*)(sAlo + off) = l;
            split2(pb[i].x, pb[i].y, h.x, l.x);
            split2(pb[i].z, pb[i].w, h.y, l.y);
            *(uint2*)(sBhi + off) = h;
            *(uint2*)(sBlo + off) = l;
        }
    };

    auto mma_block = [&]() {
#pragma unroll
        for (int ks = 0; ks < 2; ks++) {
            uint32_t a[4][4], bh[4][2], bx[4][2];
#pragma unroll
            for (int mf = 0; mf < 4; mf++) {
                int row = wm * 64 + mf * 16 + a_r;
                ldsm4(a[mf], aHiB + swz(row, ks * 2 + a_cx));
            }
#pragma unroll
            for (int p = 0; p < 2; p++) {
                int row = wn * 32 + p * 16 + b_r;
                uint32_t t[4];
                ldsm4(t, bHiB + swz(row, ks * 2 + b_cx));
                bh[p * 2][0] = t[0]; bh[p * 2][1] = t[1];
                bh[p * 2 + 1][0] = t[2]; bh[p * 2 + 1][1] = t[3];
            }
#pragma unroll
            for (int mf = 0; mf < 4; mf++)
#pragma unroll
                for (int nf = 0; nf < 4; nf++)
                    mma16816(acc[mf][nf][0], acc[mf][nf][1], acc[mf][nf][2], acc[mf][nf][3],
                             a[mf][0], a[mf][1], a[mf][2], a[mf][3], bh[nf][0], bh[nf][1]);
#pragma unroll
            for (int p = 0; p < 2; p++) {
                int row = wn * 32 + p * 16 + b_r;
                uint32_t t[4];
                ldsm4(t, bLoB + swz(row, ks * 2 + b_cx));
                bx[p * 2][0] = t[0]; bx[p * 2][1] = t[1];
                bx[p * 2 + 1][0] = t[2]; bx[p * 2 + 1][1] = t[3];
            }
#pragma unroll
            for (int mf = 0; mf < 4; mf++)
#pragma unroll
                for (int nf = 0; nf < 4; nf++)
                    mma16816(acc[mf][nf][0], acc[mf][nf][1], acc[mf][nf][2], acc[mf][nf][3],
                             a[mf][0], a[mf][1], a[mf][2], a[mf][3], bx[nf][0], bx[nf][1]);
#pragma unroll
            for (int mf = 0; mf < 4; mf++) {
                int row = wm * 64 + mf * 16 + a_r;
                ldsm4(a[mf], aLoB + swz(row, ks * 2 + a_cx));
            }
#pragma unroll
            for (int mf = 0; mf < 4; mf++)
#pragma unroll
                for (int nf = 0; nf < 4; nf++)
                    mma16816(acc[mf][nf][0], acc[mf][nf][1], acc[mf][nf][2], acc[mf][nf][3],
                             a[mf][0], a[mf][1], a[mf][2], a[mf][3], bh[nf][0], bh[nf][1]);
        }
    };

    load(0);
    store();
    __syncthreads();
    for (int it = 1; it < TOT; it++) {
        load(it);
        mma_block();
        __syncthreads();
        store();
        __syncthreads();
    }
    mma_block();

    // Epilogue
#pragma unroll
    for (int mf = 0; mf < 4; mf++) {
        int r = m0 + wm * 64 + mf * 16 + (lane >> 2);
#pragma unroll
        for (int nf = 0; nf < 4; nf++) {
            int c = n0 + wn * 32 + nf * 8 + (lane & 3) * 2;
            float v0 = acc[mf][nf][0], v1 = acc[mf][nf][1];
            float v2 = acc[mf][nf][2], v3 = acc[mf][nf][3];
            if (EPI == 1) {
                float b0 = bias[c], b1 = bias[c + 1];
                float x0 = v0 + b0, x1 = v1 + b1, x2 = v2 + b0, x3 = v3 + b1;
                v0 = fminf(fmaxf(fmaxf(x0, 0.f) + log1pf(__expf(-fabsf(x0))), 1e-3f), 0.1f);
                v1 = fminf(fmaxf(fmaxf(x1, 0.f) + log1pf(__expf(-fabsf(x1))), 1e-3f), 0.1f);
                v2 = fminf(fmaxf(fmaxf(x2, 0.f) + log1pf(__expf(-fabsf(x2))), 1e-3f), 0.1f);
                v3 = fminf(fmaxf(fmaxf(x3, 0.f) + log1pf(__expf(-fabsf(x3))), 1e-3f), 0.1f);
            }
            if (EPI == 3) {
                if (n0 < 2048) {     // xs half -> bf16 hi/lo
                    uint32_t h, l;
                    split2(v0, v1, h, l);
                    *(uint32_t*)(xsh + (size_t)r * 2048 + c) = h;
                    *(uint32_t*)(xsl + (size_t)r * 2048 + c) = l;
                    split2(v2, v3, h, l);
                    *(uint32_t*)(xsh + (size_t)(r + 8) * 2048 + c) = h;
                    *(uint32_t*)(xsl + (size_t)(r + 8) * 2048 + c) = l;
                } else {             // res half -> silu -> sres fp32
                    int cc = c - 2048;
                    *(float2*)(C + (size_t)r * ldc + cc)
                        = make_float2(silu(v0), silu(v1));
                    *(float2*)(C + (size_t)(r + 8) * ldc + cc)
                        = make_float2(silu(v2), silu(v3));
                }
            } else {
                *(float2*)(C + (size_t)r * ldc + c)       = make_float2(v0, v1);
                *(float2*)(C + (size_t)(r + 8) * ldc + c) = make_float2(v2, v3);
            }
        }
    }
}

// ---------------------------------------------------------------------------
// Halo-fused grouped causal conv (R6-proven).
// ---------------------------------------------------------------------------
#define CONV_STG  82944                      // 2*8704 (A hi/lo) + 4*16384 (B)
#define CONV_SMEM (2 * CONV_STG + 1024)

__global__ __launch_bounds__(256) void conv_halo(
    const bf16* __restrict__ Ah, const bf16* __restrict__ Al,   // xs [4096,2048]
    const bf16* __restrict__ Bh, const bf16* __restrict__ Bl,   // convT [4][2048,1024]
    const float* __restrict__ bias, float* __restrict__ U)
{
    extern __shared__ char dyn[];
    const uint32_t rawb = smem_u32(dyn);
    const uint32_t base = (rawb + 1023u) & ~1023u;
    char* tp = dyn + (base - rawb);

    const int tid  = threadIdx.x;
    const int lane = tid & 31;
    const int wid  = tid >> 5;
    const int wm   = wid & 1;
    const int wn   = wid >> 1;
    const int m0   = blockIdx.y * 128;
    const int n0   = blockIdx.x * 128;
    const int colbase = (n0 >= 1024) ? 1024 : 0;
    const bool headok = (m0 & (LSEQ - 1)) != 0;

    const int a_r  = lane & 15;
    const int a_cx = lane >> 4;
    const int b_r  = (lane & 7) + ((lane >> 4) << 3);
    const int b_cx = (lane >> 3) & 1;

    float acc[4][4][4];
#pragma unroll
    for (int i = 0; i < 4; i++)
#pragma unroll
        for (int j = 0; j < 4; j++)
#pragma unroll
            for (int k = 0; k < 4; k++) acc[i][j][k] = 0.f;

    uint4 sa[6], rb1[8], rb2[8];

    auto loadA = [&](int kb) {
#pragma unroll
        for (int i = 0; i < 3; i++) {
            int c = tid + i * 256;
            if (i < 2 || c < 524) {
                int row = c >> 2, seg = c & 3;
                bool valid = headok || (row >= 3);
                long grow = (long)m0 - 3 + row;
                if (valid) {
                    sa[i * 2]     = *(const uint4*)(Ah + grow * 2048 + colbase + kb * 32 + seg * 8);
                    sa[i * 2 + 1] = *(const uint4*)(Al + grow * 2048 + colbase + kb * 32 + seg * 8);
                } else {
                    sa[i * 2]     = make_uint4(0, 0, 0, 0);
                    sa[i * 2 + 1] = make_uint4(0, 0, 0, 0);
                }
            }
        }
    };
    auto stsA = [&](int s) {
        char* sb = tp + s * CONV_STG;
#pragma unroll
        for (int i = 0; i < 3; i++) {
            int c = tid + i * 256;
            if (i < 2 || c < 524) {
                int row = c >> 2, seg = c & 3;
                uint32_t off = swz(row, seg);
                *(uint4*)(sb + off)        = sa[i * 2];
                *(uint4*)(sb + 8704 + off) = sa[i * 2 + 1];
            }
        }
    };
    auto loadB = [&](int kb, int half, uint4* rb) {
#pragma unroll
        for (int i = 0; i < 4; i++) {
            int c = tid + i * 256;
            int tap = half * 2 + (c >> 9);
            int cc = c & 511;
            int row = cc >> 2, seg = cc & 3;
            const bf16* ph = Bh + (size_t)tap * 2048 * 1024 + (size_t)(n0 + row) * 1024 + kb * 32 + seg * 8;
            const bf16* pl = Bl + (size_t)tap * 2048 * 1024 + (size_t)(n0 + row) * 1024 + kb * 32 + seg * 8;
            rb[i * 2]     = *(const uint4*)ph;
            rb[i * 2 + 1] = *(const uint4*)pl;
        }
    };
    auto stsB = [&](int s, int half, uint4* rb) {
#pragma unroll
        for (int i = 0; i < 4; i++) {
            int c = tid + i * 256;
            int tap = half * 2 + (c >> 9);
            int cc = c & 511;
            int row = cc >> 2, seg = cc & 3;
            char* bb = tp + s * CONV_STG + 17408 + tap * 16384;
            uint32_t off = swz(row, seg);
            *(uint4*)(bb + off)        = rb[i * 2];
            *(uint4*)(bb + 8192 + off) = rb[i * 2 + 1];
        }
    };
    auto mma_tap = [&](int s, int tap) {
        uint32_t aHiB = base + (uint32_t)s * CONV_STG;
        uint32_t aLoB = aHiB + 8704;
        uint32_t bHiB = aHiB + 17408 + (uint32_t)tap * 16384;
        uint32_t bLoB = bHiB + 8192;
#pragma unroll
        for (int ks = 0; ks < 2; ks++) {
            uint32_t a[4][4], bh[4][2], bx[4][2];
#pragma unroll
            for (int mf = 0; mf < 4; mf++) {
                int row = wm * 64 + mf * 16 + a_r + tap;
                ldsm4(a[mf], aHiB + swz(row, ks * 2 + a_cx));
            }
#pragma unroll
            for (int p = 0; p < 2; p++) {
                int row = wn * 32 + p * 16 + b_r;
                uint32_t t[4];
                ldsm4(t, bHiB + swz(row, ks * 2 + b_cx));
                bh[p * 2][0] = t[0]; bh[p * 2][1] = t[1];
                bh[p * 2 + 1][0] = t[2]; bh[p * 2 + 1][1] = t[3];
            }
#pragma unroll
            for (int mf = 0; mf < 4; mf++)
#pragma unroll
                for (int nf = 0; nf < 4; nf++)
                    mma16816(acc[mf][nf][0], acc[mf][nf][1], acc[mf][nf][2], acc[mf][nf][3],
                             a[mf][0], a[mf][1], a[mf][2], a[mf][3], bh[nf][0], bh[nf][1]);
#pragma unroll
            for (int p = 0; p < 2; p++) {
                int row = wn * 32 + p * 16 + b_r;
                uint32_t t[4];
                ldsm4(t, bLoB + swz(row, ks * 2 + b_cx));
                bx[p * 2][0] = t[0]; bx[p * 2][1] = t[1];
                bx[p * 2 + 1][0] = t[2]; bx[p * 2 + 1][1] = t[3];
            }
#pragma unroll
            for (int mf = 0; mf < 4; mf++)
#pragma unroll
                for (int nf = 0; nf < 4; nf++)
                    mma16816(acc[mf][nf][0], acc[mf][nf][1], acc[mf][nf][2], acc[mf][nf][3],
                             a[mf][0], a[mf][1], a[mf][2], a[mf][3], bx[nf][0], bx[nf][1]);
#pragma unroll
            for (int mf = 0; mf < 4; mf++) {
                int row = wm * 64 + mf * 16 + a_r + tap;
                ldsm4(a[mf], aLoB + swz(row, ks * 2 + a_cx));
            }
#pragma unroll
            for (int mf = 0; mf < 4; mf++)
#pragma unroll
                for (int nf = 0; nf < 4; nf++)
                    mma16816(acc[mf][nf][0], acc[mf][nf][1], acc[mf][nf][2], acc[mf][nf][3],
                             a[mf][0], a[mf][1], a[mf][2], a[mf][3], bh[nf][0], bh[nf][1]);
        }
    };

    loadA(0); loadB(0, 0, rb1); loadB(0, 1, rb2);
    stsA(0); stsB(0, 0, rb1); stsB(0, 1, rb2);
    __syncthreads();

    for (int kb = 0; kb < 32; kb++) {
        int cur = kb & 1, nxt = cur ^ 1;
        bool more = (kb + 1) < 32;
        if (more) { loadA(kb + 1); loadB(kb + 1, 0, rb1); }
        mma_tap(cur, 0);
        mma_tap(cur, 1);
        if (more) { stsA(nxt); stsB(nxt, 0, rb1); loadB(kb + 1, 1, rb2); }
        mma_tap(cur, 2);
        mma_tap(cur, 3);
        if (more) stsB(nxt, 1, rb2);
        __syncthreads();
    }

#pragma unroll
    for (int mf = 0; mf < 4; mf++) {
        int r = m0 + wm * 64 + mf * 16 + (lane >> 2);
#pragma unroll
        for (int nf = 0; nf < 4; nf++) {
            int c = n0 + wn * 32 + nf * 8 + (lane & 3) * 2;
            float b0 = bias[c], b1 = bias[c + 1];
            float v0 = silu(acc[mf][nf][0] + b0);
            float v1 = silu(acc[mf][nf][1] + b1);
            float v2 = silu(acc[mf][nf][2] + b0);
            float v3 = silu(acc[mf][nf][3] + b1);
            *(float2*)(U + (size_t)r * DINNER + c)       = make_float2(v0, v1);
            *(float2*)(U + (size_t)(r + 8) * DINNER + c) = make_float2(v2, v3);
        }
    }
}

// ---------------------------------------------------------------------------
// Fused weight preprocessing (one launch)
// ---------------------------------------------------------------------------
__global__ __launch_bounds__(256) void fused_transpose(
    const float* __restrict__ Win, const float* __restrict__ convk,
    const float* __restrict__ Wout, const float* __restrict__ Wdt,
    float* __restrict__ winT, bf16* __restrict__ cTh, bf16* __restrict__ cTl,
    float* __restrict__ woutT, float* __restrict__ wdtT)
{
    int z = blockIdx.z;
    const float* src; int R, C;
    if (z == 0)      { src = Win;  R = 1024; C = 4096; }
    else if (z <= 4) { src = convk + (size_t)(z - 1) * 1024 * 2048; R = 1024; C = 2048; }
    else if (z == 5) { src = Wout; R = 2048; C = 1024; }
    else             { src = Wdt;  R = 64;   C = 2048; }
    if (blockIdx.x * 32 >= C || blockIdx.y * 32 >= R) return;

    __shared__ float t[32][33];
    int x = blockIdx.x * 32 + threadIdx.x;
#pragma unroll
    for (int j = 0; j < 4; j++) {
        int y = blockIdx.y * 32 + threadIdx.y + j * 8;
        t[threadIdx.y + j * 8][threadIdx.x] = src[(size_t)y * C + x];
    }
    __syncthreads();
    int x2 = blockIdx.y * 32 + threadIdx.x;
#pragma unroll
    for (int j = 0; j < 4; j++) {
        int y2 = blockIdx.x * 32 + threadIdx.y + j * 8;
        float v = t[threadIdx.x][threadIdx.y + j * 8];
        if (z == 0) {
            winT[(size_t)y2 * R + x2] = v;
        } else if (z <= 4) {
            size_t off = (size_t)(z - 1) * 2048 * 1024 + (size_t)y2 * R + x2;
            bf16 h = __float2bfloat16_rn(v);
            cTh[off] = h;
            cTl[off] = __float2bfloat16_rn(v - __bfloat162float(h));
        } else if (z == 5) {
            woutT[(size_t)y2 * R + x2] = v;
        } else {
            wdtT[(size_t)y2 * R + x2] = v;
        }
    }
}

// ---------------------------------------------------------------------------
// Split-K narrow GEMM, improved blocking: BM=64, acc[4][6] per thread.
// Grid (64 m-blocks, 8 k-chunks).  24 FMA per 10 LDS (was 12 per 8).
// ---------------------------------------------------------------------------
__global__ __launch_bounds__(256) void gemm_n96_partial(
    const float* __restrict__ A, const float* __restrict__ B,
    float* __restrict__ P)
{
    const int BK = 32, NN = 96, KC = 256, BM = 64;
    __shared__ float As[BK][BM];
    __shared__ float Bs[BK][NN];

    const int m0 = blockIdx.x * BM;
    const int kc = blockIdx.y;
    const int kbeg = kc * KC;
    const int tid = threadIdx.x;
    const int tx = tid & 15;     // 16 -> 6 cols each
    const int ty = tid >> 4;     // 16 -> 4 rows each

    float acc[4][6];
#pragma unroll
    for (int r = 0; r < 4; r++)
#pragma unroll
        for (int j = 0; j < 6; j++) acc[r][j] = 0.f;

    for (int k0 = kbeg; k0 < kbeg + KC; k0 += BK) {
        // A tile 64x32 fp32 -> 512 float4 chunks, 2 per thread, transposed
#pragma unroll
        for (int i = 0; i < 2; i++) {
            int idx = tid + i * 256;
            int row = idx >> 3;
            int cv  = (idx & 7) * 4;
            float4 a = *(const float4*)(A + (size_t)(m0 + row) * DINNER + k0 + cv);
            As[cv + 0][row] = a.x; As[cv + 1][row] = a.y;
            As[cv + 2][row] = a.z; As[cv + 3][row] = a.w;
        }
        // B tile 32x96 -> 768 float4, 3 per thread
#pragma unroll
        for (int i = 0; i < 3; i++) {
            int idx  = tid + i * 256;
            int rowB = idx / 24;
            int cv   = (idx % 24) * 4;
            *(float4*)(&Bs[rowB][cv]) =
                *(const float4*)(B + (size_t)(k0 + rowB) * NN + cv);
        }
        __syncthreads();
#pragma unroll
        for (int k = 0; k < BK; k++) {
            float a[4];
            *(float4*)a = *(const float4*)(&As[k][ty * 4]);
            float b[6];
            *(float2*)(b)     = *(const float2*)(&Bs[k][tx * 6]);
            *(float2*)(b + 2) = *(const float2*)(&Bs[k][tx * 6 + 2]);
            *(float2*)(b + 4) = *(const float2*)(&Bs[k][tx * 6 + 4]);
#pragma unroll
            for (int r = 0; r < 4; r++)
#pragma unroll
                for (int j = 0; j < 6; j++)
                    acc[r][j] = fmaf(a[r], b[j], acc[r][j]);
        }
        __syncthreads();
    }
    float* out = P + (size_t)kc * BLROWS * 96;
#pragma unroll
    for (int r = 0; r < 4; r++) {
        int m = m0 + ty * 4 + r;
#pragma unroll
        for (int j = 0; j < 6; j++)
            out[(size_t)m * 96 + tx * 6 + j] = acc[r][j];
    }
}

// Deterministic fixed-order reduction of 8 partials -> dbc
__global__ __launch_bounds__(256) void gemm_n96_reduce(
    const float* __restrict__ P, float* __restrict__ C)
{
    size_t i = ((size_t)blockIdx.x * blockDim.x + threadIdx.x) * 4;
    const size_t S = (size_t)BLROWS * 96;
    float4 s = *(const float4*)(P + i);
#pragma unroll
    for (int kc = 1; kc < 8; kc++) {
        float4 v = *(const float4*)(P + kc * S + i);
        s.x += v.x; s.y += v.y; s.z += v.z; s.w += v.w;
    }
    *(float4*)(C + i) = s;
}

// ---------------------------------------------------------------------------
// Selective scan with fused gate + explicit t+1 register prefetch.
// y = (scan + u*D) * silu(res)
// ---------------------------------------------------------------------------
__global__ __launch_bounds__(256) void scan_kernel(
    const float* __restrict__ delta, const float* __restrict__ u,
    const float* __restrict__ dbc, const float* __restrict__ A_log,
    const float* __restrict__ Dp, const float* __restrict__ sres,
    float* __restrict__ Y)
{
    int tid = blockIdx.x * blockDim.x + threadIdx.x;
    int n = tid & 15;
    int d = (tid >> 4) & (DINNER - 1);
    int b = tid >> 15;

    const float a  = -__expf(A_log[d * DSTATE + n]);
    const float Dd = Dp[d];

    const size_t rowbase = (size_t)b * LSEQ;
    const float* dptr = delta + rowbase * DINNER + d;
    const float* uptr = u     + rowbase * DINNER + d;
    const float* bc   = dbc   + rowbase * 96;
    const float* rp   = sres  + rowbase * DINNER + d;
    float*       yp   = Y     + rowbase * DINNER + d;

    // prefetch t=0
    float de0 = dptr[0];
    float uu0 = uptr[0];
    float Bn0 = bc[DTRANK + n];
    float Cn0 = bc[DTRANK + DSTATE + n];
    float rr0 = rp[0];

    float h = 0.f;
    for (int t = 0; t < LSEQ; t++) {
        // issue t+1 loads before using t values (off the critical path)
        int t1 = (t + 1 < LSEQ) ? (t + 1) : t;
        float de1 = dptr[(size_t)t1 * DINNER];
        float uu1 = uptr[(size_t)t1 * DINNER];
        float Bn1 = bc[t1 * 96 + DTRANK + n];
        float Cn1 = bc[t1 * 96 + DTRANK + DSTATE + n];
        float rr1 = rp[(size_t)t1 * DINNER];

        float dA = __expf(de0 * a);
        h = fmaf(dA, h, de0 * uu0 * Bn0);
        float p = h * Cn0;
        p += __shfl_xor_sync(0xffffffffu, p, 8);
        p += __shfl_xor_sync(0xffffffffu, p, 4);
        p += __shfl_xor_sync(0xffffffffu, p, 2);
        p += __shfl_xor_sync(0xffffffffu, p, 1);
        if (n == 0)
            yp[(size_t)t * DINNER] = fmaf(uu0, Dd, p) * rr0;

        de0 = de1; uu0 = uu1; Bn0 = Bn1; Cn0 = Cn1; rr0 = rr1;
    }
}

// ---------------------------------------------------------------------------
// Launch
// ---------------------------------------------------------------------------
extern "C" void kernel_launch(void* const* d_in, const int* in_sizes, int n_in,
                              void* d_out, int out_size)
{
    (void)in_sizes; (void)n_in; (void)out_size;
    const float* x      = (const float*)d_in[0];
    const float* W_in   = (const float*)d_in[1];
    const float* conv_k = (const float*)d_in[2];
    const float* conv_b = (const float*)d_in[3];
    const float* W_x    = (const float*)d_in[4];
    const float* W_dt   = (const float*)d_in[5];
    const float* b_dt   = (const float*)d_in[6];
    const float* A_log  = (const float*)d_in[7];
    const float* Dvec   = (const float*)d_in[8];
    const float* W_out  = (const float*)d_in[9];
    float* out = (float*)d_out;

    bf16 *xsh, *xsl, *convTh, *convTl;
    float *sres, *u, *dbc, *dbcp, *delta, *y, *winT, *woutT, *wdtT;
    cudaGetSymbolAddress((void**)&xsh,   g_xsh);
    cudaGetSymbolAddress((void**)&xsl,   g_xsl);
    cudaGetSymbolAddress((void**)&sres,  g_sres);
    cudaGetSymbolAddress((void**)&u,     g_u);
    cudaGetSymbolAddress((void**)&dbc,   g_dbc);
    cudaGetSymbolAddress((void**)&dbcp,  g_dbc_part);
    cudaGetSymbolAddress((void**)&delta, g_delta);
    cudaGetSymbolAddress((void**)&y,     g_y);
    cudaGetSymbolAddress((void**)&winT,  g_WinT);
    cudaGetSymbolAddress((void**)&convTh, g_convTh);
    cudaGetSymbolAddress((void**)&convTl, g_convTl);
    cudaGetSymbolAddress((void**)&woutT, g_WoutT);
    cudaGetSymbolAddress((void**)&wdtT,  g_WdtT);

    cudaFuncSetAttribute(conv_halo, cudaFuncAttributeMaxDynamicSharedMemorySize, CONV_SMEM);

    // 0) all weight preprocessing in ONE launch
    fused_transpose<<<dim3(128, 64, 7), dim3(32, 8)>>>(
        W_in, conv_k, W_out, W_dt, winT, convTh, convTl, woutT, wdtT);

    // 1) GEMM1: xs -> bf16 hi/lo,  silu(res) -> sres fp32
    mma_gemm<3><<<dim3(32, 32), 256>>>(
        x, DMODEL, winT, DMODEL, sres, DINNER, DMODEL, nullptr, xsh, xsl);

    // 2) halo-fused grouped causal conv + bias + silu -> u fp32
    conv_halo<<<dim3(16, 32), 256, CONV_SMEM>>>(
        xsh, xsl, convTh, convTl, conv_b, u);

    // 3) dbc = u @ W_x  (split-K 8x, BM=64 blocking + deterministic reduce)
    gemm_n96_partial<<<dim3(64, 8), 256>>>(u, W_x, dbcp);
    gemm_n96_reduce<<<(BLROWS * 96 / 4) / 256, 256>>>(dbcp, dbc);

    // 4) delta = clip(softplus(dt_raw @ W_dt + b_dt))
    mma_gemm<1><<<dim3(16, 32), 256>>>(
        dbc, 96, wdtT, DTRANK, delta, DINNER, DTRANK, b_dt, nullptr, nullptr);

    // 5) selective scan + fused gate -> y fp32
    scan_kernel<<<256, 256>>>(delta, u, dbc, A_log, Dvec, sres, y);

    // 6) out = y @ W_out
    mma_gemm<0><<<dim3(8, 32), 256>>>(
        y, DINNER, woutT, DINNER, out, DMODEL, DINNER, nullptr, nullptr, nullptr);
}

// round 9
// speedup vs baseline: 1.2174x; 1.2174x over previous
#include <cuda_runtime.h>
#include <cuda_bf16.h>
#include <cstdint>

// Problem constants
#define BLROWS 4096   // B*L = 2*2048
#define LSEQ   2048
#define DMODEL 1024
#define DINNER 2048
#define DSTATE 16
#define DTRANK 64

typedef __nv_bfloat16 bf16;

// ---------------------------------------------------------------------------
// Scratch (device globals)
// ---------------------------------------------------------------------------
__device__ bf16  g_xsh[(size_t)BLROWS * DINNER];     // xs split (from GEMM1)
__device__ bf16  g_xsl[(size_t)BLROWS * DINNER];
__device__ float g_sres[(size_t)BLROWS * DINNER];    // silu(res)
__device__ float g_u  [(size_t)BLROWS * DINNER];     // silu(conv)
__device__ float g_dbc[(size_t)BLROWS * 96];
__device__ float g_dbc_part[(size_t)8 * BLROWS * 96];   // split-K partials
__device__ float g_delta[(size_t)BLROWS * DINNER];
__device__ float g_y [(size_t)BLROWS * DINNER];      // gated y (fp32)
// Transposed weights
__device__ float g_WinT [(size_t)4096 * 1024];                       // fp32
__device__ bf16  g_convTh[(size_t)4 * 2048 * 1024], g_convTl[(size_t)4 * 2048 * 1024];
__device__ float g_WoutT[(size_t)1024 * 2048];                       // fp32
__device__ float g_WdtT [(size_t)2048 * 64];                         // fp32

// ---------------------------------------------------------------------------
// PTX helpers
// ---------------------------------------------------------------------------
__device__ __forceinline__ uint32_t smem_u32(const void* p) {
    uint32_t a;
    asm("{ .reg .u64 t; cvta.to.shared.u64 t, %1; cvt.u32.u64 %0, t; }"
        : "=r"(a) : "l"(p));
    return a;
}
__device__ __forceinline__ void ldsm4(uint32_t* r, uint32_t addr) {
    asm volatile("ldmatrix.sync.aligned.m8n8.x4.shared.b16 {%0,%1,%2,%3}, [%4];"
        : "=r"(r[0]), "=r"(r[1]), "=r"(r[2]), "=r"(r[3]) : "r"(addr));
}
__device__ __forceinline__ void mma16816(
    float& d0, float& d1, float& d2, float& d3,
    uint32_t a0, uint32_t a1, uint32_t a2, uint32_t a3,
    uint32_t b0, uint32_t b1)
{
    asm volatile(
        "mma.sync.aligned.m16n8k16.row.col.f32.bf16.bf16.f32 "
        "{%0,%1,%2,%3}, {%4,%5,%6,%7}, {%8,%9}, {%0,%1,%2,%3};"
        : "+f"(d0), "+f"(d1), "+f"(d2), "+f"(d3)
        : "r"(a0), "r"(a1), "r"(a2), "r"(a3), "r"(b0), "r"(b1));
}
// bf16 2-way split of a pair of floats -> packed bf16x2 (hi, lo)
__device__ __forceinline__ void split2(float x, float y, uint32_t& hi, uint32_t& lo) {
    bf16 hx = __float2bfloat16_rn(x);
    bf16 hy = __float2bfloat16_rn(y);
    __nv_bfloat162 h; h.x = hx; h.y = hy;
    __nv_bfloat162 l = __floats2bfloat162_rn(x - __bfloat162float(hx),
                                             y - __bfloat162float(hy));
    hi = *reinterpret_cast<uint32_t*>(&h);
    lo = *reinterpret_cast<uint32_t*>(&l);
}
// SMEM tile row = 64B (32 bf16) in 4x16B chunks, xor-swizzled
__device__ __forceinline__ uint32_t swz(int row, int chunk) {
    return (uint32_t)((row << 6) + (((chunk ^ ((row >> 1) & 3)) & 3) << 4));
}
__device__ __forceinline__ float silu(float v) { return v / (1.f + __expf(-v)); }

// ---------------------------------------------------------------------------
// R3-proven bf16x3 mma GEMM (fp32 inputs, in-kernel split, single buffer,
// register prefetch, 2 syncs/iter).  C-tile[128,128] = A[M,K] @ Bt[N,K]^T.
// EPI: 0 fp32 store; 1 softplus+clip(+bias); 3 GEMM1 dual output.
// ---------------------------------------------------------------------------
template <int EPI>
__global__ __launch_bounds__(256) void mma_gemm(
    const float* __restrict__ A, int lda,
    const float* __restrict__ Bt, int ldb,
    float* __restrict__ C, int ldc,
    int K, const float* __restrict__ bias,
    bf16* __restrict__ xsh, bf16* __restrict__ xsl)
{
    __shared__ __align__(16) char sAhi[8192], sAlo[8192], sBhi[8192], sBlo[8192];

    const int tid  = threadIdx.x;
    const int lane = tid & 31;
    const int wid  = tid >> 5;
    const int wm   = wid & 1;
    const int wn   = wid >> 1;
    const int m0   = blockIdx.y * 128;
    const int n0   = blockIdx.x * 128;
    const int TOT  = K >> 5;

    const uint32_t aHiB = smem_u32(sAhi), aLoB = smem_u32(sAlo);
    const uint32_t bHiB = smem_u32(sBhi), bLoB = smem_u32(sBlo);

    const int a_r  = lane & 15;
    const int a_cx = lane >> 4;
    const int b_r  = (lane & 7) + ((lane >> 4) << 3);
    const int b_cx = (lane >> 3) & 1;

    float acc[4][4][4];
#pragma unroll
    for (int i = 0; i < 4; i++)
#pragma unroll
        for (int j = 0; j < 4; j++)
#pragma unroll
            for (int k = 0; k < 4; k++) acc[i][j][k] = 0.f;

    float4 pa[4], pb[4];

    auto load = [&](int kb) {
#pragma unroll
        for (int i = 0; i < 4; i++) {
            int idx = tid + i * 256;
            int row = idx >> 3, seg = idx & 7;
            pa[i] = *(const float4*)(A + (size_t)(m0 + row) * lda + kb * 32 + seg * 4);
            pb[i] = *(const float4*)(Bt + (size_t)(n0 + row) * ldb + kb * 32 + seg * 4);
        }
    };

    auto store = [&]() {
#pragma unroll
        for (int i = 0; i < 4; i++) {
            int idx = tid + i * 256;
            int row = idx >> 3, seg = idx & 7;
            uint32_t off = swz(row, seg >> 1) + (seg & 1) * 8;
            uint2 h, l;
            split2(pa[i].x, pa[i].y, h.x, l.x);
            split2(pa[i].z, pa[i].w, h.y, l.y);
            *(uint2*)(sAhi + off) = h;
            *(uint2*)(sAlo + off) = l;
            split2(pb[i].x, pb[i].y, h.x, l.x);
            split2(pb[i].z, pb[i].w, h.y, l.y);
            *(uint2*)(sBhi + off) = h;
            *(uint2*)(sBlo + off) = l;
        }
    };

    auto mma_block = [&]() {
#pragma unroll
        for (int ks = 0; ks < 2; ks++) {
            uint32_t a[4][4], bh[4][2], bx[4][2];
#pragma unroll
            for (int mf = 0; mf < 4; mf++) {
                int row = wm * 64 + mf * 16 + a_r;
                ldsm4(a[mf], aHiB + swz(row, ks * 2 + a_cx));
            }
#pragma unroll
            for (int p = 0; p < 2; p++) {
                int row = wn * 32 + p * 16 + b_r;
                uint32_t t[4];
                ldsm4(t, bHiB + swz(row, ks * 2 + b_cx));
                bh[p * 2][0] = t[0]; bh[p * 2][1] = t[1];
                bh[p * 2 + 1][0] = t[2]; bh[p * 2 + 1][1] = t[3];
            }
#pragma unroll
            for (int mf = 0; mf < 4; mf++)
#pragma unroll
                for (int nf = 0; nf < 4; nf++)
                    mma16816(acc[mf][nf][0], acc[mf][nf][1], acc[mf][nf][2], acc[mf][nf][3],
                             a[mf][0], a[mf][1], a[mf][2], a[mf][3], bh[nf][0], bh[nf][1]);
#pragma unroll
            for (int p = 0; p < 2; p++) {
                int row = wn * 32 + p * 16 + b_r;
                uint32_t t[4];
                ldsm4(t, bLoB + swz(row, ks * 2 + b_cx));
                bx[p * 2][0] = t[0]; bx[p * 2][1] = t[1];
                bx[p * 2 + 1][0] = t[2]; bx[p * 2 + 1][1] = t[3];
            }
#pragma unroll
            for (int mf = 0; mf < 4; mf++)
#pragma unroll
                for (int nf = 0; nf < 4; nf++)
                    mma16816(acc[mf][nf][0], acc[mf][nf][1], acc[mf][nf][2], acc[mf][nf][3],
                             a[mf][0], a[mf][1], a[mf][2], a[mf][3], bx[nf][0], bx[nf][1]);
#pragma unroll
            for (int mf = 0; mf < 4; mf++) {
                int row = wm * 64 + mf * 16 + a_r;
                ldsm4(a[mf], aLoB + swz(row, ks * 2 + a_cx));
            }
#pragma unroll
            for (int mf = 0; mf < 4; mf++)
#pragma unroll
                for (int nf = 0; nf < 4; nf++)
                    mma16816(acc[mf][nf][0], acc[mf][nf][1], acc[mf][nf][2], acc[mf][nf][3],
                             a[mf][0], a[mf][1], a[mf][2], a[mf][3], bh[nf][0], bh[nf][1]);
        }
    };

    load(0);
    store();
    __syncthreads();
    for (int it = 1; it < TOT; it++) {
        load(it);
        mma_block();
        __syncthreads();
        store();
        __syncthreads();
    }
    mma_block();

    // Epilogue
#pragma unroll
    for (int mf = 0; mf < 4; mf++) {
        int r = m0 + wm * 64 + mf * 16 + (lane >> 2);
#pragma unroll
        for (int nf = 0; nf < 4; nf++) {
            int c = n0 + wn * 32 + nf * 8 + (lane & 3) * 2;
            float v0 = acc[mf][nf][0], v1 = acc[mf][nf][1];
            float v2 = acc[mf][nf][2], v3 = acc[mf][nf][3];
            if (EPI == 1) {
                float b0 = bias[c], b1 = bias[c + 1];
                float x0 = v0 + b0, x1 = v1 + b1, x2 = v2 + b0, x3 = v3 + b1;
                v0 = fminf(fmaxf(fmaxf(x0, 0.f) + log1pf(__expf(-fabsf(x0))), 1e-3f), 0.1f);
                v1 = fminf(fmaxf(fmaxf(x1, 0.f) + log1pf(__expf(-fabsf(x1))), 1e-3f), 0.1f);
                v2 = fminf(fmaxf(fmaxf(x2, 0.f) + log1pf(__expf(-fabsf(x2))), 1e-3f), 0.1f);
                v3 = fminf(fmaxf(fmaxf(x3, 0.f) + log1pf(__expf(-fabsf(x3))), 1e-3f), 0.1f);
            }
            if (EPI == 3) {
                if (n0 < 2048) {     // xs half -> bf16 hi/lo
                    uint32_t h, l;
                    split2(v0, v1, h, l);
                    *(uint32_t*)(xsh + (size_t)r * 2048 + c) = h;
                    *(uint32_t*)(xsl + (size_t)r * 2048 + c) = l;
                    split2(v2, v3, h, l);
                    *(uint32_t*)(xsh + (size_t)(r + 8) * 2048 + c) = h;
                    *(uint32_t*)(xsl + (size_t)(r + 8) * 2048 + c) = l;
                } else {             // res half -> silu -> sres fp32
                    int cc = c - 2048;
                    *(float2*)(C + (size_t)r * ldc + cc)
                        = make_float2(silu(v0), silu(v1));
                    *(float2*)(C + (size_t)(r + 8) * ldc + cc)
                        = make_float2(silu(v2), silu(v3));
                }
            } else {
                *(float2*)(C + (size_t)r * ldc + c)       = make_float2(v0, v1);
                *(float2*)(C + (size_t)(r + 8) * ldc + c) = make_float2(v2, v3);
            }
        }
    }
}

// ---------------------------------------------------------------------------
// Halo-fused grouped causal conv (R6-proven).
// ---------------------------------------------------------------------------
#define CONV_STG  82944                      // 2*8704 (A hi/lo) + 4*16384 (B)
#define CONV_SMEM (2 * CONV_STG + 1024)

__global__ __launch_bounds__(256) void conv_halo(
    const bf16* __restrict__ Ah, const bf16* __restrict__ Al,   // xs [4096,2048]
    const bf16* __restrict__ Bh, const bf16* __restrict__ Bl,   // convT [4][2048,1024]
    const float* __restrict__ bias, float* __restrict__ U)
{
    extern __shared__ char dyn[];
    const uint32_t rawb = smem_u32(dyn);
    const uint32_t base = (rawb + 1023u) & ~1023u;
    char* tp = dyn + (base - rawb);

    const int tid  = threadIdx.x;
    const int lane = tid & 31;
    const int wid  = tid >> 5;
    const int wm   = wid & 1;
    const int wn   = wid >> 1;
    const int m0   = blockIdx.y * 128;
    const int n0   = blockIdx.x * 128;
    const int colbase = (n0 >= 1024) ? 1024 : 0;
    const bool headok = (m0 & (LSEQ - 1)) != 0;

    const int a_r  = lane & 15;
    const int a_cx = lane >> 4;
    const int b_r  = (lane & 7) + ((lane >> 4) << 3);
    const int b_cx = (lane >> 3) & 1;

    float acc[4][4][4];
#pragma unroll
    for (int i = 0; i < 4; i++)
#pragma unroll
        for (int j = 0; j < 4; j++)
#pragma unroll
            for (int k = 0; k < 4; k++) acc[i][j][k] = 0.f;

    uint4 sa[6], rb1[8], rb2[8];

    auto loadA = [&](int kb) {
#pragma unroll
        for (int i = 0; i < 3; i++) {
            int c = tid + i * 256;
            if (i < 2 || c < 524) {
                int row = c >> 2, seg = c & 3;
                bool valid = headok || (row >= 3);
                long grow = (long)m0 - 3 + row;
                if (valid) {
                    sa[i * 2]     = *(const uint4*)(Ah + grow * 2048 + colbase + kb * 32 + seg * 8);
                    sa[i * 2 + 1] = *(const uint4*)(Al + grow * 2048 + colbase + kb * 32 + seg * 8);
                } else {
                    sa[i * 2]     = make_uint4(0, 0, 0, 0);
                    sa[i * 2 + 1] = make_uint4(0, 0, 0, 0);
                }
            }
        }
    };
    auto stsA = [&](int s) {
        char* sb = tp + s * CONV_STG;
#pragma unroll
        for (int i = 0; i < 3; i++) {
            int c = tid + i * 256;
            if (i < 2 || c < 524) {
                int row = c >> 2, seg = c & 3;
                uint32_t off = swz(row, seg);
                *(uint4*)(sb + off)        = sa[i * 2];
                *(uint4*)(sb + 8704 + off) = sa[i * 2 + 1];
            }
        }
    };
    auto loadB = [&](int kb, int half, uint4* rb) {
#pragma unroll
        for (int i = 0; i < 4; i++) {
            int c = tid + i * 256;
            int tap = half * 2 + (c >> 9);
            int cc = c & 511;
            int row = cc >> 2, seg = cc & 3;
            const bf16* ph = Bh + (size_t)tap * 2048 * 1024 + (size_t)(n0 + row) * 1024 + kb * 32 + seg * 8;
            const bf16* pl = Bl + (size_t)tap * 2048 * 1024 + (size_t)(n0 + row) * 1024 + kb * 32 + seg * 8;
            rb[i * 2]     = *(const uint4*)ph;
            rb[i * 2 + 1] = *(const uint4*)pl;
        }
    };
    auto stsB = [&](int s, int half, uint4* rb) {
#pragma unroll
        for (int i = 0; i < 4; i++) {
            int c = tid + i * 256;
            int tap = half * 2 + (c >> 9);
            int cc = c & 511;
            int row = cc >> 2, seg = cc & 3;
            char* bb = tp + s * CONV_STG + 17408 + tap * 16384;
            uint32_t off = swz(row, seg);
            *(uint4*)(bb + off)        = rb[i * 2];
            *(uint4*)(bb + 8192 + off) = rb[i * 2 + 1];
        }
    };
    auto mma_tap = [&](int s, int tap) {
        uint32_t aHiB = base + (uint32_t)s * CONV_STG;
        uint32_t aLoB = aHiB + 8704;
        uint32_t bHiB = aHiB + 17408 + (uint32_t)tap * 16384;
        uint32_t bLoB = bHiB + 8192;
#pragma unroll
        for (int ks = 0; ks < 2; ks++) {
            uint32_t a[4][4], bh[4][2], bx[4][2];
#pragma unroll
            for (int mf = 0; mf < 4; mf++) {
                int row = wm * 64 + mf * 16 + a_r + tap;
                ldsm4(a[mf], aHiB + swz(row, ks * 2 + a_cx));
            }
#pragma unroll
            for (int p = 0; p < 2; p++) {
                int row = wn * 32 + p * 16 + b_r;
                uint32_t t[4];
                ldsm4(t, bHiB + swz(row, ks * 2 + b_cx));
                bh[p * 2][0] = t[0]; bh[p * 2][1] = t[1];
                bh[p * 2 + 1][0] = t[2]; bh[p * 2 + 1][1] = t[3];
            }
#pragma unroll
            for (int mf = 0; mf < 4; mf++)
#pragma unroll
                for (int nf = 0; nf < 4; nf++)
                    mma16816(acc[mf][nf][0], acc[mf][nf][1], acc[mf][nf][2], acc[mf][nf][3],
                             a[mf][0], a[mf][1], a[mf][2], a[mf][3], bh[nf][0], bh[nf][1]);
#pragma unroll
            for (int p = 0; p < 2; p++) {
                int row = wn * 32 + p * 16 + b_r;
                uint32_t t[4];
                ldsm4(t, bLoB + swz(row, ks * 2 + b_cx));
                bx[p * 2][0] = t[0]; bx[p * 2][1] = t[1];
                bx[p * 2 + 1][0] = t[2]; bx[p * 2 + 1][1] = t[3];
            }
#pragma unroll
            for (int mf = 0; mf < 4; mf++)
#pragma unroll
                for (int nf = 0; nf < 4; nf++)
                    mma16816(acc[mf][nf][0], acc[mf][nf][1], acc[mf][nf][2], acc[mf][nf][3],
                             a[mf][0], a[mf][1], a[mf][2], a[mf][3], bx[nf][0], bx[nf][1]);
#pragma unroll
            for (int mf = 0; mf < 4; mf++) {
                int row = wm * 64 + mf * 16 + a_r + tap;
                ldsm4(a[mf], aLoB + swz(row, ks * 2 + a_cx));
            }
#pragma unroll
            for (int mf = 0; mf < 4; mf++)
#pragma unroll
                for (int nf = 0; nf < 4; nf++)
                    mma16816(acc[mf][nf][0], acc[mf][nf][1], acc[mf][nf][2], acc[mf][nf][3],
                             a[mf][0], a[mf][1], a[mf][2], a[mf][3], bh[nf][0], bh[nf][1]);
        }
    };

    loadA(0); loadB(0, 0, rb1); loadB(0, 1, rb2);
    stsA(0); stsB(0, 0, rb1); stsB(0, 1, rb2);
    __syncthreads();

    for (int kb = 0; kb < 32; kb++) {
        int cur = kb & 1, nxt = cur ^ 1;
        bool more = (kb + 1) < 32;
        if (more) { loadA(kb + 1); loadB(kb + 1, 0, rb1); }
        mma_tap(cur, 0);
        mma_tap(cur, 1);
        if (more) { stsA(nxt); stsB(nxt, 0, rb1); loadB(kb + 1, 1, rb2); }
        mma_tap(cur, 2);
        mma_tap(cur, 3);
        if (more) stsB(nxt, 1, rb2);
        __syncthreads();
    }

#pragma unroll
    for (int mf = 0; mf < 4; mf++) {
        int r = m0 + wm * 64 + mf * 16 + (lane >> 2);
#pragma unroll
        for (int nf = 0; nf < 4; nf++) {
            int c = n0 + wn * 32 + nf * 8 + (lane & 3) * 2;
            float b0 = bias[c], b1 = bias[c + 1];
            float v0 = silu(acc[mf][nf][0] + b0);
            float v1 = silu(acc[mf][nf][1] + b1);
            float v2 = silu(acc[mf][nf][2] + b0);
            float v3 = silu(acc[mf][nf][3] + b1);
            *(float2*)(U + (size_t)r * DINNER + c)       = make_float2(v0, v1);
            *(float2*)(U + (size_t)(r + 8) * DINNER + c) = make_float2(v2, v3);
        }
    }
}

// ---------------------------------------------------------------------------
// Fused weight preprocessing (one launch)
// ---------------------------------------------------------------------------
__global__ __launch_bounds__(256) void fused_transpose(
    const float* __restrict__ Win, const float* __restrict__ convk,
    const float* __restrict__ Wout, const float* __restrict__ Wdt,
    float* __restrict__ winT, bf16* __restrict__ cTh, bf16* __restrict__ cTl,
    float* __restrict__ woutT, float* __restrict__ wdtT)
{
    int z = blockIdx.z;
    const float* src; int R, C;
    if (z == 0)      { src = Win;  R = 1024; C = 4096; }
    else if (z <= 4) { src = convk + (size_t)(z - 1) * 1024 * 2048; R = 1024; C = 2048; }
    else if (z == 5) { src = Wout; R = 2048; C = 1024; }
    else             { src = Wdt;  R = 64;   C = 2048; }
    if (blockIdx.x * 32 >= C || blockIdx.y * 32 >= R) return;

    __shared__ float t[32][33];
    int x = blockIdx.x * 32 + threadIdx.x;
#pragma unroll
    for (int j = 0; j < 4; j++) {
        int y = blockIdx.y * 32 + threadIdx.y + j * 8;
        t[threadIdx.y + j * 8][threadIdx.x] = src[(size_t)y * C + x];
    }
    __syncthreads();
    int x2 = blockIdx.y * 32 + threadIdx.x;
#pragma unroll
    for (int j = 0; j < 4; j++) {
        int y2 = blockIdx.x * 32 + threadIdx.y + j * 8;
        float v = t[threadIdx.x][threadIdx.y + j * 8];
        if (z == 0) {
            winT[(size_t)y2 * R + x2] = v;
        } else if (z <= 4) {
            size_t off = (size_t)(z - 1) * 2048 * 1024 + (size_t)y2 * R + x2;
            bf16 h = __float2bfloat16_rn(v);
            cTh[off] = h;
            cTl[off] = __float2bfloat16_rn(v - __bfloat162float(h));
        } else if (z == 5) {
            woutT[(size_t)y2 * R + x2] = v;
        } else {
            wdtT[(size_t)y2 * R + x2] = v;
        }
    }
}

// ---------------------------------------------------------------------------
// Split-K narrow GEMM, BM=64 blocking (R8-measured win: 75 -> 62 us).
// Grid (64 m-blocks, 8 k-chunks) + deterministic reduce.
// ---------------------------------------------------------------------------
__global__ __launch_bounds__(256) void gemm_n96_partial(
    const float* __restrict__ A, const float* __restrict__ B,
    float* __restrict__ P)
{
    const int BK = 32, NN = 96, KC = 256, BM = 64;
    __shared__ float As[BK][BM];
    __shared__ float Bs[BK][NN];

    const int m0 = blockIdx.x * BM;
    const int kc = blockIdx.y;
    const int kbeg = kc * KC;
    const int tid = threadIdx.x;
    const int tx = tid & 15;     // 16 -> 6 cols each
    const int ty = tid >> 4;     // 16 -> 4 rows each

    float acc[4][6];
#pragma unroll
    for (int r = 0; r < 4; r++)
#pragma unroll
        for (int j = 0; j < 6; j++) acc[r][j] = 0.f;

    for (int k0 = kbeg; k0 < kbeg + KC; k0 += BK) {
        // A tile 64x32 fp32 -> 512 float4 chunks, 2 per thread, transposed
#pragma unroll
        for (int i = 0; i < 2; i++) {
            int idx = tid + i * 256;
            int row = idx >> 3;
            int cv  = (idx & 7) * 4;
            float4 a = *(const float4*)(A + (size_t)(m0 + row) * DINNER + k0 + cv);
            As[cv + 0][row] = a.x; As[cv + 1][row] = a.y;
            As[cv + 2][row] = a.z; As[cv + 3][row] = a.w;
        }
        // B tile 32x96 -> 768 float4, 3 per thread
#pragma unroll
        for (int i = 0; i < 3; i++) {
            int idx  = tid + i * 256;
            int rowB = idx / 24;
            int cv   = (idx % 24) * 4;
            *(float4*)(&Bs[rowB][cv]) =
                *(const float4*)(B + (size_t)(k0 + rowB) * NN + cv);
        }
        __syncthreads();
#pragma unroll
        for (int k = 0; k < BK; k++) {
            float a[4];
            *(float4*)a = *(const float4*)(&As[k][ty * 4]);
            float b[6];
            *(float2*)(b)     = *(const float2*)(&Bs[k][tx * 6]);
            *(float2*)(b + 2) = *(const float2*)(&Bs[k][tx * 6 + 2]);
            *(float2*)(b + 4) = *(const float2*)(&Bs[k][tx * 6 + 4]);
#pragma unroll
            for (int r = 0; r < 4; r++)
#pragma unroll
                for (int j = 0; j < 6; j++)
                    acc[r][j] = fmaf(a[r], b[j], acc[r][j]);
        }
        __syncthreads();
    }
    float* out = P + (size_t)kc * BLROWS * 96;
#pragma unroll
    for (int r = 0; r < 4; r++) {
        int m = m0 + ty * 4 + r;
#pragma unroll
        for (int j = 0; j < 6; j++)
            out[(size_t)m * 96 + tx * 6 + j] = acc[r][j];
    }
}

// Deterministic fixed-order reduction of 8 partials -> dbc
__global__ __launch_bounds__(256) void gemm_n96_reduce(
    const float* __restrict__ P, float* __restrict__ C)
{
    size_t i = ((size_t)blockIdx.x * blockDim.x + threadIdx.x) * 4;
    const size_t S = (size_t)BLROWS * 96;
    float4 s = *(const float4*)(P + i);
#pragma unroll
    for (int kc = 1; kc < 8; kc++) {
        float4 v = *(const float4*)(P + kc * S + i);
        s.x += v.x; s.y += v.y; s.z += v.z; s.w += v.w;
    }
    *(float4*)(C + i) = s;
}

// ---------------------------------------------------------------------------
// Selective scan with fused gate (R7-proven loop body — no manual prefetch).
// y = (scan + u*D) * silu(res)
// ---------------------------------------------------------------------------
__global__ __launch_bounds__(256) void scan_kernel(
    const float* __restrict__ delta, const float* __restrict__ u,
    const float* __restrict__ dbc, const float* __restrict__ A_log,
    const float* __restrict__ Dp, const float* __restrict__ sres,
    float* __restrict__ Y)
{
    int tid = blockIdx.x * blockDim.x + threadIdx.x;
    int n = tid & 15;
    int d = (tid >> 4) & (DINNER - 1);
    int b = tid >> 15;

    const float a  = -__expf(A_log[d * DSTATE + n]);
    const float Dd = Dp[d];

    const size_t rowbase = (size_t)b * LSEQ;
    const float* dptr = delta + rowbase * DINNER + d;
    const float* uptr = u     + rowbase * DINNER + d;
    const float* bc   = dbc   + rowbase * 96;
    const float* rp   = sres  + rowbase * DINNER + d;
    float*       yp   = Y     + rowbase * DINNER + d;

    float h = 0.f;
    for (int t = 0; t < LSEQ; t++) {
        float de = dptr[(size_t)t * DINNER];
        float uu = uptr[(size_t)t * DINNER];
        float Bn = bc[t * 96 + DTRANK + n];
        float Cn = bc[t * 96 + DTRANK + DSTATE + n];
        float dA = __expf(de * a);
        h = fmaf(dA, h, de * uu * Bn);
        float p = h * Cn;
        p += __shfl_xor_sync(0xffffffffu, p, 8);
        p += __shfl_xor_sync(0xffffffffu, p, 4);
        p += __shfl_xor_sync(0xffffffffu, p, 2);
        p += __shfl_xor_sync(0xffffffffu, p, 1);
        if (n == 0)
            yp[(size_t)t * DINNER] = fmaf(uu, Dd, p) * rp[(size_t)t * DINNER];
    }
}

// ---------------------------------------------------------------------------
// Launch
// ---------------------------------------------------------------------------
extern "C" void kernel_launch(void* const* d_in, const int* in_sizes, int n_in,
                              void* d_out, int out_size)
{
    (void)in_sizes; (void)n_in; (void)out_size;
    const float* x      = (const float*)d_in[0];
    const float* W_in   = (const float*)d_in[1];
    const float* conv_k = (const float*)d_in[2];
    const float* conv_b = (const float*)d_in[3];
    const float* W_x    = (const float*)d_in[4];
    const float* W_dt   = (const float*)d_in[5];
    const float* b_dt   = (const float*)d_in[6];
    const float* A_log  = (const float*)d_in[7];
    const float* Dvec   = (const float*)d_in[8];
    const float* W_out  = (const float*)d_in[9];
    float* out = (float*)d_out;

    bf16 *xsh, *xsl, *convTh, *convTl;
    float *sres, *u, *dbc, *dbcp, *delta, *y, *winT, *woutT, *wdtT;
    cudaGetSymbolAddress((void**)&xsh,   g_xsh);
    cudaGetSymbolAddress((void**)&xsl,   g_xsl);
    cudaGetSymbolAddress((void**)&sres,  g_sres);
    cudaGetSymbolAddress((void**)&u,     g_u);
    cudaGetSymbolAddress((void**)&dbc,   g_dbc);
    cudaGetSymbolAddress((void**)&dbcp,  g_dbc_part);
    cudaGetSymbolAddress((void**)&delta, g_delta);
    cudaGetSymbolAddress((void**)&y,     g_y);
    cudaGetSymbolAddress((void**)&winT,  g_WinT);
    cudaGetSymbolAddress((void**)&convTh, g_convTh);
    cudaGetSymbolAddress((void**)&convTl, g_convTl);
    cudaGetSymbolAddress((void**)&woutT, g_WoutT);
    cudaGetSymbolAddress((void**)&wdtT,  g_WdtT);

    cudaFuncSetAttribute(conv_halo, cudaFuncAttributeMaxDynamicSharedMemorySize, CONV_SMEM);

    // 0) all weight preprocessing in ONE launch
    fused_transpose<<<dim3(128, 64, 7), dim3(32, 8)>>>(
        W_in, conv_k, W_out, W_dt, winT, convTh, convTl, woutT, wdtT);

    // 1) GEMM1: xs -> bf16 hi/lo,  silu(res) -> sres fp32
    mma_gemm<3><<<dim3(32, 32), 256>>>(
        x, DMODEL, winT, DMODEL, sres, DINNER, DMODEL, nullptr, xsh, xsl);

    // 2) halo-fused grouped causal conv + bias + silu -> u fp32
    conv_halo<<<dim3(16, 32), 256, CONV_SMEM>>>(
        xsh, xsl, convTh, convTl, conv_b, u);

    // 3) dbc = u @ W_x  (split-K 8x, BM=64 blocking + deterministic reduce)
    gemm_n96_partial<<<dim3(64, 8), 256>>>(u, W_x, dbcp);
    gemm_n96_reduce<<<(BLROWS * 96 / 4) / 256, 256>>>(dbcp, dbc);

    // 4) delta = clip(softplus(dt_raw @ W_dt + b_dt))
    mma_gemm<1><<<dim3(16, 32), 256>>>(
        dbc, 96, wdtT, DTRANK, delta, DINNER, DTRANK, b_dt, nullptr, nullptr);

    // 5) selective scan + fused gate -> y fp32
    scan_kernel<<<256, 256>>>(delta, u, dbc, A_log, Dvec, sres, y);

    // 6) out = y @ W_out
    mma_gemm<0><<<dim3(8, 32), 256>>>(
        y, DINNER, woutT, DINNER, out, DMODEL, DINNER, nullptr, nullptr, nullptr);
}

// round 10
// speedup vs baseline: 1.5642x; 1.2849x over previous
#include <cuda_runtime.h>
#include <cuda_bf16.h>
#include <cstdint>

// Problem constants
#define BLROWS 4096   // B*L = 2*2048
#define LSEQ   2048
#define DMODEL 1024
#define DINNER 2048
#define DSTATE 16
#define DTRANK 64
#define NCH    16     // scan chunks
#define TC     128    // chunk length

typedef __nv_bfloat16 bf16;

// ---------------------------------------------------------------------------
// Scratch (device globals)
// ---------------------------------------------------------------------------
__device__ bf16  g_xsh[(size_t)BLROWS * DINNER];
__device__ bf16  g_xsl[(size_t)BLROWS * DINNER];
__device__ float g_sres[(size_t)BLROWS * DINNER];
__device__ float g_u  [(size_t)BLROWS * DINNER];
__device__ float g_dbc[(size_t)BLROWS * 96];
__device__ float g_dbc_part[(size_t)8 * BLROWS * 96];
__device__ float g_delta[(size_t)BLROWS * DINNER];
__device__ float g_y [(size_t)BLROWS * DINNER];
// scan chunk scratch: [b][c][d][n]
__device__ float g_scanP [(size_t)2 * NCH * DINNER * DSTATE];
__device__ float g_scanH [(size_t)2 * NCH * DINNER * DSTATE];
__device__ float g_scanHi[(size_t)2 * NCH * DINNER * DSTATE];
// Transposed weights
__device__ float g_WinT [(size_t)4096 * 1024];
__device__ bf16  g_convTh[(size_t)4 * 2048 * 1024], g_convTl[(size_t)4 * 2048 * 1024];
__device__ float g_WoutT[(size_t)1024 * 2048];
__device__ float g_WdtT [(size_t)2048 * 64];

// ---------------------------------------------------------------------------
// PTX helpers
// ---------------------------------------------------------------------------
__device__ __forceinline__ uint32_t smem_u32(const void* p) {
    uint32_t a;
    asm("{ .reg .u64 t; cvta.to.shared.u64 t, %1; cvt.u32.u64 %0, t; }"
        : "=r"(a) : "l"(p));
    return a;
}
__device__ __forceinline__ void ldsm4(uint32_t* r, uint32_t addr) {
    asm volatile("ldmatrix.sync.aligned.m8n8.x4.shared.b16 {%0,%1,%2,%3}, [%4];"
        : "=r"(r[0]), "=r"(r[1]), "=r"(r[2]), "=r"(r[3]) : "r"(addr));
}
__device__ __forceinline__ void mma16816(
    float& d0, float& d1, float& d2, float& d3,
    uint32_t a0, uint32_t a1, uint32_t a2, uint32_t a3,
    uint32_t b0, uint32_t b1)
{
    asm volatile(
        "mma.sync.aligned.m16n8k16.row.col.f32.bf16.bf16.f32 "
        "{%0,%1,%2,%3}, {%4,%5,%6,%7}, {%8,%9}, {%0,%1,%2,%3};"
        : "+f"(d0), "+f"(d1), "+f"(d2), "+f"(d3)
        : "r"(a0), "r"(a1), "r"(a2), "r"(a3), "r"(b0), "r"(b1));
}
// bf16 2-way split of a pair of floats -> packed bf16x2 (hi, lo)
__device__ __forceinline__ void split2(float x, float y, uint32_t& hi, uint32_t& lo) {
    bf16 hx = __float2bfloat16_rn(x);
    bf16 hy = __float2bfloat16_rn(y);
    __nv_bfloat162 h; h.x = hx; h.y = hy;
    __nv_bfloat162 l = __floats2bfloat162_rn(x - __bfloat162float(hx),
                                             y - __bfloat162float(hy));
    hi = *reinterpret_cast<uint32_t*>(&h);
    lo = *reinterpret_cast<uint32_t*>(&l);
}
// SMEM tile row = 64B (32 bf16) in 4x16B chunks, xor-swizzled
__device__ __forceinline__ uint32_t swz(int row, int chunk) {
    return (uint32_t)((row << 6) + (((chunk ^ ((row >> 1) & 3)) & 3) << 4));
}
__device__ __forceinline__ float silu(float v) { return v / (1.f + __expf(-v)); }

// ---------------------------------------------------------------------------
// R3-proven bf16x3 mma GEMM.  (unchanged from R9)
// ---------------------------------------------------------------------------
template <int EPI>
__global__ __launch_bounds__(256) void mma_gemm(
    const float* __restrict__ A, int lda,
    const float* __restrict__ Bt, int ldb,
    float* __restrict__ C, int ldc,
    int K, const float* __restrict__ bias,
    bf16* __restrict__ xsh, bf16* __restrict__ xsl)
{
    __shared__ __align__(16) char sAhi[8192], sAlo[8192], sBhi[8192], sBlo[8192];

    const int tid  = threadIdx.x;
    const int lane = tid & 31;
    const int wid  = tid >> 5;
    const int wm   = wid & 1;
    const int wn   = wid >> 1;
    const int m0   = blockIdx.y * 128;
    const int n0   = blockIdx.x * 128;
    const int TOT  = K >> 5;

    const uint32_t aHiB = smem_u32(sAhi), aLoB = smem_u32(sAlo);
    const uint32_t bHiB = smem_u32(sBhi), bLoB = smem_u32(sBlo);

    const int a_r  = lane & 15;
    const int a_cx = lane >> 4;
    const int b_r  = (lane & 7) + ((lane >> 4) << 3);
    const int b_cx = (lane >> 3) & 1;

    float acc[4][4][4];
#pragma unroll
    for (int i = 0; i < 4; i++)
#pragma unroll
        for (int j = 0; j < 4; j++)
#pragma unroll
            for (int k = 0; k < 4; k++) acc[i][j][k] = 0.f;

    float4 pa[4], pb[4];

    auto load = [&](int kb) {
#pragma unroll
        for (int i = 0; i < 4; i++) {
            int idx = tid + i * 256;
            int row = idx >> 3, seg = idx & 7;
            pa[i] = *(const float4*)(A + (size_t)(m0 + row) * lda + kb * 32 + seg * 4);
            pb[i] = *(const float4*)(Bt + (size_t)(n0 + row) * ldb + kb * 32 + seg * 4);
        }
    };

    auto store = [&]() {
#pragma unroll
        for (int i = 0; i < 4; i++) {
            int idx = tid + i * 256;
            int row = idx >> 3, seg = idx & 7;
            uint32_t off = swz(row, seg >> 1) + (seg & 1) * 8;
            uint2 h, l;
            split2(pa[i].x, pa[i].y, h.x, l.x);
            split2(pa[i].z, pa[i].w, h.y, l.y);
            *(uint2*)(sAhi + off) = h;
            *(uint2*)(sAlo + off) = l;
            split2(pb[i].x, pb[i].y, h.x, l.x);
            split2(pb[i].z, pb[i].w, h.y, l.y);
            *(uint2*)(sBhi + off) = h;
            *(uint2*)(sBlo + off) = l;
        }
    };

    auto mma_block = [&]() {
#pragma unroll
        for (int ks = 0; ks < 2; ks++) {
            uint32_t a[4][4], bh[4][2], bx[4][2];
#pragma unroll
            for (int mf = 0; mf < 4; mf++) {
                int row = wm * 64 + mf * 16 + a_r;
                ldsm4(a[mf], aHiB + swz(row, ks * 2 + a_cx));
            }
#pragma unroll
            for (int p = 0; p < 2; p++) {
                int row = wn * 32 + p * 16 + b_r;
                uint32_t t[4];
                ldsm4(t, bHiB + swz(row, ks * 2 + b_cx));
                bh[p * 2][0] = t[0]; bh[p * 2][1] = t[1];
                bh[p * 2 + 1][0] = t[2]; bh[p * 2 + 1][1] = t[3];
            }
#pragma unroll
            for (int mf = 0; mf < 4; mf++)
#pragma unroll
                for (int nf = 0; nf < 4; nf++)
                    mma16816(acc[mf][nf][0], acc[mf][nf][1], acc[mf][nf][2], acc[mf][nf][3],
                             a[mf][0], a[mf][1], a[mf][2], a[mf][3], bh[nf][0], bh[nf][1]);
#pragma unroll
            for (int p = 0; p < 2; p++) {
                int row = wn * 32 + p * 16 + b_r;
                uint32_t t[4];
                ldsm4(t, bLoB + swz(row, ks * 2 + b_cx));
                bx[p * 2][0] = t[0]; bx[p * 2][1] = t[1];
                bx[p * 2 + 1][0] = t[2]; bx[p * 2 + 1][1] = t[3];
            }
#pragma unroll
            for (int mf = 0; mf < 4; mf++)
#pragma unroll
                for (int nf = 0; nf < 4; nf++)
                    mma16816(acc[mf][nf][0], acc[mf][nf][1], acc[mf][nf][2], acc[mf][nf][3],
                             a[mf][0], a[mf][1], a[mf][2], a[mf][3], bx[nf][0], bx[nf][1]);
#pragma unroll
            for (int mf = 0; mf < 4; mf++) {
                int row = wm * 64 + mf * 16 + a_r;
                ldsm4(a[mf], aLoB + swz(row, ks * 2 + a_cx));
            }
#pragma unroll
            for (int mf = 0; mf < 4; mf++)
#pragma unroll
                for (int nf = 0; nf < 4; nf++)
                    mma16816(acc[mf][nf][0], acc[mf][nf][1], acc[mf][nf][2], acc[mf][nf][3],
                             a[mf][0], a[mf][1], a[mf][2], a[mf][3], bh[nf][0], bh[nf][1]);
        }
    };

    load(0);
    store();
    __syncthreads();
    for (int it = 1; it < TOT; it++) {
        load(it);
        mma_block();
        __syncthreads();
        store();
        __syncthreads();
    }
    mma_block();

    // Epilogue
#pragma unroll
    for (int mf = 0; mf < 4; mf++) {
        int r = m0 + wm * 64 + mf * 16 + (lane >> 2);
#pragma unroll
        for (int nf = 0; nf < 4; nf++) {
            int c = n0 + wn * 32 + nf * 8 + (lane & 3) * 2;
            float v0 = acc[mf][nf][0], v1 = acc[mf][nf][1];
            float v2 = acc[mf][nf][2], v3 = acc[mf][nf][3];
            if (EPI == 1) {
                float b0 = bias[c], b1 = bias[c + 1];
                float x0 = v0 + b0, x1 = v1 + b1, x2 = v2 + b0, x3 = v3 + b1;
                v0 = fminf(fmaxf(fmaxf(x0, 0.f) + log1pf(__expf(-fabsf(x0))), 1e-3f), 0.1f);
                v1 = fminf(fmaxf(fmaxf(x1, 0.f) + log1pf(__expf(-fabsf(x1))), 1e-3f), 0.1f);
                v2 = fminf(fmaxf(fmaxf(x2, 0.f) + log1pf(__expf(-fabsf(x2))), 1e-3f), 0.1f);
                v3 = fminf(fmaxf(fmaxf(x3, 0.f) + log1pf(__expf(-fabsf(x3))), 1e-3f), 0.1f);
            }
            if (EPI == 3) {
                if (n0 < 2048) {
                    uint32_t h, l;
                    split2(v0, v1, h, l);
                    *(uint32_t*)(xsh + (size_t)r * 2048 + c) = h;
                    *(uint32_t*)(xsl + (size_t)r * 2048 + c) = l;
                    split2(v2, v3, h, l);
                    *(uint32_t*)(xsh + (size_t)(r + 8) * 2048 + c) = h;
                    *(uint32_t*)(xsl + (size_t)(r + 8) * 2048 + c) = l;
                } else {
                    int cc = c - 2048;
                    *(float2*)(C + (size_t)r * ldc + cc)
                        = make_float2(silu(v0), silu(v1));
                    *(float2*)(C + (size_t)(r + 8) * ldc + cc)
                        = make_float2(silu(v2), silu(v3));
                }
            } else {
                *(float2*)(C + (size_t)r * ldc + c)       = make_float2(v0, v1);
                *(float2*)(C + (size_t)(r + 8) * ldc + c) = make_float2(v2, v3);
            }
        }
    }
}

// ---------------------------------------------------------------------------
// Halo-fused grouped causal conv (R6-proven, unchanged).
// ---------------------------------------------------------------------------
#define CONV_STG  82944
#define CONV_SMEM (2 * CONV_STG + 1024)

__global__ __launch_bounds__(256) void conv_halo(
    const bf16* __restrict__ Ah, const bf16* __restrict__ Al,
    const bf16* __restrict__ Bh, const bf16* __restrict__ Bl,
    const float* __restrict__ bias, float* __restrict__ U)
{
    extern __shared__ char dyn[];
    const uint32_t rawb = smem_u32(dyn);
    const uint32_t base = (rawb + 1023u) & ~1023u;
    char* tp = dyn + (base - rawb);

    const int tid  = threadIdx.x;
    const int lane = tid & 31;
    const int wid  = tid >> 5;
    const int wm   = wid & 1;
    const int wn   = wid >> 1;
    const int m0   = blockIdx.y * 128;
    const int n0   = blockIdx.x * 128;
    const int colbase = (n0 >= 1024) ? 1024 : 0;
    const bool headok = (m0 & (LSEQ - 1)) != 0;

    const int a_r  = lane & 15;
    const int a_cx = lane >> 4;
    const int b_r  = (lane & 7) + ((lane >> 4) << 3);
    const int b_cx = (lane >> 3) & 1;

    float acc[4][4][4];
#pragma unroll
    for (int i = 0; i < 4; i++)
#pragma unroll
        for (int j = 0; j < 4; j++)
#pragma unroll
            for (int k = 0; k < 4; k++) acc[i][j][k] = 0.f;

    uint4 sa[6], rb1[8], rb2[8];

    auto loadA = [&](int kb) {
#pragma unroll
        for (int i = 0; i < 3; i++) {
            int c = tid + i * 256;
            if (i < 2 || c < 524) {
                int row = c >> 2, seg = c & 3;
                bool valid = headok || (row >= 3);
                long grow = (long)m0 - 3 + row;
                if (valid) {
                    sa[i * 2]     = *(const uint4*)(Ah + grow * 2048 + colbase + kb * 32 + seg * 8);
                    sa[i * 2 + 1] = *(const uint4*)(Al + grow * 2048 + colbase + kb * 32 + seg * 8);
                } else {
                    sa[i * 2]     = make_uint4(0, 0, 0, 0);
                    sa[i * 2 + 1] = make_uint4(0, 0, 0, 0);
                }
            }
        }
    };
    auto stsA = [&](int s) {
        char* sb = tp + s * CONV_STG;
#pragma unroll
        for (int i = 0; i < 3; i++) {
            int c = tid + i * 256;
            if (i < 2 || c < 524) {
                int row = c >> 2, seg = c & 3;
                uint32_t off = swz(row, seg);
                *(uint4*)(sb + off)        = sa[i * 2];
                *(uint4*)(sb + 8704 + off) = sa[i * 2 + 1];
            }
        }
    };
    auto loadB = [&](int kb, int half, uint4* rb) {
#pragma unroll
        for (int i = 0; i < 4; i++) {
            int c = tid + i * 256;
            int tap = half * 2 + (c >> 9);
            int cc = c & 511;
            int row = cc >> 2, seg = cc & 3;
            const bf16* ph = Bh + (size_t)tap * 2048 * 1024 + (size_t)(n0 + row) * 1024 + kb * 32 + seg * 8;
            const bf16* pl = Bl + (size_t)tap * 2048 * 1024 + (size_t)(n0 + row) * 1024 + kb * 32 + seg * 8;
            rb[i * 2]     = *(const uint4*)ph;
            rb[i * 2 + 1] = *(const uint4*)pl;
        }
    };
    auto stsB = [&](int s, int half, uint4* rb) {
#pragma unroll
        for (int i = 0; i < 4; i++) {
            int c = tid + i * 256;
            int tap = half * 2 + (c >> 9);
            int cc = c & 511;
            int row = cc >> 2, seg = cc & 3;
            char* bb = tp + s * CONV_STG + 17408 + tap * 16384;
            uint32_t off = swz(row, seg);
            *(uint4*)(bb + off)        = rb[i * 2];
            *(uint4*)(bb + 8192 + off) = rb[i * 2 + 1];
        }
    };
    auto mma_tap = [&](int s, int tap) {
        uint32_t aHiB = base + (uint32_t)s * CONV_STG;
        uint32_t aLoB = aHiB + 8704;
        uint32_t bHiB = aHiB + 17408 + (uint32_t)tap * 16384;
        uint32_t bLoB = bHiB + 8192;
#pragma unroll
        for (int ks = 0; ks < 2; ks++) {
            uint32_t a[4][4], bh[4][2], bx[4][2];
#pragma unroll
            for (int mf = 0; mf < 4; mf++) {
                int row = wm * 64 + mf * 16 + a_r + tap;
                ldsm4(a[mf], aHiB + swz(row, ks * 2 + a_cx));
            }
#pragma unroll
            for (int p = 0; p < 2; p++) {
                int row = wn * 32 + p * 16 + b_r;
                uint32_t t[4];
                ldsm4(t, bHiB + swz(row, ks * 2 + b_cx));
                bh[p * 2][0] = t[0]; bh[p * 2][1] = t[1];
                bh[p * 2 + 1][0] = t[2]; bh[p * 2 + 1][1] = t[3];
            }
#pragma unroll
            for (int mf = 0; mf < 4; mf++)
#pragma unroll
                for (int nf = 0; nf < 4; nf++)
                    mma16816(acc[mf][nf][0], acc[mf][nf][1], acc[mf][nf][2], acc[mf][nf][3],
                             a[mf][0], a[mf][1], a[mf][2], a[mf][3], bh[nf][0], bh[nf][1]);
#pragma unroll
            for (int p = 0; p < 2; p++) {
                int row = wn * 32 + p * 16 + b_r;
                uint32_t t[4];
                ldsm4(t, bLoB + swz(row, ks * 2 + b_cx));
                bx[p * 2][0] = t[0]; bx[p * 2][1] = t[1];
                bx[p * 2 + 1][0] = t[2]; bx[p * 2 + 1][1] = t[3];
            }
#pragma unroll
            for (int mf = 0; mf < 4; mf++)
#pragma unroll
                for (int nf = 0; nf < 4; nf++)
                    mma16816(acc[mf][nf][0], acc[mf][nf][1], acc[mf][nf][2], acc[mf][nf][3],
                             a[mf][0], a[mf][1], a[mf][2], a[mf][3], bx[nf][0], bx[nf][1]);
#pragma unroll
            for (int mf = 0; mf < 4; mf++) {
                int row = wm * 64 + mf * 16 + a_r + tap;
                ldsm4(a[mf], aLoB + swz(row, ks * 2 + a_cx));
            }
#pragma unroll
            for (int mf = 0; mf < 4; mf++)
#pragma unroll
                for (int nf = 0; nf < 4; nf++)
                    mma16816(acc[mf][nf][0], acc[mf][nf][1], acc[mf][nf][2], acc[mf][nf][3],
                             a[mf][0], a[mf][1], a[mf][2], a[mf][3], bh[nf][0], bh[nf][1]);
        }
    };

    loadA(0); loadB(0, 0, rb1); loadB(0, 1, rb2);
    stsA(0); stsB(0, 0, rb1); stsB(0, 1, rb2);
    __syncthreads();

    for (int kb = 0; kb < 32; kb++) {
        int cur = kb & 1, nxt = cur ^ 1;
        bool more = (kb + 1) < 32;
        if (more) { loadA(kb + 1); loadB(kb + 1, 0, rb1); }
        mma_tap(cur, 0);
        mma_tap(cur, 1);
        if (more) { stsA(nxt); stsB(nxt, 0, rb1); loadB(kb + 1, 1, rb2); }
        mma_tap(cur, 2);
        mma_tap(cur, 3);
        if (more) stsB(nxt, 1, rb2);
        __syncthreads();
    }

#pragma unroll
    for (int mf = 0; mf < 4; mf++) {
        int r = m0 + wm * 64 + mf * 16 + (lane >> 2);
#pragma unroll
        for (int nf = 0; nf < 4; nf++) {
            int c = n0 + wn * 32 + nf * 8 + (lane & 3) * 2;
            float b0 = bias[c], b1 = bias[c + 1];
            float v0 = silu(acc[mf][nf][0] + b0);
            float v1 = silu(acc[mf][nf][1] + b1);
            float v2 = silu(acc[mf][nf][2] + b0);
            float v3 = silu(acc[mf][nf][3] + b1);
            *(float2*)(U + (size_t)r * DINNER + c)       = make_float2(v0, v1);
            *(float2*)(U + (size_t)(r + 8) * DINNER + c) = make_float2(v2, v3);
        }
    }
}

// ---------------------------------------------------------------------------
// Fused weight preprocessing (unchanged)
// ---------------------------------------------------------------------------
__global__ __launch_bounds__(256) void fused_transpose(
    const float* __restrict__ Win, const float* __restrict__ convk,
    const float* __restrict__ Wout, const float* __restrict__ Wdt,
    float* __restrict__ winT, bf16* __restrict__ cTh, bf16* __restrict__ cTl,
    float* __restrict__ woutT, float* __restrict__ wdtT)
{
    int z = blockIdx.z;
    const float* src; int R, C;
    if (z == 0)      { src = Win;  R = 1024; C = 4096; }
    else if (z <= 4) { src = convk + (size_t)(z - 1) * 1024 * 2048; R = 1024; C = 2048; }
    else if (z == 5) { src = Wout; R = 2048; C = 1024; }
    else             { src = Wdt;  R = 64;   C = 2048; }
    if (blockIdx.x * 32 >= C || blockIdx.y * 32 >= R) return;

    __shared__ float t[32][33];
    int x = blockIdx.x * 32 + threadIdx.x;
#pragma unroll
    for (int j = 0; j < 4; j++) {
        int y = blockIdx.y * 32 + threadIdx.y + j * 8;
        t[threadIdx.y + j * 8][threadIdx.x] = src[(size_t)y * C + x];
    }
    __syncthreads();
    int x2 = blockIdx.y * 32 + threadIdx.x;
#pragma unroll
    for (int j = 0; j < 4; j++) {
        int y2 = blockIdx.x * 32 + threadIdx.y + j * 8;
        float v = t[threadIdx.x][threadIdx.y + j * 8];
        if (z == 0) {
            winT[(size_t)y2 * R + x2] = v;
        } else if (z <= 4) {
            size_t off = (size_t)(z - 1) * 2048 * 1024 + (size_t)y2 * R + x2;
            bf16 h = __float2bfloat16_rn(v);
            cTh[off] = h;
            cTl[off] = __float2bfloat16_rn(v - __bfloat162float(h));
        } else if (z == 5) {
            woutT[(size_t)y2 * R + x2] = v;
        } else {
            wdtT[(size_t)y2 * R + x2] = v;
        }
    }
}

// ---------------------------------------------------------------------------
// Split-K narrow GEMM (R9-proven, unchanged)
// ---------------------------------------------------------------------------
__global__ __launch_bounds__(256) void gemm_n96_partial(
    const float* __restrict__ A, const float* __restrict__ B,
    float* __restrict__ P)
{
    const int BK = 32, NN = 96, KC = 256, BM = 64;
    __shared__ float As[BK][BM];
    __shared__ float Bs[BK][NN];

    const int m0 = blockIdx.x * BM;
    const int kc = blockIdx.y;
    const int kbeg = kc * KC;
    const int tid = threadIdx.x;
    const int tx = tid & 15;
    const int ty = tid >> 4;

    float acc[4][6];
#pragma unroll
    for (int r = 0; r < 4; r++)
#pragma unroll
        for (int j = 0; j < 6; j++) acc[r][j] = 0.f;

    for (int k0 = kbeg; k0 < kbeg + KC; k0 += BK) {
#pragma unroll
        for (int i = 0; i < 2; i++) {
            int idx = tid + i * 256;
            int row = idx >> 3;
            int cv  = (idx & 7) * 4;
            float4 a = *(const float4*)(A + (size_t)(m0 + row) * DINNER + k0 + cv);
            As[cv + 0][row] = a.x; As[cv + 1][row] = a.y;
            As[cv + 2][row] = a.z; As[cv + 3][row] = a.w;
        }
#pragma unroll
        for (int i = 0; i < 3; i++) {
            int idx  = tid + i * 256;
            int rowB = idx / 24;
            int cv   = (idx % 24) * 4;
            *(float4*)(&Bs[rowB][cv]) =
                *(const float4*)(B + (size_t)(k0 + rowB) * NN + cv);
        }
        __syncthreads();
#pragma unroll
        for (int k = 0; k < BK; k++) {
            float a[4];
            *(float4*)a = *(const float4*)(&As[k][ty * 4]);
            float b[6];
            *(float2*)(b)     = *(const float2*)(&Bs[k][tx * 6]);
            *(float2*)(b + 2) = *(const float2*)(&Bs[k][tx * 6 + 2]);
            *(float2*)(b + 4) = *(const float2*)(&Bs[k][tx * 6 + 4]);
#pragma unroll
            for (int r = 0; r < 4; r++)
#pragma unroll
                for (int j = 0; j < 6; j++)
                    acc[r][j] = fmaf(a[r], b[j], acc[r][j]);
        }
        __syncthreads();
    }
    float* out = P + (size_t)kc * BLROWS * 96;
#pragma unroll
    for (int r = 0; r < 4; r++) {
        int m = m0 + ty * 4 + r;
#pragma unroll
        for (int j = 0; j < 6; j++)
            out[(size_t)m * 96 + tx * 6 + j] = acc[r][j];
    }
}

__global__ __launch_bounds__(256) void gemm_n96_reduce(
    const float* __restrict__ P, float* __restrict__ C)
{
    size_t i = ((size_t)blockIdx.x * blockDim.x + threadIdx.x) * 4;
    const size_t S = (size_t)BLROWS * 96;
    float4 s = *(const float4*)(P + i);
#pragma unroll
    for (int kc = 1; kc < 8; kc++) {
        float4 v = *(const float4*)(P + kc * S + i);
        s.x += v.x; s.y += v.y; s.z += v.z; s.w += v.w;
    }
    *(float4*)(C + i) = s;
}

// ---------------------------------------------------------------------------
// Chunked parallel scan.
// Lane layout: lane = ng | (dl<<2)  (ng: 4 n-groups of 4, dl: 8 consecutive d)
// Pass 1: per (b,c,d,n) compute P = prod(dA), H = chunk scan with h_in = 0.
// Pass 2: sequential combine over 16 chunks -> HIN.
// Pass 3: re-scan chunk from HIN, C-dot + u*D, gate by sres, write y.
// Scratch layout [b][c][d][n].
// ---------------------------------------------------------------------------
__global__ __launch_bounds__(256) void scan_pass1(
    const float* __restrict__ delta, const float* __restrict__ u,
    const float* __restrict__ dbc, const float* __restrict__ A_log,
    float* __restrict__ P, float* __restrict__ H)
{
    const int tid  = threadIdx.x;
    const int lane = tid & 31;
    const int w    = tid >> 5;
    const int ng   = lane & 3;
    const int dl   = lane >> 2;
    const int d    = blockIdx.x * 64 + w * 8 + dl;
    const int c    = blockIdx.y;
    const int b    = blockIdx.z;

    float4 al = *(const float4*)(A_log + d * DSTATE + ng * 4);
    const float a0 = -__expf(al.x), a1 = -__expf(al.y);
    const float a2 = -__expf(al.z), a3 = -__expf(al.w);

    const size_t trow = (size_t)b * LSEQ + (size_t)c * TC;
    const float* dp  = delta + trow * DINNER + d;
    const float* up  = u     + trow * DINNER + d;
    const float* bcp = dbc   + trow * 96 + DTRANK + ng * 4;

    float h0 = 0.f, h1 = 0.f, h2 = 0.f, h3 = 0.f;
    float p0 = 1.f, p1 = 1.f, p2 = 1.f, p3 = 1.f;
    for (int t = 0; t < TC; t++) {
        float de = dp[(size_t)t * DINNER];
        float uu = up[(size_t)t * DINNER];
        float4 Bv = *(const float4*)(bcp + t * 96);
        float dA0 = __expf(de * a0), dA1 = __expf(de * a1);
        float dA2 = __expf(de * a2), dA3 = __expf(de * a3);
        float du = de * uu;
        p0 *= dA0; p1 *= dA1; p2 *= dA2; p3 *= dA3;
        h0 = fmaf(dA0, h0, du * Bv.x);
        h1 = fmaf(dA1, h1, du * Bv.y);
        h2 = fmaf(dA2, h2, du * Bv.z);
        h3 = fmaf(dA3, h3, du * Bv.w);
    }
    size_t o = (((size_t)b * NCH + c) * DINNER + d) * DSTATE + ng * 4;
    *(float4*)(P + o) = make_float4(p0, p1, p2, p3);
    *(float4*)(H + o) = make_float4(h0, h1, h2, h3);
}

__global__ __launch_bounds__(256) void scan_pass2(
    const float* __restrict__ P, const float* __restrict__ H,
    float* __restrict__ HIN)
{
    int idx = blockIdx.x * blockDim.x + threadIdx.x;   // (b, d, n) flat: 65536
    int n = idx & 15;
    int d = (idx >> 4) & (DINNER - 1);
    int b = idx >> 15;
    float hin = 0.f;
#pragma unroll
    for (int c = 0; c < NCH; c++) {
        size_t o = (((size_t)b * NCH + c) * DINNER + d) * DSTATE + n;
        HIN[o] = hin;
        hin = fmaf(P[o], hin, H[o]);
    }
}

__global__ __launch_bounds__(256) void scan_pass3(
    const float* __restrict__ delta, const float* __restrict__ u,
    const float* __restrict__ dbc, const float* __restrict__ A_log,
    const float* __restrict__ Dp, const float* __restrict__ sres,
    const float* __restrict__ HIN, float* __restrict__ Y)
{
    const int tid  = threadIdx.x;
    const int lane = tid & 31;
    const int w    = tid >> 5;
    const int ng   = lane & 3;
    const int dl   = lane >> 2;
    const int d    = blockIdx.x * 64 + w * 8 + dl;
    const int c    = blockIdx.y;
    const int b    = blockIdx.z;

    float4 al = *(const float4*)(A_log + d * DSTATE + ng * 4);
    const float a0 = -__expf(al.x), a1 = -__expf(al.y);
    const float a2 = -__expf(al.z), a3 = -__expf(al.w);
    const float Dd = Dp[d];

    const size_t trow = (size_t)b * LSEQ + (size_t)c * TC;
    const float* dp  = delta + trow * DINNER + d;
    const float* up  = u     + trow * DINNER + d;
    const float* rp  = sres  + trow * DINNER + d;
    const float* bcp = dbc   + trow * 96 + DTRANK + ng * 4;
    float*       yp  = Y     + trow * DINNER + d;

    size_t o = (((size_t)b * NCH + c) * DINNER + d) * DSTATE + ng * 4;
    float4 hv = *(const float4*)(HIN + o);
    float h0 = hv.x, h1 = hv.y, h2 = hv.z, h3 = hv.w;

    for (int t = 0; t < TC; t++) {
        float de = dp[(size_t)t * DINNER];
        float uu = up[(size_t)t * DINNER];
        float4 Bv = *(const float4*)(bcp + t * 96);
        float4 Cv = *(const float4*)(bcp + t * 96 + DSTATE);
        float dA0 = __expf(de * a0), dA1 = __expf(de * a1);
        float dA2 = __expf(de * a2), dA3 = __expf(de * a3);
        float du = de * uu;
        h0 = fmaf(dA0, h0, du * Bv.x);
        h1 = fmaf(dA1, h1, du * Bv.y);
        h2 = fmaf(dA2, h2, du * Bv.z);
        h3 = fmaf(dA3, h3, du * Bv.w);
        float pp = h0 * Cv.x + h1 * Cv.y + h2 * Cv.z + h3 * Cv.w;
        pp += __shfl_xor_sync(0xffffffffu, pp, 1);
        pp += __shfl_xor_sync(0xffffffffu, pp, 2);
        if (ng == 0)
            yp[(size_t)t * DINNER] = fmaf(uu, Dd, pp) * rp[(size_t)t * DINNER];
    }
}

// ---------------------------------------------------------------------------
// Launch
// ---------------------------------------------------------------------------
extern "C" void kernel_launch(void* const* d_in, const int* in_sizes, int n_in,
                              void* d_out, int out_size)
{
    (void)in_sizes; (void)n_in; (void)out_size;
    const float* x      = (const float*)d_in[0];
    const float* W_in   = (const float*)d_in[1];
    const float* conv_k = (const float*)d_in[2];
    const float* conv_b = (const float*)d_in[3];
    const float* W_x    = (const float*)d_in[4];
    const float* W_dt   = (const float*)d_in[5];
    const float* b_dt   = (const float*)d_in[6];
    const float* A_log  = (const float*)d_in[7];
    const float* Dvec   = (const float*)d_in[8];
    const float* W_out  = (const float*)d_in[9];
    float* out = (float*)d_out;

    bf16 *xsh, *xsl, *convTh, *convTl;
    float *sres, *u, *dbc, *dbcp, *delta, *y, *winT, *woutT, *wdtT;
    float *scP, *scH, *scHi;
    cudaGetSymbolAddress((void**)&xsh,   g_xsh);
    cudaGetSymbolAddress((void**)&xsl,   g_xsl);
    cudaGetSymbolAddress((void**)&sres,  g_sres);
    cudaGetSymbolAddress((void**)&u,     g_u);
    cudaGetSymbolAddress((void**)&dbc,   g_dbc);
    cudaGetSymbolAddress((void**)&dbcp,  g_dbc_part);
    cudaGetSymbolAddress((void**)&delta, g_delta);
    cudaGetSymbolAddress((void**)&y,     g_y);
    cudaGetSymbolAddress((void**)&winT,  g_WinT);
    cudaGetSymbolAddress((void**)&convTh, g_convTh);
    cudaGetSymbolAddress((void**)&convTl, g_convTl);
    cudaGetSymbolAddress((void**)&woutT, g_WoutT);
    cudaGetSymbolAddress((void**)&wdtT,  g_WdtT);
    cudaGetSymbolAddress((void**)&scP,   g_scanP);
    cudaGetSymbolAddress((void**)&scH,   g_scanH);
    cudaGetSymbolAddress((void**)&scHi,  g_scanHi);

    cudaFuncSetAttribute(conv_halo, cudaFuncAttributeMaxDynamicSharedMemorySize, CONV_SMEM);

    // 0) all weight preprocessing in ONE launch
    fused_transpose<<<dim3(128, 64, 7), dim3(32, 8)>>>(
        W_in, conv_k, W_out, W_dt, winT, convTh, convTl, woutT, wdtT);

    // 1) GEMM1: xs -> bf16 hi/lo,  silu(res) -> sres fp32
    mma_gemm<3><<<dim3(32, 32), 256>>>(
        x, DMODEL, winT, DMODEL, sres, DINNER, DMODEL, nullptr, xsh, xsl);

    // 2) halo-fused grouped causal conv + bias + silu -> u fp32
    conv_halo<<<dim3(16, 32), 256, CONV_SMEM>>>(
        xsh, xsl, convTh, convTl, conv_b, u);

    // 3) dbc = u @ W_x  (split-K 8x, BM=64 blocking + deterministic reduce)
    gemm_n96_partial<<<dim3(64, 8), 256>>>(u, W_x, dbcp);
    gemm_n96_reduce<<<(BLROWS * 96 / 4) / 256, 256>>>(dbcp, dbc);

    // 4) delta = clip(softplus(dt_raw @ W_dt + b_dt))
    mma_gemm<1><<<dim3(16, 32), 256>>>(
        dbc, 96, wdtT, DTRANK, delta, DINNER, DTRANK, b_dt, nullptr, nullptr);

    // 5) chunked parallel scan (+ fused gate) -> y fp32
    scan_pass1<<<dim3(32, NCH, 2), 256>>>(delta, u, dbc, A_log, scP, scH);
    scan_pass2<<<256, 256>>>(scP, scH, scHi);
    scan_pass3<<<dim3(32, NCH, 2), 256>>>(delta, u, dbc, A_log, Dvec, sres, scHi, y);

    // 6) out = y @ W_out
    mma_gemm<0><<<dim3(8, 32), 256>>>(
        y, DINNER, woutT, DINNER, out, DMODEL, DINNER, nullptr, nullptr, nullptr);
}

// round 11
// speedup vs baseline: 1.9142x; 1.2238x over previous
#include <cuda_runtime.h>
#include <cuda_bf16.h>
#include <cuda_fp16.h>
#include <cstdint>

// Problem constants
#define BLROWS 4096   // B*L = 2*2048
#define LSEQ   2048
#define DMODEL 1024
#define DINNER 2048
#define DSTATE 16
#define DTRANK 64
#define NCH    16     // scan chunks
#define TC     128    // chunk length

typedef __nv_bfloat16 bf16;
typedef __half h16;

// ---------------------------------------------------------------------------
// Scratch (device globals)
// ---------------------------------------------------------------------------
__device__ h16   g_xsh[(size_t)BLROWS * DINNER];     // xs fp16 hi (from GEMM1)
__device__ h16   g_xsl[(size_t)BLROWS * DINNER];     // xs fp16 lo
__device__ float g_sres[(size_t)BLROWS * DINNER];
__device__ float g_u  [(size_t)BLROWS * DINNER];
__device__ float g_dbc[(size_t)BLROWS * 96];
__device__ float g_dbc_part[(size_t)8 * BLROWS * 96];
__device__ float g_delta[(size_t)BLROWS * DINNER];
__device__ float g_y [(size_t)BLROWS * DINNER];
// scan chunk scratch: [b][c][d][n]
__device__ float g_scanP [(size_t)2 * NCH * DINNER * DSTATE];
__device__ float g_scanH [(size_t)2 * NCH * DINNER * DSTATE];
__device__ float g_scanHi[(size_t)2 * NCH * DINNER * DSTATE];
// Transposed weights
__device__ float g_WinT [(size_t)4096 * 1024];                 // fp32
__device__ h16   g_convTf[(size_t)4 * 2048 * 1024];            // fp16 single
__device__ float g_WoutT[(size_t)1024 * 2048];                 // fp32
__device__ float g_WdtT [(size_t)2048 * 64];                   // fp32

// ---------------------------------------------------------------------------
// PTX helpers
// ---------------------------------------------------------------------------
__device__ __forceinline__ uint32_t smem_u32(const void* p) {
    uint32_t a;
    asm("{ .reg .u64 t; cvta.to.shared.u64 t, %1; cvt.u32.u64 %0, t; }"
        : "=r"(a) : "l"(p));
    return a;
}
__device__ __forceinline__ void ldsm4(uint32_t* r, uint32_t addr) {
    asm volatile("ldmatrix.sync.aligned.m8n8.x4.shared.b16 {%0,%1,%2,%3}, [%4];"
        : "=r"(r[0]), "=r"(r[1]), "=r"(r[2]), "=r"(r[3]) : "r"(addr));
}
__device__ __forceinline__ void mma16816(
    float& d0, float& d1, float& d2, float& d3,
    uint32_t a0, uint32_t a1, uint32_t a2, uint32_t a3,
    uint32_t b0, uint32_t b1)
{
    asm volatile(
        "mma.sync.aligned.m16n8k16.row.col.f32.bf16.bf16.f32 "
        "{%0,%1,%2,%3}, {%4,%5,%6,%7}, {%8,%9}, {%0,%1,%2,%3};"
        : "+f"(d0), "+f"(d1), "+f"(d2), "+f"(d3)
        : "r"(a0), "r"(a1), "r"(a2), "r"(a3), "r"(b0), "r"(b1));
}
__device__ __forceinline__ void mma16816h(
    float& d0, float& d1, float& d2, float& d3,
    uint32_t a0, uint32_t a1, uint32_t a2, uint32_t a3,
    uint32_t b0, uint32_t b1)
{
    asm volatile(
        "mma.sync.aligned.m16n8k16.row.col.f32.f16.f16.f32 "
        "{%0,%1,%2,%3}, {%4,%5,%6,%7}, {%8,%9}, {%0,%1,%2,%3};"
        : "+f"(d0), "+f"(d1), "+f"(d2), "+f"(d3)
        : "r"(a0), "r"(a1), "r"(a2), "r"(a3), "r"(b0), "r"(b1));
}
// bf16 2-way split of two floats -> packed bf16x2 (hi, lo)
__device__ __forceinline__ void split2(float x, float y, uint32_t& hi, uint32_t& lo) {
    bf16 hx = __float2bfloat16_rn(x);
    bf16 hy = __float2bfloat16_rn(y);
    __nv_bfloat162 h; h.x = hx; h.y = hy;
    __nv_bfloat162 l = __floats2bfloat162_rn(x - __bfloat162float(hx),
                                             y - __bfloat162float(hy));
    hi = *reinterpret_cast<uint32_t*>(&h);
    lo = *reinterpret_cast<uint32_t*>(&l);
}
// fp16 2-way split (A exact to ~2^-22)
__device__ __forceinline__ void split2h(float x, float y, uint32_t& hi, uint32_t& lo) {
    h16 hx = __float2half_rn(x);
    h16 hy = __float2half_rn(y);
    __half2 h = __halves2half2(hx, hy);
    __half2 l = __floats2half2_rn(x - __half2float(hx), y - __half2float(hy));
    hi = *reinterpret_cast<uint32_t*>(&h);
    lo = *reinterpret_cast<uint32_t*>(&l);
}
// SMEM tile row = 64B (32 elems) in 4x16B chunks, xor-swizzled
__device__ __forceinline__ uint32_t swz(int row, int chunk) {
    return (uint32_t)((row << 6) + (((chunk ^ ((row >> 1) & 3)) & 3) << 4));
}
__device__ __forceinline__ float silu(float v) { return v / (1.f + __expf(-v)); }

// ---------------------------------------------------------------------------
// mma GEMM.  PREC=0: bf16x3 (R3-proven).  PREC=1: fp16 A-split x2 products,
// fp16-single B.  C-tile[128,128] = A[M,K] @ Bt[N,K]^T.
// EPI: 0 fp32 store; 1 softplus+clip(+bias); 3 GEMM1 dual out (xs fp16 split).
// ---------------------------------------------------------------------------
template <int EPI, int PREC>
__global__ __launch_bounds__(256) void mma_gemm(
    const float* __restrict__ A, int lda,
    const float* __restrict__ Bt, int ldb,
    float* __restrict__ C, int ldc,
    int K, const float* __restrict__ bias,
    h16* __restrict__ xsh, h16* __restrict__ xsl)
{
    __shared__ __align__(16) char sAhi[8192], sAlo[8192], sBhi[8192], sBlo[8192];

    const int tid  = threadIdx.x;
    const int lane = tid & 31;
    const int wid  = tid >> 5;
    const int wm   = wid & 1;
    const int wn   = wid >> 1;
    const int m0   = blockIdx.y * 128;
    const int n0   = blockIdx.x * 128;
    const int TOT  = K >> 5;

    const uint32_t aHiB = smem_u32(sAhi), aLoB = smem_u32(sAlo);
    const uint32_t bHiB = smem_u32(sBhi), bLoB = smem_u32(sBlo);

    const int a_r  = lane & 15;
    const int a_cx = lane >> 4;
    const int b_r  = (lane & 7) + ((lane >> 4) << 3);
    const int b_cx = (lane >> 3) & 1;

    float acc[4][4][4];
#pragma unroll
    for (int i = 0; i < 4; i++)
#pragma unroll
        for (int j = 0; j < 4; j++)
#pragma unroll
            for (int k = 0; k < 4; k++) acc[i][j][k] = 0.f;

    float4 pa[4], pb[4];

    auto load = [&](int kb) {
#pragma unroll
        for (int i = 0; i < 4; i++) {
            int idx = tid + i * 256;
            int row = idx >> 3, seg = idx & 7;
            pa[i] = *(const float4*)(A + (size_t)(m0 + row) * lda + kb * 32 + seg * 4);
            pb[i] = *(const float4*)(Bt + (size_t)(n0 + row) * ldb + kb * 32 + seg * 4);
        }
    };

    auto store = [&]() {
#pragma unroll
        for (int i = 0; i < 4; i++) {
            int idx = tid + i * 256;
            int row = idx >> 3, seg = idx & 7;
            uint32_t off = swz(row, seg >> 1) + (seg & 1) * 8;
            uint2 h, l;
            if (PREC == 0) {
                split2(pa[i].x, pa[i].y, h.x, l.x);
                split2(pa[i].z, pa[i].w, h.y, l.y);
                *(uint2*)(sAhi + off) = h;
                *(uint2*)(sAlo + off) = l;
                split2(pb[i].x, pb[i].y, h.x, l.x);
                split2(pb[i].z, pb[i].w, h.y, l.y);
                *(uint2*)(sBhi + off) = h;
                *(uint2*)(sBlo + off) = l;
            } else {
                split2h(pa[i].x, pa[i].y, h.x, l.x);
                split2h(pa[i].z, pa[i].w, h.y, l.y);
                *(uint2*)(sAhi + off) = h;
                *(uint2*)(sAlo + off) = l;
                __half2 b0 = __floats2half2_rn(pb[i].x, pb[i].y);
                __half2 b1 = __floats2half2_rn(pb[i].z, pb[i].w);
                h.x = *reinterpret_cast<uint32_t*>(&b0);
                h.y = *reinterpret_cast<uint32_t*>(&b1);
                *(uint2*)(sBhi + off) = h;
            }
        }
    };

    auto mma_block = [&]() {
#pragma unroll
        for (int ks = 0; ks < 2; ks++) {
            uint32_t a[4][4], bh[4][2];
#pragma unroll
            for (int mf = 0; mf < 4; mf++) {
                int row = wm * 64 + mf * 16 + a_r;
                ldsm4(a[mf], aHiB + swz(row, ks * 2 + a_cx));
            }
#pragma unroll
            for (int p = 0; p < 2; p++) {
                int row = wn * 32 + p * 16 + b_r;
                uint32_t t[4];
                ldsm4(t, bHiB + swz(row, ks * 2 + b_cx));
                bh[p * 2][0] = t[0]; bh[p * 2][1] = t[1];
                bh[p * 2 + 1][0] = t[2]; bh[p * 2 + 1][1] = t[3];
            }
#pragma unroll
            for (int mf = 0; mf < 4; mf++)
#pragma unroll
                for (int nf = 0; nf < 4; nf++) {
                    if (PREC == 0)
                        mma16816(acc[mf][nf][0], acc[mf][nf][1], acc[mf][nf][2], acc[mf][nf][3],
                                 a[mf][0], a[mf][1], a[mf][2], a[mf][3], bh[nf][0], bh[nf][1]);
                    else
                        mma16816h(acc[mf][nf][0], acc[mf][nf][1], acc[mf][nf][2], acc[mf][nf][3],
                                  a[mf][0], a[mf][1], a[mf][2], a[mf][3], bh[nf][0], bh[nf][1]);
                }
            if (PREC == 0) {
                uint32_t bx[4][2];
#pragma unroll
                for (int p = 0; p < 2; p++) {
                    int row = wn * 32 + p * 16 + b_r;
                    uint32_t t[4];
                    ldsm4(t, bLoB + swz(row, ks * 2 + b_cx));
                    bx[p * 2][0] = t[0]; bx[p * 2][1] = t[1];
                    bx[p * 2 + 1][0] = t[2]; bx[p * 2 + 1][1] = t[3];
                }
#pragma unroll
                for (int mf = 0; mf < 4; mf++)
#pragma unroll
                    for (int nf = 0; nf < 4; nf++)
                        mma16816(acc[mf][nf][0], acc[mf][nf][1], acc[mf][nf][2], acc[mf][nf][3],
                                 a[mf][0], a[mf][1], a[mf][2], a[mf][3], bx[nf][0], bx[nf][1]);
            }
#pragma unroll
            for (int mf = 0; mf < 4; mf++) {
                int row = wm * 64 + mf * 16 + a_r;
                ldsm4(a[mf], aLoB + swz(row, ks * 2 + a_cx));
            }
#pragma unroll
            for (int mf = 0; mf < 4; mf++)
#pragma unroll
                for (int nf = 0; nf < 4; nf++) {
                    if (PREC == 0)
                        mma16816(acc[mf][nf][0], acc[mf][nf][1], acc[mf][nf][2], acc[mf][nf][3],
                                 a[mf][0], a[mf][1], a[mf][2], a[mf][3], bh[nf][0], bh[nf][1]);
                    else
                        mma16816h(acc[mf][nf][0], acc[mf][nf][1], acc[mf][nf][2], acc[mf][nf][3],
                                  a[mf][0], a[mf][1], a[mf][2], a[mf][3], bh[nf][0], bh[nf][1]);
                }
        }
    };

    load(0);
    store();
    __syncthreads();
    for (int it = 1; it < TOT; it++) {
        load(it);
        mma_block();
        __syncthreads();
        store();
        __syncthreads();
    }
    mma_block();

    // Epilogue
#pragma unroll
    for (int mf = 0; mf < 4; mf++) {
        int r = m0 + wm * 64 + mf * 16 + (lane >> 2);
#pragma unroll
        for (int nf = 0; nf < 4; nf++) {
            int c = n0 + wn * 32 + nf * 8 + (lane & 3) * 2;
            float v0 = acc[mf][nf][0], v1 = acc[mf][nf][1];
            float v2 = acc[mf][nf][2], v3 = acc[mf][nf][3];
            if (EPI == 1) {
                float b0 = bias[c], b1 = bias[c + 1];
                float x0 = v0 + b0, x1 = v1 + b1, x2 = v2 + b0, x3 = v3 + b1;
                v0 = fminf(fmaxf(fmaxf(x0, 0.f) + log1pf(__expf(-fabsf(x0))), 1e-3f), 0.1f);
                v1 = fminf(fmaxf(fmaxf(x1, 0.f) + log1pf(__expf(-fabsf(x1))), 1e-3f), 0.1f);
                v2 = fminf(fmaxf(fmaxf(x2, 0.f) + log1pf(__expf(-fabsf(x2))), 1e-3f), 0.1f);
                v3 = fminf(fmaxf(fmaxf(x3, 0.f) + log1pf(__expf(-fabsf(x3))), 1e-3f), 0.1f);
            }
            if (EPI == 3) {
                if (n0 < 2048) {     // xs half -> fp16 hi/lo for conv
                    uint32_t h, l;
                    split2h(v0, v1, h, l);
                    *(uint32_t*)(xsh + (size_t)r * 2048 + c) = h;
                    *(uint32_t*)(xsl + (size_t)r * 2048 + c) = l;
                    split2h(v2, v3, h, l);
                    *(uint32_t*)(xsh + (size_t)(r + 8) * 2048 + c) = h;
                    *(uint32_t*)(xsl + (size_t)(r + 8) * 2048 + c) = l;
                } else {             // res half -> silu -> sres fp32
                    int cc = c - 2048;
                    *(float2*)(C + (size_t)r * ldc + cc)
                        = make_float2(silu(v0), silu(v1));
                    *(float2*)(C + (size_t)(r + 8) * ldc + cc)
                        = make_float2(silu(v2), silu(v3));
                }
            } else {
                *(float2*)(C + (size_t)r * ldc + c)       = make_float2(v0, v1);
                *(float2*)(C + (size_t)(r + 8) * ldc + c) = make_float2(v2, v3);
            }
        }
    }
}

// ---------------------------------------------------------------------------
// Halo-fused grouped causal conv, fp16 2-product:
// A = xs fp16 hi/lo (131-row halo), B = conv weights fp16 single, 4 taps.
// ---------------------------------------------------------------------------
#define CONV_STG  50176                      // 2*8704 (A hi/lo) + 4*8192 (B)
#define CONV_SMEM (2 * CONV_STG + 1024)

__global__ __launch_bounds__(256) void conv_halo(
    const h16* __restrict__ Ah, const h16* __restrict__ Al,   // xs [4096,2048]
    const h16* __restrict__ Bf,                               // convT fp16 [4][2048,1024]
    const float* __restrict__ bias, float* __restrict__ U)
{
    extern __shared__ char dyn[];
    const uint32_t rawb = smem_u32(dyn);
    const uint32_t base = (rawb + 1023u) & ~1023u;
    char* tp = dyn + (base - rawb);

    const int tid  = threadIdx.x;
    const int lane = tid & 31;
    const int wid  = tid >> 5;
    const int wm   = wid & 1;
    const int wn   = wid >> 1;
    const int m0   = blockIdx.y * 128;
    const int n0   = blockIdx.x * 128;
    const int colbase = (n0 >= 1024) ? 1024 : 0;
    const bool headok = (m0 & (LSEQ - 1)) != 0;

    const int a_r  = lane & 15;
    const int a_cx = lane >> 4;
    const int b_r  = (lane & 7) + ((lane >> 4) << 3);
    const int b_cx = (lane >> 3) & 1;

    float acc[4][4][4];
#pragma unroll
    for (int i = 0; i < 4; i++)
#pragma unroll
        for (int j = 0; j < 4; j++)
#pragma unroll
            for (int k = 0; k < 4; k++) acc[i][j][k] = 0.f;

    uint4 sa[6], rb1[4], rb2[4];

    auto loadA = [&](int kb) {
#pragma unroll
        for (int i = 0; i < 3; i++) {
            int c = tid + i * 256;
            if (i < 2 || c < 524) {
                int row = c >> 2, seg = c & 3;
                bool valid = headok || (row >= 3);
                long grow = (long)m0 - 3 + row;
                if (valid) {
                    sa[i * 2]     = *(const uint4*)(Ah + grow * 2048 + colbase + kb * 32 + seg * 8);
                    sa[i * 2 + 1] = *(const uint4*)(Al + grow * 2048 + colbase + kb * 32 + seg * 8);
                } else {
                    sa[i * 2]     = make_uint4(0, 0, 0, 0);
                    sa[i * 2 + 1] = make_uint4(0, 0, 0, 0);
                }
            }
        }
    };
    auto stsA = [&](int s) {
        char* sb = tp + s * CONV_STG;
#pragma unroll
        for (int i = 0; i < 3; i++) {
            int c = tid + i * 256;
            if (i < 2 || c < 524) {
                int row = c >> 2, seg = c & 3;
                uint32_t off = swz(row, seg);
                *(uint4*)(sb + off)        = sa[i * 2];
                *(uint4*)(sb + 8704 + off) = sa[i * 2 + 1];
            }
        }
    };
    // per half: 2 taps x 512 chunks = 1024 -> 4 per thread
    auto loadB = [&](int kb, int half, uint4* rb) {
#pragma unroll
        for (int i = 0; i < 4; i++) {
            int c = tid + i * 256;
            int tap = half * 2 + (c >> 9);
            int cc = c & 511;
            int row = cc >> 2, seg = cc & 3;
            rb[i] = *(const uint4*)(Bf + (size_t)tap * 2048 * 1024
                                       + (size_t)(n0 + row) * 1024 + kb * 32 + seg * 8);
        }
    };
    auto stsB = [&](int s, int half, uint4* rb) {
#pragma unroll
        for (int i = 0; i < 4; i++) {
            int c = tid + i * 256;
            int tap = half * 2 + (c >> 9);
            int cc = c & 511;
            int row = cc >> 2, seg = cc & 3;
            char* bb = tp + s * CONV_STG + 17408 + tap * 8192;
            *(uint4*)(bb + swz(row, seg)) = rb[i];
        }
    };
    auto mma_tap = [&](int s, int tap) {
        uint32_t aHiB = base + (uint32_t)s * CONV_STG;
        uint32_t aLoB = aHiB + 8704;
        uint32_t bB   = aHiB + 17408 + (uint32_t)tap * 8192;
#pragma unroll
        for (int ks = 0; ks < 2; ks++) {
            uint32_t a[4][4], bh[4][2];
#pragma unroll
            for (int mf = 0; mf < 4; mf++) {
                int row = wm * 64 + mf * 16 + a_r + tap;
                ldsm4(a[mf], aHiB + swz(row, ks * 2 + a_cx));
            }
#pragma unroll
            for (int p = 0; p < 2; p++) {
                int row = wn * 32 + p * 16 + b_r;
                uint32_t t[4];
                ldsm4(t, bB + swz(row, ks * 2 + b_cx));
                bh[p * 2][0] = t[0]; bh[p * 2][1] = t[1];
                bh[p * 2 + 1][0] = t[2]; bh[p * 2 + 1][1] = t[3];
            }
#pragma unroll
            for (int mf = 0; mf < 4; mf++)
#pragma unroll
                for (int nf = 0; nf < 4; nf++)
                    mma16816h(acc[mf][nf][0], acc[mf][nf][1], acc[mf][nf][2], acc[mf][nf][3],
                              a[mf][0], a[mf][1], a[mf][2], a[mf][3], bh[nf][0], bh[nf][1]);
#pragma unroll
            for (int mf = 0; mf < 4; mf++) {
                int row = wm * 64 + mf * 16 + a_r + tap;
                ldsm4(a[mf], aLoB + swz(row, ks * 2 + a_cx));
            }
#pragma unroll
            for (int mf = 0; mf < 4; mf++)
#pragma unroll
                for (int nf = 0; nf < 4; nf++)
                    mma16816h(acc[mf][nf][0], acc[mf][nf][1], acc[mf][nf][2], acc[mf][nf][3],
                              a[mf][0], a[mf][1], a[mf][2], a[mf][3], bh[nf][0], bh[nf][1]);
        }
    };

    loadA(0); loadB(0, 0, rb1); loadB(0, 1, rb2);
    stsA(0); stsB(0, 0, rb1); stsB(0, 1, rb2);
    __syncthreads();

    for (int kb = 0; kb < 32; kb++) {
        int cur = kb & 1, nxt = cur ^ 1;
        bool more = (kb + 1) < 32;
        if (more) { loadA(kb + 1); loadB(kb + 1, 0, rb1); }
        mma_tap(cur, 0);
        mma_tap(cur, 1);
        if (more) { stsA(nxt); stsB(nxt, 0, rb1); loadB(kb + 1, 1, rb2); }
        mma_tap(cur, 2);
        mma_tap(cur, 3);
        if (more) stsB(nxt, 1, rb2);
        __syncthreads();
    }

#pragma unroll
    for (int mf = 0; mf < 4; mf++) {
        int r = m0 + wm * 64 + mf * 16 + (lane >> 2);
#pragma unroll
        for (int nf = 0; nf < 4; nf++) {
            int c = n0 + wn * 32 + nf * 8 + (lane & 3) * 2;
            float b0 = bias[c], b1 = bias[c + 1];
            float v0 = silu(acc[mf][nf][0] + b0);
            float v1 = silu(acc[mf][nf][1] + b1);
            float v2 = silu(acc[mf][nf][2] + b0);
            float v3 = silu(acc[mf][nf][3] + b1);
            *(float2*)(U + (size_t)r * DINNER + c)       = make_float2(v0, v1);
            *(float2*)(U + (size_t)(r + 8) * DINNER + c) = make_float2(v2, v3);
        }
    }
}

// ---------------------------------------------------------------------------
// Fused weight preprocessing (one launch).  conv -> fp16 single now.
// ---------------------------------------------------------------------------
__global__ __launch_bounds__(256) void fused_transpose(
    const float* __restrict__ Win, const float* __restrict__ convk,
    const float* __restrict__ Wout, const float* __restrict__ Wdt,
    float* __restrict__ winT, h16* __restrict__ cTf,
    float* __restrict__ woutT, float* __restrict__ wdtT)
{
    int z = blockIdx.z;
    const float* src; int R, C;
    if (z == 0)      { src = Win;  R = 1024; C = 4096; }
    else if (z <= 4) { src = convk + (size_t)(z - 1) * 1024 * 2048; R = 1024; C = 2048; }
    else if (z == 5) { src = Wout; R = 2048; C = 1024; }
    else             { src = Wdt;  R = 64;   C = 2048; }
    if (blockIdx.x * 32 >= C || blockIdx.y * 32 >= R) return;

    __shared__ float t[32][33];
    int x = blockIdx.x * 32 + threadIdx.x;
#pragma unroll
    for (int j = 0; j < 4; j++) {
        int y = blockIdx.y * 32 + threadIdx.y + j * 8;
        t[threadIdx.y + j * 8][threadIdx.x] = src[(size_t)y * C + x];
    }
    __syncthreads();
    int x2 = blockIdx.y * 32 + threadIdx.x;
#pragma unroll
    for (int j = 0; j < 4; j++) {
        int y2 = blockIdx.x * 32 + threadIdx.y + j * 8;
        float v = t[threadIdx.x][threadIdx.y + j * 8];
        if (z == 0) {
            winT[(size_t)y2 * R + x2] = v;
        } else if (z <= 4) {
            cTf[(size_t)(z - 1) * 2048 * 1024 + (size_t)y2 * R + x2] = __float2half_rn(v);
        } else if (z == 5) {
            woutT[(size_t)y2 * R + x2] = v;
        } else {
            wdtT[(size_t)y2 * R + x2] = v;
        }
    }
}

// ---------------------------------------------------------------------------
// Split-K narrow GEMM (R9-proven, unchanged)
// ---------------------------------------------------------------------------
__global__ __launch_bounds__(256) void gemm_n96_partial(
    const float* __restrict__ A, const float* __restrict__ B,
    float* __restrict__ P)
{
    const int BK = 32, NN = 96, KC = 256, BM = 64;
    __shared__ float As[BK][BM];
    __shared__ float Bs[BK][NN];

    const int m0 = blockIdx.x * BM;
    const int kc = blockIdx.y;
    const int kbeg = kc * KC;
    const int tid = threadIdx.x;
    const int tx = tid & 15;
    const int ty = tid >> 4;

    float acc[4][6];
#pragma unroll
    for (int r = 0; r < 4; r++)
#pragma unroll
        for (int j = 0; j < 6; j++) acc[r][j] = 0.f;

    for (int k0 = kbeg; k0 < kbeg + KC; k0 += BK) {
#pragma unroll
        for (int i = 0; i < 2; i++) {
            int idx = tid + i * 256;
            int row = idx >> 3;
            int cv  = (idx & 7) * 4;
            float4 a = *(const float4*)(A + (size_t)(m0 + row) * DINNER + k0 + cv);
            As[cv + 0][row] = a.x; As[cv + 1][row] = a.y;
            As[cv + 2][row] = a.z; As[cv + 3][row] = a.w;
        }
#pragma unroll
        for (int i = 0; i < 3; i++) {
            int idx  = tid + i * 256;
            int rowB = idx / 24;
            int cv   = (idx % 24) * 4;
            *(float4*)(&Bs[rowB][cv]) =
                *(const float4*)(B + (size_t)(k0 + rowB) * NN + cv);
        }
        __syncthreads();
#pragma unroll
        for (int k = 0; k < BK; k++) {
            float a[4];
            *(float4*)a = *(const float4*)(&As[k][ty * 4]);
            float b[6];
            *(float2*)(b)     = *(const float2*)(&Bs[k][tx * 6]);
            *(float2*)(b + 2) = *(const float2*)(&Bs[k][tx * 6 + 2]);
            *(float2*)(b + 4) = *(const float2*)(&Bs[k][tx * 6 + 4]);
#pragma unroll
            for (int r = 0; r < 4; r++)
#pragma unroll
                for (int j = 0; j < 6; j++)
                    acc[r][j] = fmaf(a[r], b[j], acc[r][j]);
        }
        __syncthreads();
    }
    float* out = P + (size_t)kc * BLROWS * 96;
#pragma unroll
    for (int r = 0; r < 4; r++) {
        int m = m0 + ty * 4 + r;
#pragma unroll
        for (int j = 0; j < 6; j++)
            out[(size_t)m * 96 + tx * 6 + j] = acc[r][j];
    }
}

__global__ __launch_bounds__(256) void gemm_n96_reduce(
    const float* __restrict__ P, float* __restrict__ C)
{
    size_t i = ((size_t)blockIdx.x * blockDim.x + threadIdx.x) * 4;
    const size_t S = (size_t)BLROWS * 96;
    float4 s = *(const float4*)(P + i);
#pragma unroll
    for (int kc = 1; kc < 8; kc++) {
        float4 v = *(const float4*)(P + kc * S + i);
        s.x += v.x; s.y += v.y; s.z += v.z; s.w += v.w;
    }
    *(float4*)(C + i) = s;
}

// ---------------------------------------------------------------------------
// Chunked parallel scan (R10-proven, unchanged)
// ---------------------------------------------------------------------------
__global__ __launch_bounds__(256) void scan_pass1(
    const float* __restrict__ delta, const float* __restrict__ u,
    const float* __restrict__ dbc, const float* __restrict__ A_log,
    float* __restrict__ P, float* __restrict__ H)
{
    const int tid  = threadIdx.x;
    const int lane = tid & 31;
    const int w    = tid >> 5;
    const int ng   = lane & 3;
    const int dl   = lane >> 2;
    const int d    = blockIdx.x * 64 + w * 8 + dl;
    const int c    = blockIdx.y;
    const int b    = blockIdx.z;

    float4 al = *(const float4*)(A_log + d * DSTATE + ng * 4);
    const float a0 = -__expf(al.x), a1 = -__expf(al.y);
    const float a2 = -__expf(al.z), a3 = -__expf(al.w);

    const size_t trow = (size_t)b * LSEQ + (size_t)c * TC;
    const float* dp  = delta + trow * DINNER + d;
    const float* up  = u     + trow * DINNER + d;
    const float* bcp = dbc   + trow * 96 + DTRANK + ng * 4;

    float h0 = 0.f, h1 = 0.f, h2 = 0.f, h3 = 0.f;
    float p0 = 1.f, p1 = 1.f, p2 = 1.f, p3 = 1.f;
    for (int t = 0; t < TC; t++) {
        float de = dp[(size_t)t * DINNER];
        float uu = up[(size_t)t * DINNER];
        float4 Bv = *(const float4*)(bcp + t * 96);
        float dA0 = __expf(de * a0), dA1 = __expf(de * a1);
        float dA2 = __expf(de * a2), dA3 = __expf(de * a3);
        float du = de * uu;
        p0 *= dA0; p1 *= dA1; p2 *= dA2; p3 *= dA3;
        h0 = fmaf(dA0, h0, du * Bv.x);
        h1 = fmaf(dA1, h1, du * Bv.y);
        h2 = fmaf(dA2, h2, du * Bv.z);
        h3 = fmaf(dA3, h3, du * Bv.w);
    }
    size_t o = (((size_t)b * NCH + c) * DINNER + d) * DSTATE + ng * 4;
    *(float4*)(P + o) = make_float4(p0, p1, p2, p3);
    *(float4*)(H + o) = make_float4(h0, h1, h2, h3);
}

__global__ __launch_bounds__(256) void scan_pass2(
    const float* __restrict__ P, const float* __restrict__ H,
    float* __restrict__ HIN)
{
    int idx = blockIdx.x * blockDim.x + threadIdx.x;
    int n = idx & 15;
    int d = (idx >> 4) & (DINNER - 1);
    int b = idx >> 15;
    float hin = 0.f;
#pragma unroll
    for (int c = 0; c < NCH; c++) {
        size_t o = (((size_t)b * NCH + c) * DINNER + d) * DSTATE + n;
        HIN[o] = hin;
        hin = fmaf(P[o], hin, H[o]);
    }
}

__global__ __launch_bounds__(256) void scan_pass3(
    const float* __restrict__ delta, const float* __restrict__ u,
    const float* __restrict__ dbc, const float* __restrict__ A_log,
    const float* __restrict__ Dp, const float* __restrict__ sres,
    const float* __restrict__ HIN, float* __restrict__ Y)
{
    const int tid  = threadIdx.x;
    const int lane = tid & 31;
    const int w    = tid >> 5;
    const int ng   = lane & 3;
    const int dl   = lane >> 2;
    const int d    = blockIdx.x * 64 + w * 8 + dl;
    const int c    = blockIdx.y;
    const int b    = blockIdx.z;

    float4 al = *(const float4*)(A_log + d * DSTATE + ng * 4);
    const float a0 = -__expf(al.x), a1 = -__expf(al.y);
    const float a2 = -__expf(al.z), a3 = -__expf(al.w);
    const float Dd = Dp[d];

    const size_t trow = (size_t)b * LSEQ + (size_t)c * TC;
    const float* dp  = delta + trow * DINNER + d;
    const float* up  = u     + trow * DINNER + d;
    const float* rp  = sres  + trow * DINNER + d;
    const float* bcp = dbc   + trow * 96 + DTRANK + ng * 4;
    float*       yp  = Y     + trow * DINNER + d;

    size_t o = (((size_t)b * NCH + c) * DINNER + d) * DSTATE + ng * 4;
    float4 hv = *(const float4*)(HIN + o);
    float h0 = hv.x, h1 = hv.y, h2 = hv.z, h3 = hv.w;

    for (int t = 0; t < TC; t++) {
        float de = dp[(size_t)t * DINNER];
        float uu = up[(size_t)t * DINNER];
        float4 Bv = *(const float4*)(bcp + t * 96);
        float4 Cv = *(const float4*)(bcp + t * 96 + DSTATE);
        float dA0 = __expf(de * a0), dA1 = __expf(de * a1);
        float dA2 = __expf(de * a2), dA3 = __expf(de * a3);
        float du = de * uu;
        h0 = fmaf(dA0, h0, du * Bv.x);
        h1 = fmaf(dA1, h1, du * Bv.y);
        h2 = fmaf(dA2, h2, du * Bv.z);
        h3 = fmaf(dA3, h3, du * Bv.w);
        float pp = h0 * Cv.x + h1 * Cv.y + h2 * Cv.z + h3 * Cv.w;
        pp += __shfl_xor_sync(0xffffffffu, pp, 1);
        pp += __shfl_xor_sync(0xffffffffu, pp, 2);
        if (ng == 0)
            yp[(size_t)t * DINNER] = fmaf(uu, Dd, pp) * rp[(size_t)t * DINNER];
    }
}

// ---------------------------------------------------------------------------
// Launch
// ---------------------------------------------------------------------------
extern "C" void kernel_launch(void* const* d_in, const int* in_sizes, int n_in,
                              void* d_out, int out_size)
{
    (void)in_sizes; (void)n_in; (void)out_size;
    const float* x      = (const float*)d_in[0];
    const float* W_in   = (const float*)d_in[1];
    const float* conv_k = (const float*)d_in[2];
    const float* conv_b = (const float*)d_in[3];
    const float* W_x    = (const float*)d_in[4];
    const float* W_dt   = (const float*)d_in[5];
    const float* b_dt   = (const float*)d_in[6];
    const float* A_log  = (const float*)d_in[7];
    const float* Dvec   = (const float*)d_in[8];
    const float* W_out  = (const float*)d_in[9];
    float* out = (float*)d_out;

    h16 *xsh, *xsl, *convTf;
    float *sres, *u, *dbc, *dbcp, *delta, *y, *winT, *woutT, *wdtT;
    float *scP, *scH, *scHi;
    cudaGetSymbolAddress((void**)&xsh,   g_xsh);
    cudaGetSymbolAddress((void**)&xsl,   g_xsl);
    cudaGetSymbolAddress((void**)&sres,  g_sres);
    cudaGetSymbolAddress((void**)&u,     g_u);
    cudaGetSymbolAddress((void**)&dbc,   g_dbc);
    cudaGetSymbolAddress((void**)&dbcp,  g_dbc_part);
    cudaGetSymbolAddress((void**)&delta, g_delta);
    cudaGetSymbolAddress((void**)&y,     g_y);
    cudaGetSymbolAddress((void**)&winT,  g_WinT);
    cudaGetSymbolAddress((void**)&convTf, g_convTf);
    cudaGetSymbolAddress((void**)&woutT, g_WoutT);
    cudaGetSymbolAddress((void**)&wdtT,  g_WdtT);
    cudaGetSymbolAddress((void**)&scP,   g_scanP);
    cudaGetSymbolAddress((void**)&scH,   g_scanH);
    cudaGetSymbolAddress((void**)&scHi,  g_scanHi);

    cudaFuncSetAttribute(conv_halo, cudaFuncAttributeMaxDynamicSharedMemorySize, CONV_SMEM);

    // 0) all weight preprocessing in ONE launch
    fused_transpose<<<dim3(128, 64, 7), dim3(32, 8)>>>(
        W_in, conv_k, W_out, W_dt, winT, convTf, woutT, wdtT);

    // 1) GEMM1 (bf16x3): xs -> fp16 hi/lo, silu(res) -> sres fp32
    mma_gemm<3, 0><<<dim3(32, 32), 256>>>(
        x, DMODEL, winT, DMODEL, sres, DINNER, DMODEL, nullptr, xsh, xsl);

    // 2) halo-fused grouped causal conv (fp16 2-product) + bias + silu -> u
    conv_halo<<<dim3(16, 32), 256, CONV_SMEM>>>(
        xsh, xsl, convTf, conv_b, u);

    // 3) dbc = u @ W_x
    gemm_n96_partial<<<dim3(64, 8), 256>>>(u, W_x, dbcp);
    gemm_n96_reduce<<<(BLROWS * 96 / 4) / 256, 256>>>(dbcp, dbc);

    // 4) delta = clip(softplus(dt_raw @ W_dt + b_dt))  (bf16x3)
    mma_gemm<1, 0><<<dim3(16, 32), 256>>>(
        dbc, 96, wdtT, DTRANK, delta, DINNER, DTRANK, b_dt, nullptr, nullptr);

    // 5) chunked parallel scan (+ fused gate) -> y fp32
    scan_pass1<<<dim3(32, NCH, 2), 256>>>(delta, u, dbc, A_log, scP, scH);
    scan_pass2<<<256, 256>>>(scP, scH, scHi);
    scan_pass3<<<dim3(32, NCH, 2), 256>>>(delta, u, dbc, A_log, Dvec, sres, scHi, y);

    // 6) out = y @ W_out  (fp16 2-product)
    mma_gemm<0, 1><<<dim3(8, 32), 256>>>(
        y, DINNER, woutT, DINNER, out, DMODEL, DINNER, nullptr, nullptr, nullptr);
}

// round 12
// speedup vs baseline: 2.2604x; 1.1809x over previous
#include <cuda_runtime.h>
#include <cuda_bf16.h>
#include <cuda_fp16.h>
#include <cstdint>

// Problem constants
#define BLROWS 4096   // B*L = 2*2048
#define LSEQ   2048
#define DMODEL 1024
#define DINNER 2048
#define DSTATE 16
#define DTRANK 64
#define NCH    16     // scan chunks
#define TC     128    // chunk length

typedef __nv_bfloat16 bf16;
typedef __half h16;

// ---------------------------------------------------------------------------
// Scratch (device globals)
// ---------------------------------------------------------------------------
__device__ h16   g_xsh[(size_t)BLROWS * DINNER];     // xs fp16 hi (from GEMM1)
__device__ h16   g_xsl[(size_t)BLROWS * DINNER];     // xs fp16 lo
__device__ float g_sres[(size_t)BLROWS * DINNER];
__device__ float g_u  [(size_t)BLROWS * DINNER];
__device__ float g_dbc[(size_t)BLROWS * 96];
__device__ float g_dbc_part[(size_t)8 * BLROWS * 96];
__device__ float g_delta[(size_t)BLROWS * DINNER];
__device__ float g_y [(size_t)BLROWS * DINNER];
// scan chunk scratch: [b][c][d][n]
__device__ float g_scanP [(size_t)2 * NCH * DINNER * DSTATE];
__device__ float g_scanH [(size_t)2 * NCH * DINNER * DSTATE];
__device__ float g_scanHi[(size_t)2 * NCH * DINNER * DSTATE];
// Transposed weights
__device__ float g_WinT [(size_t)4096 * 1024];                 // fp32
__device__ h16   g_convTf[(size_t)4 * 2048 * 1024];            // fp16 single
__device__ float g_WoutT[(size_t)1024 * 2048];                 // fp32
__device__ float g_WdtT [(size_t)2048 * 64];                   // fp32

// ---------------------------------------------------------------------------
// PTX helpers
// ---------------------------------------------------------------------------
__device__ __forceinline__ uint32_t smem_u32(const void* p) {
    uint32_t a;
    asm("{ .reg .u64 t; cvta.to.shared.u64 t, %1; cvt.u32.u64 %0, t; }"
        : "=r"(a) : "l"(p));
    return a;
}
__device__ __forceinline__ void ldsm4(uint32_t* r, uint32_t addr) {
    asm volatile("ldmatrix.sync.aligned.m8n8.x4.shared.b16 {%0,%1,%2,%3}, [%4];"
        : "=r"(r[0]), "=r"(r[1]), "=r"(r[2]), "=r"(r[3]) : "r"(addr));
}
__device__ __forceinline__ void mma16816(
    float& d0, float& d1, float& d2, float& d3,
    uint32_t a0, uint32_t a1, uint32_t a2, uint32_t a3,
    uint32_t b0, uint32_t b1)
{
    asm volatile(
        "mma.sync.aligned.m16n8k16.row.col.f32.bf16.bf16.f32 "
        "{%0,%1,%2,%3}, {%4,%5,%6,%7}, {%8,%9}, {%0,%1,%2,%3};"
        : "+f"(d0), "+f"(d1), "+f"(d2), "+f"(d3)
        : "r"(a0), "r"(a1), "r"(a2), "r"(a3), "r"(b0), "r"(b1));
}
__device__ __forceinline__ void mma16816h(
    float& d0, float& d1, float& d2, float& d3,
    uint32_t a0, uint32_t a1, uint32_t a2, uint32_t a3,
    uint32_t b0, uint32_t b1)
{
    asm volatile(
        "mma.sync.aligned.m16n8k16.row.col.f32.f16.f16.f32 "
        "{%0,%1,%2,%3}, {%4,%5,%6,%7}, {%8,%9}, {%0,%1,%2,%3};"
        : "+f"(d0), "+f"(d1), "+f"(d2), "+f"(d3)
        : "r"(a0), "r"(a1), "r"(a2), "r"(a3), "r"(b0), "r"(b1));
}
// bf16 2-way split of two floats -> packed bf16x2 (hi, lo)
__device__ __forceinline__ void split2(float x, float y, uint32_t& hi, uint32_t& lo) {
    bf16 hx = __float2bfloat16_rn(x);
    bf16 hy = __float2bfloat16_rn(y);
    __nv_bfloat162 h; h.x = hx; h.y = hy;
    __nv_bfloat162 l = __floats2bfloat162_rn(x - __bfloat162float(hx),
                                             y - __bfloat162float(hy));
    hi = *reinterpret_cast<uint32_t*>(&h);
    lo = *reinterpret_cast<uint32_t*>(&l);
}
// fp16 2-way split (A exact to ~2^-22)
__device__ __forceinline__ void split2h(float x, float y, uint32_t& hi, uint32_t& lo) {
    h16 hx = __float2half_rn(x);
    h16 hy = __float2half_rn(y);
    __half2 h = __halves2half2(hx, hy);
    __half2 l = __floats2half2_rn(x - __half2float(hx), y - __half2float(hy));
    hi = *reinterpret_cast<uint32_t*>(&h);
    lo = *reinterpret_cast<uint32_t*>(&l);
}
// SMEM tile row = 64B (32 elems) in 4x16B chunks, xor-swizzled
__device__ __forceinline__ uint32_t swz(int row, int chunk) {
    return (uint32_t)((row << 6) + (((chunk ^ ((row >> 1) & 3)) & 3) << 4));
}
__device__ __forceinline__ float silu(float v) { return v / (1.f + __expf(-v)); }

// ---------------------------------------------------------------------------
// mma GEMM.  PREC=0: bf16x3 (R3-proven).  PREC=1: fp16 A-split x2 products,
// fp16-single B.  C-tile[128,128] = A[M,K] @ Bt[N,K]^T.
// EPI: 0 fp32 store; 1 softplus+clip(+bias); 3 GEMM1 dual out (xs fp16 split).
// ---------------------------------------------------------------------------
template <int EPI, int PREC>
__global__ __launch_bounds__(256) void mma_gemm(
    const float* __restrict__ A, int lda,
    const float* __restrict__ Bt, int ldb,
    float* __restrict__ C, int ldc,
    int K, const float* __restrict__ bias,
    h16* __restrict__ xsh, h16* __restrict__ xsl)
{
    __shared__ __align__(16) char sAhi[8192], sAlo[8192], sBhi[8192], sBlo[8192];

    const int tid  = threadIdx.x;
    const int lane = tid & 31;
    const int wid  = tid >> 5;
    const int wm   = wid & 1;
    const int wn   = wid >> 1;
    const int m0   = blockIdx.y * 128;
    const int n0   = blockIdx.x * 128;
    const int TOT  = K >> 5;

    const uint32_t aHiB = smem_u32(sAhi), aLoB = smem_u32(sAlo);
    const uint32_t bHiB = smem_u32(sBhi), bLoB = smem_u32(sBlo);

    const int a_r  = lane & 15;
    const int a_cx = lane >> 4;
    const int b_r  = (lane & 7) + ((lane >> 4) << 3);
    const int b_cx = (lane >> 3) & 1;

    float acc[4][4][4];
#pragma unroll
    for (int i = 0; i < 4; i++)
#pragma unroll
        for (int j = 0; j < 4; j++)
#pragma unroll
            for (int k = 0; k < 4; k++) acc[i][j][k] = 0.f;

    float4 pa[4], pb[4];

    auto load = [&](int kb) {
#pragma unroll
        for (int i = 0; i < 4; i++) {
            int idx = tid + i * 256;
            int row = idx >> 3, seg = idx & 7;
            pa[i] = *(const float4*)(A + (size_t)(m0 + row) * lda + kb * 32 + seg * 4);
            pb[i] = *(const float4*)(Bt + (size_t)(n0 + row) * ldb + kb * 32 + seg * 4);
        }
    };

    auto store = [&]() {
#pragma unroll
        for (int i = 0; i < 4; i++) {
            int idx = tid + i * 256;
            int row = idx >> 3, seg = idx & 7;
            uint32_t off = swz(row, seg >> 1) + (seg & 1) * 8;
            uint2 h, l;
            if (PREC == 0) {
                split2(pa[i].x, pa[i].y, h.x, l.x);
                split2(pa[i].z, pa[i].w, h.y, l.y);
                *(uint2*)(sAhi + off) = h;
                *(uint2*)(sAlo + off) = l;
                split2(pb[i].x, pb[i].y, h.x, l.x);
                split2(pb[i].z, pb[i].w, h.y, l.y);
                *(uint2*)(sBhi + off) = h;
                *(uint2*)(sBlo + off) = l;
            } else {
                split2h(pa[i].x, pa[i].y, h.x, l.x);
                split2h(pa[i].z, pa[i].w, h.y, l.y);
                *(uint2*)(sAhi + off) = h;
                *(uint2*)(sAlo + off) = l;
                __half2 b0 = __floats2half2_rn(pb[i].x, pb[i].y);
                __half2 b1 = __floats2half2_rn(pb[i].z, pb[i].w);
                h.x = *reinterpret_cast<uint32_t*>(&b0);
                h.y = *reinterpret_cast<uint32_t*>(&b1);
                *(uint2*)(sBhi + off) = h;
            }
        }
    };

    auto mma_block = [&]() {
#pragma unroll
        for (int ks = 0; ks < 2; ks++) {
            uint32_t a[4][4], bh[4][2];
#pragma unroll
            for (int mf = 0; mf < 4; mf++) {
                int row = wm * 64 + mf * 16 + a_r;
                ldsm4(a[mf], aHiB + swz(row, ks * 2 + a_cx));
            }
#pragma unroll
            for (int p = 0; p < 2; p++) {
                int row = wn * 32 + p * 16 + b_r;
                uint32_t t[4];
                ldsm4(t, bHiB + swz(row, ks * 2 + b_cx));
                bh[p * 2][0] = t[0]; bh[p * 2][1] = t[1];
                bh[p * 2 + 1][0] = t[2]; bh[p * 2 + 1][1] = t[3];
            }
#pragma unroll
            for (int mf = 0; mf < 4; mf++)
#pragma unroll
                for (int nf = 0; nf < 4; nf++) {
                    if (PREC == 0)
                        mma16816(acc[mf][nf][0], acc[mf][nf][1], acc[mf][nf][2], acc[mf][nf][3],
                                 a[mf][0], a[mf][1], a[mf][2], a[mf][3], bh[nf][0], bh[nf][1]);
                    else
                        mma16816h(acc[mf][nf][0], acc[mf][nf][1], acc[mf][nf][2], acc[mf][nf][3],
                                  a[mf][0], a[mf][1], a[mf][2], a[mf][3], bh[nf][0], bh[nf][1]);
                }
            if (PREC == 0) {
                uint32_t bx[4][2];
#pragma unroll
                for (int p = 0; p < 2; p++) {
                    int row = wn * 32 + p * 16 + b_r;
                    uint32_t t[4];
                    ldsm4(t, bLoB + swz(row, ks * 2 + b_cx));
                    bx[p * 2][0] = t[0]; bx[p * 2][1] = t[1];
                    bx[p * 2 + 1][0] = t[2]; bx[p * 2 + 1][1] = t[3];
                }
#pragma unroll
                for (int mf = 0; mf < 4; mf++)
#pragma unroll
                    for (int nf = 0; nf < 4; nf++)
                        mma16816(acc[mf][nf][0], acc[mf][nf][1], acc[mf][nf][2], acc[mf][nf][3],
                                 a[mf][0], a[mf][1], a[mf][2], a[mf][3], bx[nf][0], bx[nf][1]);
            }
#pragma unroll
            for (int mf = 0; mf < 4; mf++) {
                int row = wm * 64 + mf * 16 + a_r;
                ldsm4(a[mf], aLoB + swz(row, ks * 2 + a_cx));
            }
#pragma unroll
            for (int mf = 0; mf < 4; mf++)
#pragma unroll
                for (int nf = 0; nf < 4; nf++) {
                    if (PREC == 0)
                        mma16816(acc[mf][nf][0], acc[mf][nf][1], acc[mf][nf][2], acc[mf][nf][3],
                                 a[mf][0], a[mf][1], a[mf][2], a[mf][3], bh[nf][0], bh[nf][1]);
                    else
                        mma16816h(acc[mf][nf][0], acc[mf][nf][1], acc[mf][nf][2], acc[mf][nf][3],
                                  a[mf][0], a[mf][1], a[mf][2], a[mf][3], bh[nf][0], bh[nf][1]);
                }
        }
    };

    load(0);
    store();
    __syncthreads();
    for (int it = 1; it < TOT; it++) {
        load(it);
        mma_block();
        __syncthreads();
        store();
        __syncthreads();
    }
    mma_block();

    // Epilogue
#pragma unroll
    for (int mf = 0; mf < 4; mf++) {
        int r = m0 + wm * 64 + mf * 16 + (lane >> 2);
#pragma unroll
        for (int nf = 0; nf < 4; nf++) {
            int c = n0 + wn * 32 + nf * 8 + (lane & 3) * 2;
            float v0 = acc[mf][nf][0], v1 = acc[mf][nf][1];
            float v2 = acc[mf][nf][2], v3 = acc[mf][nf][3];
            if (EPI == 1) {
                float b0 = bias[c], b1 = bias[c + 1];
                float x0 = v0 + b0, x1 = v1 + b1, x2 = v2 + b0, x3 = v3 + b1;
                v0 = fminf(fmaxf(fmaxf(x0, 0.f) + log1pf(__expf(-fabsf(x0))), 1e-3f), 0.1f);
                v1 = fminf(fmaxf(fmaxf(x1, 0.f) + log1pf(__expf(-fabsf(x1))), 1e-3f), 0.1f);
                v2 = fminf(fmaxf(fmaxf(x2, 0.f) + log1pf(__expf(-fabsf(x2))), 1e-3f), 0.1f);
                v3 = fminf(fmaxf(fmaxf(x3, 0.f) + log1pf(__expf(-fabsf(x3))), 1e-3f), 0.1f);
            }
            if (EPI == 3) {
                if (n0 < 2048) {     // xs half -> fp16 hi/lo for conv
                    uint32_t h, l;
                    split2h(v0, v1, h, l);
                    *(uint32_t*)(xsh + (size_t)r * 2048 + c) = h;
                    *(uint32_t*)(xsl + (size_t)r * 2048 + c) = l;
                    split2h(v2, v3, h, l);
                    *(uint32_t*)(xsh + (size_t)(r + 8) * 2048 + c) = h;
                    *(uint32_t*)(xsl + (size_t)(r + 8) * 2048 + c) = l;
                } else {             // res half -> silu -> sres fp32
                    int cc = c - 2048;
                    *(float2*)(C + (size_t)r * ldc + cc)
                        = make_float2(silu(v0), silu(v1));
                    *(float2*)(C + (size_t)(r + 8) * ldc + cc)
                        = make_float2(silu(v2), silu(v3));
                }
            } else {
                *(float2*)(C + (size_t)r * ldc + c)       = make_float2(v0, v1);
                *(float2*)(C + (size_t)(r + 8) * ldc + c) = make_float2(v2, v3);
            }
        }
    }
}

// ---------------------------------------------------------------------------
// Halo-fused grouped causal conv, fp16 2-product (R11-proven, unchanged)
// ---------------------------------------------------------------------------
#define CONV_STG  50176                      // 2*8704 (A hi/lo) + 4*8192 (B)
#define CONV_SMEM (2 * CONV_STG + 1024)

__global__ __launch_bounds__(256) void conv_halo(
    const h16* __restrict__ Ah, const h16* __restrict__ Al,   // xs [4096,2048]
    const h16* __restrict__ Bf,                               // convT fp16 [4][2048,1024]
    const float* __restrict__ bias, float* __restrict__ U)
{
    extern __shared__ char dyn[];
    const uint32_t rawb = smem_u32(dyn);
    const uint32_t base = (rawb + 1023u) & ~1023u;
    char* tp = dyn + (base - rawb);

    const int tid  = threadIdx.x;
    const int lane = tid & 31;
    const int wid  = tid >> 5;
    const int wm   = wid & 1;
    const int wn   = wid >> 1;
    const int m0   = blockIdx.y * 128;
    const int n0   = blockIdx.x * 128;
    const int colbase = (n0 >= 1024) ? 1024 : 0;
    const bool headok = (m0 & (LSEQ - 1)) != 0;

    const int a_r  = lane & 15;
    const int a_cx = lane >> 4;
    const int b_r  = (lane & 7) + ((lane >> 4) << 3);
    const int b_cx = (lane >> 3) & 1;

    float acc[4][4][4];
#pragma unroll
    for (int i = 0; i < 4; i++)
#pragma unroll
        for (int j = 0; j < 4; j++)
#pragma unroll
            for (int k = 0; k < 4; k++) acc[i][j][k] = 0.f;

    uint4 sa[6], rb1[4], rb2[4];

    auto loadA = [&](int kb) {
#pragma unroll
        for (int i = 0; i < 3; i++) {
            int c = tid + i * 256;
            if (i < 2 || c < 524) {
                int row = c >> 2, seg = c & 3;
                bool valid = headok || (row >= 3);
                long grow = (long)m0 - 3 + row;
                if (valid) {
                    sa[i * 2]     = *(const uint4*)(Ah + grow * 2048 + colbase + kb * 32 + seg * 8);
                    sa[i * 2 + 1] = *(const uint4*)(Al + grow * 2048 + colbase + kb * 32 + seg * 8);
                } else {
                    sa[i * 2]     = make_uint4(0, 0, 0, 0);
                    sa[i * 2 + 1] = make_uint4(0, 0, 0, 0);
                }
            }
        }
    };
    auto stsA = [&](int s) {
        char* sb = tp + s * CONV_STG;
#pragma unroll
        for (int i = 0; i < 3; i++) {
            int c = tid + i * 256;
            if (i < 2 || c < 524) {
                int row = c >> 2, seg = c & 3;
                uint32_t off = swz(row, seg);
                *(uint4*)(sb + off)        = sa[i * 2];
                *(uint4*)(sb + 8704 + off) = sa[i * 2 + 1];
            }
        }
    };
    auto loadB = [&](int kb, int half, uint4* rb) {
#pragma unroll
        for (int i = 0; i < 4; i++) {
            int c = tid + i * 256;
            int tap = half * 2 + (c >> 9);
            int cc = c & 511;
            int row = cc >> 2, seg = cc & 3;
            rb[i] = *(const uint4*)(Bf + (size_t)tap * 2048 * 1024
                                       + (size_t)(n0 + row) * 1024 + kb * 32 + seg * 8);
        }
    };
    auto stsB = [&](int s, int half, uint4* rb) {
#pragma unroll
        for (int i = 0; i < 4; i++) {
            int c = tid + i * 256;
            int tap = half * 2 + (c >> 9);
            int cc = c & 511;
            int row = cc >> 2, seg = cc & 3;
            char* bb = tp + s * CONV_STG + 17408 + tap * 8192;
            *(uint4*)(bb + swz(row, seg)) = rb[i];
        }
    };
    auto mma_tap = [&](int s, int tap) {
        uint32_t aHiB = base + (uint32_t)s * CONV_STG;
        uint32_t aLoB = aHiB + 8704;
        uint32_t bB   = aHiB + 17408 + (uint32_t)tap * 8192;
#pragma unroll
        for (int ks = 0; ks < 2; ks++) {
            uint32_t a[4][4], bh[4][2];
#pragma unroll
            for (int mf = 0; mf < 4; mf++) {
                int row = wm * 64 + mf * 16 + a_r + tap;
                ldsm4(a[mf], aHiB + swz(row, ks * 2 + a_cx));
            }
#pragma unroll
            for (int p = 0; p < 2; p++) {
                int row = wn * 32 + p * 16 + b_r;
                uint32_t t[4];
                ldsm4(t, bB + swz(row, ks * 2 + b_cx));
                bh[p * 2][0] = t[0]; bh[p * 2][1] = t[1];
                bh[p * 2 + 1][0] = t[2]; bh[p * 2 + 1][1] = t[3];
            }
#pragma unroll
            for (int mf = 0; mf < 4; mf++)
#pragma unroll
                for (int nf = 0; nf < 4; nf++)
                    mma16816h(acc[mf][nf][0], acc[mf][nf][1], acc[mf][nf][2], acc[mf][nf][3],
                              a[mf][0], a[mf][1], a[mf][2], a[mf][3], bh[nf][0], bh[nf][1]);
#pragma unroll
            for (int mf = 0; mf < 4; mf++) {
                int row = wm * 64 + mf * 16 + a_r + tap;
                ldsm4(a[mf], aLoB + swz(row, ks * 2 + a_cx));
            }
#pragma unroll
            for (int mf = 0; mf < 4; mf++)
#pragma unroll
                for (int nf = 0; nf < 4; nf++)
                    mma16816h(acc[mf][nf][0], acc[mf][nf][1], acc[mf][nf][2], acc[mf][nf][3],
                              a[mf][0], a[mf][1], a[mf][2], a[mf][3], bh[nf][0], bh[nf][1]);
        }
    };

    loadA(0); loadB(0, 0, rb1); loadB(0, 1, rb2);
    stsA(0); stsB(0, 0, rb1); stsB(0, 1, rb2);
    __syncthreads();

    for (int kb = 0; kb < 32; kb++) {
        int cur = kb & 1, nxt = cur ^ 1;
        bool more = (kb + 1) < 32;
        if (more) { loadA(kb + 1); loadB(kb + 1, 0, rb1); }
        mma_tap(cur, 0);
        mma_tap(cur, 1);
        if (more) { stsA(nxt); stsB(nxt, 0, rb1); loadB(kb + 1, 1, rb2); }
        mma_tap(cur, 2);
        mma_tap(cur, 3);
        if (more) stsB(nxt, 1, rb2);
        __syncthreads();
    }

#pragma unroll
    for (int mf = 0; mf < 4; mf++) {
        int r = m0 + wm * 64 + mf * 16 + (lane >> 2);
#pragma unroll
        for (int nf = 0; nf < 4; nf++) {
            int c = n0 + wn * 32 + nf * 8 + (lane & 3) * 2;
            float b0 = bias[c], b1 = bias[c + 1];
            float v0 = silu(acc[mf][nf][0] + b0);
            float v1 = silu(acc[mf][nf][1] + b1);
            float v2 = silu(acc[mf][nf][2] + b0);
            float v3 = silu(acc[mf][nf][3] + b1);
            *(float2*)(U + (size_t)r * DINNER + c)       = make_float2(v0, v1);
            *(float2*)(U + (size_t)(r + 8) * DINNER + c) = make_float2(v2, v3);
        }
    }
}

// ---------------------------------------------------------------------------
// Fused weight preprocessing (one launch)
// ---------------------------------------------------------------------------
__global__ __launch_bounds__(256) void fused_transpose(
    const float* __restrict__ Win, const float* __restrict__ convk,
    const float* __restrict__ Wout, const float* __restrict__ Wdt,
    float* __restrict__ winT, h16* __restrict__ cTf,
    float* __restrict__ woutT, float* __restrict__ wdtT)
{
    int z = blockIdx.z;
    const float* src; int R, C;
    if (z == 0)      { src = Win;  R = 1024; C = 4096; }
    else if (z <= 4) { src = convk + (size_t)(z - 1) * 1024 * 2048; R = 1024; C = 2048; }
    else if (z == 5) { src = Wout; R = 2048; C = 1024; }
    else             { src = Wdt;  R = 64;   C = 2048; }
    if (blockIdx.x * 32 >= C || blockIdx.y * 32 >= R) return;

    __shared__ float t[32][33];
    int x = blockIdx.x * 32 + threadIdx.x;
#pragma unroll
    for (int j = 0; j < 4; j++) {
        int y = blockIdx.y * 32 + threadIdx.y + j * 8;
        t[threadIdx.y + j * 8][threadIdx.x] = src[(size_t)y * C + x];
    }
    __syncthreads();
    int x2 = blockIdx.y * 32 + threadIdx.x;
#pragma unroll
    for (int j = 0; j < 4; j++) {
        int y2 = blockIdx.x * 32 + threadIdx.y + j * 8;
        float v = t[threadIdx.x][threadIdx.y + j * 8];
        if (z == 0) {
            winT[(size_t)y2 * R + x2] = v;
        } else if (z <= 4) {
            cTf[(size_t)(z - 1) * 2048 * 1024 + (size_t)y2 * R + x2] = __float2half_rn(v);
        } else if (z == 5) {
            woutT[(size_t)y2 * R + x2] = v;
        } else {
            wdtT[(size_t)y2 * R + x2] = v;
        }
    }
}

// ---------------------------------------------------------------------------
// Split-K narrow GEMM (R9-proven, unchanged)
// ---------------------------------------------------------------------------
__global__ __launch_bounds__(256) void gemm_n96_partial(
    const float* __restrict__ A, const float* __restrict__ B,
    float* __restrict__ P)
{
    const int BK = 32, NN = 96, KC = 256, BM = 64;
    __shared__ float As[BK][BM];
    __shared__ float Bs[BK][NN];

    const int m0 = blockIdx.x * BM;
    const int kc = blockIdx.y;
    const int kbeg = kc * KC;
    const int tid = threadIdx.x;
    const int tx = tid & 15;
    const int ty = tid >> 4;

    float acc[4][6];
#pragma unroll
    for (int r = 0; r < 4; r++)
#pragma unroll
        for (int j = 0; j < 6; j++) acc[r][j] = 0.f;

    for (int k0 = kbeg; k0 < kbeg + KC; k0 += BK) {
#pragma unroll
        for (int i = 0; i < 2; i++) {
            int idx = tid + i * 256;
            int row = idx >> 3;
            int cv  = (idx & 7) * 4;
            float4 a = *(const float4*)(A + (size_t)(m0 + row) * DINNER + k0 + cv);
            As[cv + 0][row] = a.x; As[cv + 1][row] = a.y;
            As[cv + 2][row] = a.z; As[cv + 3][row] = a.w;
        }
#pragma unroll
        for (int i = 0; i < 3; i++) {
            int idx  = tid + i * 256;
            int rowB = idx / 24;
            int cv   = (idx % 24) * 4;
            *(float4*)(&Bs[rowB][cv]) =
                *(const float4*)(B + (size_t)(k0 + rowB) * NN + cv);
        }
        __syncthreads();
#pragma unroll
        for (int k = 0; k < BK; k++) {
            float a[4];
            *(float4*)a = *(const float4*)(&As[k][ty * 4]);
            float b[6];
            *(float2*)(b)     = *(const float2*)(&Bs[k][tx * 6]);
            *(float2*)(b + 2) = *(const float2*)(&Bs[k][tx * 6 + 2]);
            *(float2*)(b + 4) = *(const float2*)(&Bs[k][tx * 6 + 4]);
#pragma unroll
            for (int r = 0; r < 4; r++)
#pragma unroll
                for (int j = 0; j < 6; j++)
                    acc[r][j] = fmaf(a[r], b[j], acc[r][j]);
        }
        __syncthreads();
    }
    float* out = P + (size_t)kc * BLROWS * 96;
#pragma unroll
    for (int r = 0; r < 4; r++) {
        int m = m0 + ty * 4 + r;
#pragma unroll
        for (int j = 0; j < 6; j++)
            out[(size_t)m * 96 + tx * 6 + j] = acc[r][j];
    }
}

__global__ __launch_bounds__(256) void gemm_n96_reduce(
    const float* __restrict__ P, float* __restrict__ C)
{
    size_t i = ((size_t)blockIdx.x * blockDim.x + threadIdx.x) * 4;
    const size_t S = (size_t)BLROWS * 96;
    float4 s = *(const float4*)(P + i);
#pragma unroll
    for (int kc = 1; kc < 8; kc++) {
        float4 v = *(const float4*)(P + kc * S + i);
        s.x += v.x; s.y += v.y; s.z += v.z; s.w += v.w;
    }
    *(float4*)(C + i) = s;
}

// ---------------------------------------------------------------------------
// Chunked parallel scan (R10-proven, unchanged)
// ---------------------------------------------------------------------------
__global__ __launch_bounds__(256) void scan_pass1(
    const float* __restrict__ delta, const float* __restrict__ u,
    const float* __restrict__ dbc, const float* __restrict__ A_log,
    float* __restrict__ P, float* __restrict__ H)
{
    const int tid  = threadIdx.x;
    const int lane = tid & 31;
    const int w    = tid >> 5;
    const int ng   = lane & 3;
    const int dl   = lane >> 2;
    const int d    = blockIdx.x * 64 + w * 8 + dl;
    const int c    = blockIdx.y;
    const int b    = blockIdx.z;

    float4 al = *(const float4*)(A_log + d * DSTATE + ng * 4);
    const float a0 = -__expf(al.x), a1 = -__expf(al.y);
    const float a2 = -__expf(al.z), a3 = -__expf(al.w);

    const size_t trow = (size_t)b * LSEQ + (size_t)c * TC;
    const float* dp  = delta + trow * DINNER + d;
    const float* up  = u     + trow * DINNER + d;
    const float* bcp = dbc   + trow * 96 + DTRANK + ng * 4;

    float h0 = 0.f, h1 = 0.f, h2 = 0.f, h3 = 0.f;
    float p0 = 1.f, p1 = 1.f, p2 = 1.f, p3 = 1.f;
    for (int t = 0; t < TC; t++) {
        float de = dp[(size_t)t * DINNER];
        float uu = up[(size_t)t * DINNER];
        float4 Bv = *(const float4*)(bcp + t * 96);
        float dA0 = __expf(de * a0), dA1 = __expf(de * a1);
        float dA2 = __expf(de * a2), dA3 = __expf(de * a3);
        float du = de * uu;
        p0 *= dA0; p1 *= dA1; p2 *= dA2; p3 *= dA3;
        h0 = fmaf(dA0, h0, du * Bv.x);
        h1 = fmaf(dA1, h1, du * Bv.y);
        h2 = fmaf(dA2, h2, du * Bv.z);
        h3 = fmaf(dA3, h3, du * Bv.w);
    }
    size_t o = (((size_t)b * NCH + c) * DINNER + d) * DSTATE + ng * 4;
    *(float4*)(P + o) = make_float4(p0, p1, p2, p3);
    *(float4*)(H + o) = make_float4(h0, h1, h2, h3);
}

__global__ __launch_bounds__(256) void scan_pass2(
    const float* __restrict__ P, const float* __restrict__ H,
    float* __restrict__ HIN)
{
    int idx = blockIdx.x * blockDim.x + threadIdx.x;
    int n = idx & 15;
    int d = (idx >> 4) & (DINNER - 1);
    int b = idx >> 15;
    float hin = 0.f;
#pragma unroll
    for (int c = 0; c < NCH; c++) {
        size_t o = (((size_t)b * NCH + c) * DINNER + d) * DSTATE + n;
        HIN[o] = hin;
        hin = fmaf(P[o], hin, H[o]);
    }
}

__global__ __launch_bounds__(256) void scan_pass3(
    const float* __restrict__ delta, const float* __restrict__ u,
    const float* __restrict__ dbc, const float* __restrict__ A_log,
    const float* __restrict__ Dp, const float* __restrict__ sres,
    const float* __restrict__ HIN, float* __restrict__ Y)
{
    const int tid  = threadIdx.x;
    const int lane = tid & 31;
    const int w    = tid >> 5;
    const int ng   = lane & 3;
    const int dl   = lane >> 2;
    const int d    = blockIdx.x * 64 + w * 8 + dl;
    const int c    = blockIdx.y;
    const int b    = blockIdx.z;

    float4 al = *(const float4*)(A_log + d * DSTATE + ng * 4);
    const float a0 = -__expf(al.x), a1 = -__expf(al.y);
    const float a2 = -__expf(al.z), a3 = -__expf(al.w);
    const float Dd = Dp[d];

    const size_t trow = (size_t)b * LSEQ + (size_t)c * TC;
    const float* dp  = delta + trow * DINNER + d;
    const float* up  = u     + trow * DINNER + d;
    const float* rp  = sres  + trow * DINNER + d;
    const float* bcp = dbc   + trow * 96 + DTRANK + ng * 4;
    float*       yp  = Y     + trow * DINNER + d;

    size_t o = (((size_t)b * NCH + c) * DINNER + d) * DSTATE + ng * 4;
    float4 hv = *(const float4*)(HIN + o);
    float h0 = hv.x, h1 = hv.y, h2 = hv.z, h3 = hv.w;

    for (int t = 0; t < TC; t++) {
        float de = dp[(size_t)t * DINNER];
        float uu = up[(size_t)t * DINNER];
        float4 Bv = *(const float4*)(bcp + t * 96);
        float4 Cv = *(const float4*)(bcp + t * 96 + DSTATE);
        float dA0 = __expf(de * a0), dA1 = __expf(de * a1);
        float dA2 = __expf(de * a2), dA3 = __expf(de * a3);
        float du = de * uu;
        h0 = fmaf(dA0, h0, du * Bv.x);
        h1 = fmaf(dA1, h1, du * Bv.y);
        h2 = fmaf(dA2, h2, du * Bv.z);
        h3 = fmaf(dA3, h3, du * Bv.w);
        float pp = h0 * Cv.x + h1 * Cv.y + h2 * Cv.z + h3 * Cv.w;
        pp += __shfl_xor_sync(0xffffffffu, pp, 1);
        pp += __shfl_xor_sync(0xffffffffu, pp, 2);
        if (ng == 0)
            yp[(size_t)t * DINNER] = fmaf(uu, Dd, pp) * rp[(size_t)t * DINNER];
    }
}

// ---------------------------------------------------------------------------
// Launch
// ---------------------------------------------------------------------------
extern "C" void kernel_launch(void* const* d_in, const int* in_sizes, int n_in,
                              void* d_out, int out_size)
{
    (void)in_sizes; (void)n_in; (void)out_size;
    const float* x      = (const float*)d_in[0];
    const float* W_in   = (const float*)d_in[1];
    const float* conv_k = (const float*)d_in[2];
    const float* conv_b = (const float*)d_in[3];
    const float* W_x    = (const float*)d_in[4];
    const float* W_dt   = (const float*)d_in[5];
    const float* b_dt   = (const float*)d_in[6];
    const float* A_log  = (const float*)d_in[7];
    const float* Dvec   = (const float*)d_in[8];
    const float* W_out  = (const float*)d_in[9];
    float* out = (float*)d_out;

    h16 *xsh, *xsl, *convTf;
    float *sres, *u, *dbc, *dbcp, *delta, *y, *winT, *woutT, *wdtT;
    float *scP, *scH, *scHi;
    cudaGetSymbolAddress((void**)&xsh,   g_xsh);
    cudaGetSymbolAddress((void**)&xsl,   g_xsl);
    cudaGetSymbolAddress((void**)&sres,  g_sres);
    cudaGetSymbolAddress((void**)&u,     g_u);
    cudaGetSymbolAddress((void**)&dbc,   g_dbc);
    cudaGetSymbolAddress((void**)&dbcp,  g_dbc_part);
    cudaGetSymbolAddress((void**)&delta, g_delta);
    cudaGetSymbolAddress((void**)&y,     g_y);
    cudaGetSymbolAddress((void**)&winT,  g_WinT);
    cudaGetSymbolAddress((void**)&convTf, g_convTf);
    cudaGetSymbolAddress((void**)&woutT, g_WoutT);
    cudaGetSymbolAddress((void**)&wdtT,  g_WdtT);
    cudaGetSymbolAddress((void**)&scP,   g_scanP);
    cudaGetSymbolAddress((void**)&scH,   g_scanH);
    cudaGetSymbolAddress((void**)&scHi,  g_scanHi);

    cudaFuncSetAttribute(conv_halo, cudaFuncAttributeMaxDynamicSharedMemorySize, CONV_SMEM);

    // 0) all weight preprocessing in ONE launch
    fused_transpose<<<dim3(128, 64, 7), dim3(32, 8)>>>(
        W_in, conv_k, W_out, W_dt, winT, convTf, woutT, wdtT);

    // 1) GEMM1 (fp16 2-product now): xs -> fp16 hi/lo, silu(res) -> sres
    mma_gemm<3, 1><<<dim3(32, 32), 256>>>(
        x, DMODEL, winT, DMODEL, sres, DINNER, DMODEL, nullptr, xsh, xsl);

    // 2) halo-fused grouped causal conv (fp16 2-product) + bias + silu -> u
    conv_halo<<<dim3(16, 32), 256, CONV_SMEM>>>(
        xsh, xsl, convTf, conv_b, u);

    // 3) dbc = u @ W_x
    gemm_n96_partial<<<dim3(64, 8), 256>>>(u, W_x, dbcp);
    gemm_n96_reduce<<<(BLROWS * 96 / 4) / 256, 256>>>(dbcp, dbc);

    // 4) delta = clip(softplus(dt_raw @ W_dt + b_dt))  (bf16x3, exact)
    mma_gemm<1, 0><<<dim3(16, 32), 256>>>(
        dbc, 96, wdtT, DTRANK, delta, DINNER, DTRANK, b_dt, nullptr, nullptr);

    // 5) chunked parallel scan (+ fused gate) -> y fp32
    scan_pass1<<<dim3(32, NCH, 2), 256>>>(delta, u, dbc, A_log, scP, scH);
    scan_pass2<<<256, 256>>>(scP, scH, scHi);
    scan_pass3<<<dim3(32, NCH, 2), 256>>>(delta, u, dbc, A_log, Dvec, sres, scHi, y);

    // 6) out = y @ W_out  (fp16 2-product)
    mma_gemm<0, 1><<<dim3(8, 32), 256>>>(
        y, DINNER, woutT, DINNER, out, DMODEL, DINNER, nullptr, nullptr, nullptr);
}

// round 13
// speedup vs baseline: 2.6120x; 1.1555x over previous
#include <cuda_runtime.h>
#include <cuda_bf16.h>
#include <cuda_fp16.h>
#include <cstdint>

// Problem constants
#define BLROWS 4096   // B*L = 2*2048
#define LSEQ   2048
#define DMODEL 1024
#define DINNER 2048
#define DSTATE 16
#define DTRANK 64
#define NCH    16     // scan chunks
#define TC     128    // chunk length

typedef __nv_bfloat16 bf16;
typedef __half h16;

// ---------------------------------------------------------------------------
// Scratch (device globals)
// ---------------------------------------------------------------------------
__device__ h16   g_xsh[(size_t)BLROWS * DINNER];     // xs fp16 (from GEMM1)
__device__ float g_sres[(size_t)BLROWS * DINNER];
__device__ float g_u  [(size_t)BLROWS * DINNER];
__device__ float g_dbc[(size_t)BLROWS * 96];
__device__ float g_dbc_part[(size_t)8 * BLROWS * 96];
__device__ float g_delta[(size_t)BLROWS * DINNER];
__device__ float g_y [(size_t)BLROWS * DINNER];
// scan chunk scratch: [b][c][d][n]
__device__ float g_scanP [(size_t)2 * NCH * DINNER * DSTATE];
__device__ float g_scanH [(size_t)2 * NCH * DINNER * DSTATE];
__device__ float g_scanHi[(size_t)2 * NCH * DINNER * DSTATE];
// Transposed weights
__device__ float g_WinT [(size_t)4096 * 1024];                 // fp32
__device__ h16   g_convTf[(size_t)4 * 2048 * 1024];            // fp16 single
__device__ float g_WoutT[(size_t)1024 * 2048];                 // fp32
__device__ float g_WdtT [(size_t)2048 * 64];                   // fp32

// ---------------------------------------------------------------------------
// PTX helpers
// ---------------------------------------------------------------------------
__device__ __forceinline__ uint32_t smem_u32(const void* p) {
    uint32_t a;
    asm("{ .reg .u64 t; cvta.to.shared.u64 t, %1; cvt.u32.u64 %0, t; }"
        : "=r"(a) : "l"(p));
    return a;
}
__device__ __forceinline__ void ldsm4(uint32_t* r, uint32_t addr) {
    asm volatile("ldmatrix.sync.aligned.m8n8.x4.shared.b16 {%0,%1,%2,%3}, [%4];"
        : "=r"(r[0]), "=r"(r[1]), "=r"(r[2]), "=r"(r[3]) : "r"(addr));
}
__device__ __forceinline__ void mma16816(
    float& d0, float& d1, float& d2, float& d3,
    uint32_t a0, uint32_t a1, uint32_t a2, uint32_t a3,
    uint32_t b0, uint32_t b1)
{
    asm volatile(
        "mma.sync.aligned.m16n8k16.row.col.f32.bf16.bf16.f32 "
        "{%0,%1,%2,%3}, {%4,%5,%6,%7}, {%8,%9}, {%0,%1,%2,%3};"
        : "+f"(d0), "+f"(d1), "+f"(d2), "+f"(d3)
        : "r"(a0), "r"(a1), "r"(a2), "r"(a3), "r"(b0), "r"(b1));
}
__device__ __forceinline__ void mma16816h(
    float& d0, float& d1, float& d2, float& d3,
    uint32_t a0, uint32_t a1, uint32_t a2, uint32_t a3,
    uint32_t b0, uint32_t b1)
{
    asm volatile(
        "mma.sync.aligned.m16n8k16.row.col.f32.f16.f16.f32 "
        "{%0,%1,%2,%3}, {%4,%5,%6,%7}, {%8,%9}, {%0,%1,%2,%3};"
        : "+f"(d0), "+f"(d1), "+f"(d2), "+f"(d3)
        : "r"(a0), "r"(a1), "r"(a2), "r"(a3), "r"(b0), "r"(b1));
}
// bf16 2-way split of two floats -> packed bf16x2 (hi, lo)
__device__ __forceinline__ void split2(float x, float y, uint32_t& hi, uint32_t& lo) {
    bf16 hx = __float2bfloat16_rn(x);
    bf16 hy = __float2bfloat16_rn(y);
    __nv_bfloat162 h; h.x = hx; h.y = hy;
    __nv_bfloat162 l = __floats2bfloat162_rn(x - __bfloat162float(hx),
                                             y - __bfloat162float(hy));
    hi = *reinterpret_cast<uint32_t*>(&h);
    lo = *reinterpret_cast<uint32_t*>(&l);
}
// fp16 2-way split (A exact to ~2^-22)
__device__ __forceinline__ void split2h(float x, float y, uint32_t& hi, uint32_t& lo) {
    h16 hx = __float2half_rn(x);
    h16 hy = __float2half_rn(y);
    __half2 h = __halves2half2(hx, hy);
    __half2 l = __floats2half2_rn(x - __half2float(hx), y - __half2float(hy));
    hi = *reinterpret_cast<uint32_t*>(&h);
    lo = *reinterpret_cast<uint32_t*>(&l);
}
// SMEM tile row = 64B (32 elems) in 4x16B chunks, xor-swizzled
__device__ __forceinline__ uint32_t swz(int row, int chunk) {
    return (uint32_t)((row << 6) + (((chunk ^ ((row >> 1) & 3)) & 3) << 4));
}
__device__ __forceinline__ float silu(float v) { return v / (1.f + __expf(-v)); }

// ---------------------------------------------------------------------------
// mma GEMM.  PREC=0: bf16x3.  PREC=1: fp16 A-split x2, fp16-single B.
// EPI: 0 fp32 store; 1 softplus+clip(+bias); 3 GEMM1 dual out (xs fp16).
// ---------------------------------------------------------------------------
template <int EPI, int PREC>
__global__ __launch_bounds__(256) void mma_gemm(
    const float* __restrict__ A, int lda,
    const float* __restrict__ Bt, int ldb,
    float* __restrict__ C, int ldc,
    int K, const float* __restrict__ bias,
    h16* __restrict__ xsh)
{
    __shared__ __align__(16) char sAhi[8192], sAlo[8192], sBhi[8192], sBlo[8192];

    const int tid  = threadIdx.x;
    const int lane = tid & 31;
    const int wid  = tid >> 5;
    const int wm   = wid & 1;
    const int wn   = wid >> 1;
    const int m0   = blockIdx.y * 128;
    const int n0   = blockIdx.x * 128;
    const int TOT  = K >> 5;

    const uint32_t aHiB = smem_u32(sAhi), aLoB = smem_u32(sAlo);
    const uint32_t bHiB = smem_u32(sBhi), bLoB = smem_u32(sBlo);

    const int a_r  = lane & 15;
    const int a_cx = lane >> 4;
    const int b_r  = (lane & 7) + ((lane >> 4) << 3);
    const int b_cx = (lane >> 3) & 1;

    float acc[4][4][4];
#pragma unroll
    for (int i = 0; i < 4; i++)
#pragma unroll
        for (int j = 0; j < 4; j++)
#pragma unroll
            for (int k = 0; k < 4; k++) acc[i][j][k] = 0.f;

    float4 pa[4], pb[4];

    auto load = [&](int kb) {
#pragma unroll
        for (int i = 0; i < 4; i++) {
            int idx = tid + i * 256;
            int row = idx >> 3, seg = idx & 7;
            pa[i] = *(const float4*)(A + (size_t)(m0 + row) * lda + kb * 32 + seg * 4);
            pb[i] = *(const float4*)(Bt + (size_t)(n0 + row) * ldb + kb * 32 + seg * 4);
        }
    };

    auto store = [&]() {
#pragma unroll
        for (int i = 0; i < 4; i++) {
            int idx = tid + i * 256;
            int row = idx >> 3, seg = idx & 7;
            uint32_t off = swz(row, seg >> 1) + (seg & 1) * 8;
            uint2 h, l;
            if (PREC == 0) {
                split2(pa[i].x, pa[i].y, h.x, l.x);
                split2(pa[i].z, pa[i].w, h.y, l.y);
                *(uint2*)(sAhi + off) = h;
                *(uint2*)(sAlo + off) = l;
                split2(pb[i].x, pb[i].y, h.x, l.x);
                split2(pb[i].z, pb[i].w, h.y, l.y);
                *(uint2*)(sBhi + off) = h;
                *(uint2*)(sBlo + off) = l;
            } else {
                split2h(pa[i].x, pa[i].y, h.x, l.x);
                split2h(pa[i].z, pa[i].w, h.y, l.y);
                *(uint2*)(sAhi + off) = h;
                *(uint2*)(sAlo + off) = l;
                __half2 b0 = __floats2half2_rn(pb[i].x, pb[i].y);
                __half2 b1 = __floats2half2_rn(pb[i].z, pb[i].w);
                h.x = *reinterpret_cast<uint32_t*>(&b0);
                h.y = *reinterpret_cast<uint32_t*>(&b1);
                *(uint2*)(sBhi + off) = h;
            }
        }
    };

    auto mma_block = [&]() {
#pragma unroll
        for (int ks = 0; ks < 2; ks++) {
            uint32_t a[4][4], bh[4][2];
#pragma unroll
            for (int mf = 0; mf < 4; mf++) {
                int row = wm * 64 + mf * 16 + a_r;
                ldsm4(a[mf], aHiB + swz(row, ks * 2 + a_cx));
            }
#pragma unroll
            for (int p = 0; p < 2; p++) {
                int row = wn * 32 + p * 16 + b_r;
                uint32_t t[4];
                ldsm4(t, bHiB + swz(row, ks * 2 + b_cx));
                bh[p * 2][0] = t[0]; bh[p * 2][1] = t[1];
                bh[p * 2 + 1][0] = t[2]; bh[p * 2 + 1][1] = t[3];
            }
#pragma unroll
            for (int mf = 0; mf < 4; mf++)
#pragma unroll
                for (int nf = 0; nf < 4; nf++) {
                    if (PREC == 0)
                        mma16816(acc[mf][nf][0], acc[mf][nf][1], acc[mf][nf][2], acc[mf][nf][3],
                                 a[mf][0], a[mf][1], a[mf][2], a[mf][3], bh[nf][0], bh[nf][1]);
                    else
                        mma16816h(acc[mf][nf][0], acc[mf][nf][1], acc[mf][nf][2], acc[mf][nf][3],
                                  a[mf][0], a[mf][1], a[mf][2], a[mf][3], bh[nf][0], bh[nf][1]);
                }
            if (PREC == 0) {
                uint32_t bx[4][2];
#pragma unroll
                for (int p = 0; p < 2; p++) {
                    int row = wn * 32 + p * 16 + b_r;
                    uint32_t t[4];
                    ldsm4(t, bLoB + swz(row, ks * 2 + b_cx));
                    bx[p * 2][0] = t[0]; bx[p * 2][1] = t[1];
                    bx[p * 2 + 1][0] = t[2]; bx[p * 2 + 1][1] = t[3];
                }
#pragma unroll
                for (int mf = 0; mf < 4; mf++)
#pragma unroll
                    for (int nf = 0; nf < 4; nf++)
                        mma16816(acc[mf][nf][0], acc[mf][nf][1], acc[mf][nf][2], acc[mf][nf][3],
                                 a[mf][0], a[mf][1], a[mf][2], a[mf][3], bx[nf][0], bx[nf][1]);
            }
#pragma unroll
            for (int mf = 0; mf < 4; mf++) {
                int row = wm * 64 + mf * 16 + a_r;
                ldsm4(a[mf], aLoB + swz(row, ks * 2 + a_cx));
            }
#pragma unroll
            for (int mf = 0; mf < 4; mf++)
#pragma unroll
                for (int nf = 0; nf < 4; nf++) {
                    if (PREC == 0)
                        mma16816(acc[mf][nf][0], acc[mf][nf][1], acc[mf][nf][2], acc[mf][nf][3],
                                 a[mf][0], a[mf][1], a[mf][2], a[mf][3], bh[nf][0], bh[nf][1]);
                    else
                        mma16816h(acc[mf][nf][0], acc[mf][nf][1], acc[mf][nf][2], acc[mf][nf][3],
                                  a[mf][0], a[mf][1], a[mf][2], a[mf][3], bh[nf][0], bh[nf][1]);
                }
        }
    };

    load(0);
    store();
    __syncthreads();
    for (int it = 1; it < TOT; it++) {
        load(it);
        mma_block();
        __syncthreads();
        store();
        __syncthreads();
    }
    mma_block();

    // Epilogue
#pragma unroll
    for (int mf = 0; mf < 4; mf++) {
        int r = m0 + wm * 64 + mf * 16 + (lane >> 2);
#pragma unroll
        for (int nf = 0; nf < 4; nf++) {
            int c = n0 + wn * 32 + nf * 8 + (lane & 3) * 2;
            float v0 = acc[mf][nf][0], v1 = acc[mf][nf][1];
            float v2 = acc[mf][nf][2], v3 = acc[mf][nf][3];
            if (EPI == 1) {
                float b0 = bias[c], b1 = bias[c + 1];
                float x0 = v0 + b0, x1 = v1 + b1, x2 = v2 + b0, x3 = v3 + b1;
                v0 = fminf(fmaxf(fmaxf(x0, 0.f) + log1pf(__expf(-fabsf(x0))), 1e-3f), 0.1f);
                v1 = fminf(fmaxf(fmaxf(x1, 0.f) + log1pf(__expf(-fabsf(x1))), 1e-3f), 0.1f);
                v2 = fminf(fmaxf(fmaxf(x2, 0.f) + log1pf(__expf(-fabsf(x2))), 1e-3f), 0.1f);
                v3 = fminf(fmaxf(fmaxf(x3, 0.f) + log1pf(__expf(-fabsf(x3))), 1e-3f), 0.1f);
            }
            if (EPI == 3) {
                if (n0 < 2048) {     // xs half -> fp16 for conv
                    __half2 p0 = __floats2half2_rn(v0, v1);
                    __half2 p1 = __floats2half2_rn(v2, v3);
                    *(uint32_t*)(xsh + (size_t)r * 2048 + c)       = *reinterpret_cast<uint32_t*>(&p0);
                    *(uint32_t*)(xsh + (size_t)(r + 8) * 2048 + c) = *reinterpret_cast<uint32_t*>(&p1);
                } else {             // res half -> silu -> sres fp32
                    int cc = c - 2048;
                    *(float2*)(C + (size_t)r * ldc + cc)
                        = make_float2(silu(v0), silu(v1));
                    *(float2*)(C + (size_t)(r + 8) * ldc + cc)
                        = make_float2(silu(v2), silu(v3));
                }
            } else {
                *(float2*)(C + (size_t)r * ldc + c)       = make_float2(v0, v1);
                *(float2*)(C + (size_t)(r + 8) * ldc + c) = make_float2(v2, v3);
            }
        }
    }
}

// ---------------------------------------------------------------------------
// Halo-fused grouped causal conv, fp16 SINGLE-product:
// A = xs fp16 (131-row halo), B = conv weights fp16, 4 taps.
// ---------------------------------------------------------------------------
#define CONV_STG  41472                      // 8704 (A) + 4*8192 (B)
#define CONV_SMEM (2 * CONV_STG + 1024)

__global__ __launch_bounds__(256) void conv_halo(
    const h16* __restrict__ Ah,            // xs fp16 [4096,2048]
    const h16* __restrict__ Bf,            // convT fp16 [4][2048,1024]
    const float* __restrict__ bias, float* __restrict__ U)
{
    extern __shared__ char dyn[];
    const uint32_t rawb = smem_u32(dyn);
    const uint32_t base = (rawb + 1023u) & ~1023u;
    char* tp = dyn + (base - rawb);

    const int tid  = threadIdx.x;
    const int lane = tid & 31;
    const int wid  = tid >> 5;
    const int wm   = wid & 1;
    const int wn   = wid >> 1;
    const int m0   = blockIdx.y * 128;
    const int n0   = blockIdx.x * 128;
    const int colbase = (n0 >= 1024) ? 1024 : 0;
    const bool headok = (m0 & (LSEQ - 1)) != 0;

    const int a_r  = lane & 15;
    const int a_cx = lane >> 4;
    const int b_r  = (lane & 7) + ((lane >> 4) << 3);
    const int b_cx = (lane >> 3) & 1;

    float acc[4][4][4];
#pragma unroll
    for (int i = 0; i < 4; i++)
#pragma unroll
        for (int j = 0; j < 4; j++)
#pragma unroll
            for (int k = 0; k < 4; k++) acc[i][j][k] = 0.f;

    uint4 sa[3], rb1[4], rb2[4];

    auto loadA = [&](int kb) {
#pragma unroll
        for (int i = 0; i < 3; i++) {
            int c = tid + i * 256;
            if (i < 2 || c < 524) {
                int row = c >> 2, seg = c & 3;
                bool valid = headok || (row >= 3);
                long grow = (long)m0 - 3 + row;
                sa[i] = valid
                    ? *(const uint4*)(Ah + grow * 2048 + colbase + kb * 32 + seg * 8)
                    : make_uint4(0, 0, 0, 0);
            }
        }
    };
    auto stsA = [&](int s) {
        char* sb = tp + s * CONV_STG;
#pragma unroll
        for (int i = 0; i < 3; i++) {
            int c = tid + i * 256;
            if (i < 2 || c < 524) {
                int row = c >> 2, seg = c & 3;
                *(uint4*)(sb + swz(row, seg)) = sa[i];
            }
        }
    };
    auto loadB = [&](int kb, int half, uint4* rb) {
#pragma unroll
        for (int i = 0; i < 4; i++) {
            int c = tid + i * 256;
            int tap = half * 2 + (c >> 9);
            int cc = c & 511;
            int row = cc >> 2, seg = cc & 3;
            rb[i] = *(const uint4*)(Bf + (size_t)tap * 2048 * 1024
                                       + (size_t)(n0 + row) * 1024 + kb * 32 + seg * 8);
        }
    };
    auto stsB = [&](int s, int half, uint4* rb) {
#pragma unroll
        for (int i = 0; i < 4; i++) {
            int c = tid + i * 256;
            int tap = half * 2 + (c >> 9);
            int cc = c & 511;
            int row = cc >> 2, seg = cc & 3;
            char* bb = tp + s * CONV_STG + 8704 + tap * 8192;
            *(uint4*)(bb + swz(row, seg)) = rb[i];
        }
    };
    auto mma_tap = [&](int s, int tap) {
        uint32_t aB = base + (uint32_t)s * CONV_STG;
        uint32_t bB = aB + 8704 + (uint32_t)tap * 8192;
#pragma unroll
        for (int ks = 0; ks < 2; ks++) {
            uint32_t a[4][4], bh[4][2];
#pragma unroll
            for (int mf = 0; mf < 4; mf++) {
                int row = wm * 64 + mf * 16 + a_r + tap;
                ldsm4(a[mf], aB + swz(row, ks * 2 + a_cx));
            }
#pragma unroll
            for (int p = 0; p < 2; p++) {
                int row = wn * 32 + p * 16 + b_r;
                uint32_t t[4];
                ldsm4(t, bB + swz(row, ks * 2 + b_cx));
                bh[p * 2][0] = t[0]; bh[p * 2][1] = t[1];
                bh[p * 2 + 1][0] = t[2]; bh[p * 2 + 1][1] = t[3];
            }
#pragma unroll
            for (int mf = 0; mf < 4; mf++)
#pragma unroll
                for (int nf = 0; nf < 4; nf++)
                    mma16816h(acc[mf][nf][0], acc[mf][nf][1], acc[mf][nf][2], acc[mf][nf][3],
                              a[mf][0], a[mf][1], a[mf][2], a[mf][3], bh[nf][0], bh[nf][1]);
        }
    };

    loadA(0); loadB(0, 0, rb1); loadB(0, 1, rb2);
    stsA(0); stsB(0, 0, rb1); stsB(0, 1, rb2);
    __syncthreads();

    for (int kb = 0; kb < 32; kb++) {
        int cur = kb & 1, nxt = cur ^ 1;
        bool more = (kb + 1) < 32;
        if (more) { loadA(kb + 1); loadB(kb + 1, 0, rb1); }
        mma_tap(cur, 0);
        mma_tap(cur, 1);
        if (more) { stsA(nxt); stsB(nxt, 0, rb1); loadB(kb + 1, 1, rb2); }
        mma_tap(cur, 2);
        mma_tap(cur, 3);
        if (more) stsB(nxt, 1, rb2);
        __syncthreads();
    }

#pragma unroll
    for (int mf = 0; mf < 4; mf++) {
        int r = m0 + wm * 64 + mf * 16 + (lane >> 2);
#pragma unroll
        for (int nf = 0; nf < 4; nf++) {
            int c = n0 + wn * 32 + nf * 8 + (lane & 3) * 2;
            float b0 = bias[c], b1 = bias[c + 1];
            float v0 = silu(acc[mf][nf][0] + b0);
            float v1 = silu(acc[mf][nf][1] + b1);
            float v2 = silu(acc[mf][nf][2] + b0);
            float v3 = silu(acc[mf][nf][3] + b1);
            *(float2*)(U + (size_t)r * DINNER + c)       = make_float2(v0, v1);
            *(float2*)(U + (size_t)(r + 8) * DINNER + c) = make_float2(v2, v3);
        }
    }
}

// ---------------------------------------------------------------------------
// Fused weight preprocessing (one launch)
// ---------------------------------------------------------------------------
__global__ __launch_bounds__(256) void fused_transpose(
    const float* __restrict__ Win, const float* __restrict__ convk,
    const float* __restrict__ Wout, const float* __restrict__ Wdt,
    float* __restrict__ winT, h16* __restrict__ cTf,
    float* __restrict__ woutT, float* __restrict__ wdtT)
{
    int z = blockIdx.z;
    const float* src; int R, C;
    if (z == 0)      { src = Win;  R = 1024; C = 4096; }
    else if (z <= 4) { src = convk + (size_t)(z - 1) * 1024 * 2048; R = 1024; C = 2048; }
    else if (z == 5) { src = Wout; R = 2048; C = 1024; }
    else             { src = Wdt;  R = 64;   C = 2048; }
    if (blockIdx.x * 32 >= C || blockIdx.y * 32 >= R) return;

    __shared__ float t[32][33];
    int x = blockIdx.x * 32 + threadIdx.x;
#pragma unroll
    for (int j = 0; j < 4; j++) {
        int y = blockIdx.y * 32 + threadIdx.y + j * 8;
        t[threadIdx.y + j * 8][threadIdx.x] = src[(size_t)y * C + x];
    }
    __syncthreads();
    int x2 = blockIdx.y * 32 + threadIdx.x;
#pragma unroll
    for (int j = 0; j < 4; j++) {
        int y2 = blockIdx.x * 32 + threadIdx.y + j * 8;
        float v = t[threadIdx.x][threadIdx.y + j * 8];
        if (z == 0) {
            winT[(size_t)y2 * R + x2] = v;
        } else if (z <= 4) {
            cTf[(size_t)(z - 1) * 2048 * 1024 + (size_t)y2 * R + x2] = __float2half_rn(v);
        } else if (z == 5) {
            woutT[(size_t)y2 * R + x2] = v;
        } else {
            wdtT[(size_t)y2 * R + x2] = v;
        }
    }
}

// ---------------------------------------------------------------------------
// Split-K narrow GEMM (R9-proven, unchanged)
// ---------------------------------------------------------------------------
__global__ __launch_bounds__(256) void gemm_n96_partial(
    const float* __restrict__ A, const float* __restrict__ B,
    float* __restrict__ P)
{
    const int BK = 32, NN = 96, KC = 256, BM = 64;
    __shared__ float As[BK][BM];
    __shared__ float Bs[BK][NN];

    const int m0 = blockIdx.x * BM;
    const int kc = blockIdx.y;
    const int kbeg = kc * KC;
    const int tid = threadIdx.x;
    const int tx = tid & 15;
    const int ty = tid >> 4;

    float acc[4][6];
#pragma unroll
    for (int r = 0; r < 4; r++)
#pragma unroll
        for (int j = 0; j < 6; j++) acc[r][j] = 0.f;

    for (int k0 = kbeg; k0 < kbeg + KC; k0 += BK) {
#pragma unroll
        for (int i = 0; i < 2; i++) {
            int idx = tid + i * 256;
            int row = idx >> 3;
            int cv  = (idx & 7) * 4;
            float4 a = *(const float4*)(A + (size_t)(m0 + row) * DINNER + k0 + cv);
            As[cv + 0][row] = a.x; As[cv + 1][row] = a.y;
            As[cv + 2][row] = a.z; As[cv + 3][row] = a.w;
        }
#pragma unroll
        for (int i = 0; i < 3; i++) {
            int idx  = tid + i * 256;
            int rowB = idx / 24;
            int cv   = (idx % 24) * 4;
            *(float4*)(&Bs[rowB][cv]) =
                *(const float4*)(B + (size_t)(k0 + rowB) * NN + cv);
        }
        __syncthreads();
#pragma unroll
        for (int k = 0; k < BK; k++) {
            float a[4];
            *(float4*)a = *(const float4*)(&As[k][ty * 4]);
            float b[6];
            *(float2*)(b)     = *(const float2*)(&Bs[k][tx * 6]);
            *(float2*)(b + 2) = *(const float2*)(&Bs[k][tx * 6 + 2]);
            *(float2*)(b + 4) = *(const float2*)(&Bs[k][tx * 6 + 4]);
#pragma unroll
            for (int r = 0; r < 4; r++)
#pragma unroll
                for (int j = 0; j < 6; j++)
                    acc[r][j] = fmaf(a[r], b[j], acc[r][j]);
        }
        __syncthreads();
    }
    float* out = P + (size_t)kc * BLROWS * 96;
#pragma unroll
    for (int r = 0; r < 4; r++) {
        int m = m0 + ty * 4 + r;
#pragma unroll
        for (int j = 0; j < 6; j++)
            out[(size_t)m * 96 + tx * 6 + j] = acc[r][j];
    }
}

__global__ __launch_bounds__(256) void gemm_n96_reduce(
    const float* __restrict__ P, float* __restrict__ C)
{
    size_t i = ((size_t)blockIdx.x * blockDim.x + threadIdx.x) * 4;
    const size_t S = (size_t)BLROWS * 96;
    float4 s = *(const float4*)(P + i);
#pragma unroll
    for (int kc = 1; kc < 8; kc++) {
        float4 v = *(const float4*)(P + kc * S + i);
        s.x += v.x; s.y += v.y; s.z += v.z; s.w += v.w;
    }
    *(float4*)(C + i) = s;
}

// ---------------------------------------------------------------------------
// Chunked parallel scan (R10-proven, unchanged)
// ---------------------------------------------------------------------------
__global__ __launch_bounds__(256) void scan_pass1(
    const float* __restrict__ delta, const float* __restrict__ u,
    const float* __restrict__ dbc, const float* __restrict__ A_log,
    float* __restrict__ P, float* __restrict__ H)
{
    const int tid  = threadIdx.x;
    const int lane = tid & 31;
    const int w    = tid >> 5;
    const int ng   = lane & 3;
    const int dl   = lane >> 2;
    const int d    = blockIdx.x * 64 + w * 8 + dl;
    const int c    = blockIdx.y;
    const int b    = blockIdx.z;

    float4 al = *(const float4*)(A_log + d * DSTATE + ng * 4);
    const float a0 = -__expf(al.x), a1 = -__expf(al.y);
    const float a2 = -__expf(al.z), a3 = -__expf(al.w);

    const size_t trow = (size_t)b * LSEQ + (size_t)c * TC;
    const float* dp  = delta + trow * DINNER + d;
    const float* up  = u     + trow * DINNER + d;
    const float* bcp = dbc   + trow * 96 + DTRANK + ng * 4;

    float h0 = 0.f, h1 = 0.f, h2 = 0.f, h3 = 0.f;
    float p0 = 1.f, p1 = 1.f, p2 = 1.f, p3 = 1.f;
    for (int t = 0; t < TC; t++) {
        float de = dp[(size_t)t * DINNER];
        float uu = up[(size_t)t * DINNER];
        float4 Bv = *(const float4*)(bcp + t * 96);
        float dA0 = __expf(de * a0), dA1 = __expf(de * a1);
        float dA2 = __expf(de * a2), dA3 = __expf(de * a3);
        float du = de * uu;
        p0 *= dA0; p1 *= dA1; p2 *= dA2; p3 *= dA3;
        h0 = fmaf(dA0, h0, du * Bv.x);
        h1 = fmaf(dA1, h1, du * Bv.y);
        h2 = fmaf(dA2, h2, du * Bv.z);
        h3 = fmaf(dA3, h3, du * Bv.w);
    }
    size_t o = (((size_t)b * NCH + c) * DINNER + d) * DSTATE + ng * 4;
    *(float4*)(P + o) = make_float4(p0, p1, p2, p3);
    *(float4*)(H + o) = make_float4(h0, h1, h2, h3);
}

__global__ __launch_bounds__(256) void scan_pass2(
    const float* __restrict__ P, const float* __restrict__ H,
    float* __restrict__ HIN)
{
    int idx = blockIdx.x * blockDim.x + threadIdx.x;
    int n = idx & 15;
    int d = (idx >> 4) & (DINNER - 1);
    int b = idx >> 15;
    float hin = 0.f;
#pragma unroll
    for (int c = 0; c < NCH; c++) {
        size_t o = (((size_t)b * NCH + c) * DINNER + d) * DSTATE + n;
        HIN[o] = hin;
        hin = fmaf(P[o], hin, H[o]);
    }
}

__global__ __launch_bounds__(256) void scan_pass3(
    const float* __restrict__ delta, const float* __restrict__ u,
    const float* __restrict__ dbc, const float* __restrict__ A_log,
    const float* __restrict__ Dp, const float* __restrict__ sres,
    const float* __restrict__ HIN, float* __restrict__ Y)
{
    const int tid  = threadIdx.x;
    const int lane = tid & 31;
    const int w    = tid >> 5;
    const int ng   = lane & 3;
    const int dl   = lane >> 2;
    const int d    = blockIdx.x * 64 + w * 8 + dl;
    const int c    = blockIdx.y;
    const int b    = blockIdx.z;

    float4 al = *(const float4*)(A_log + d * DSTATE + ng * 4);
    const float a0 = -__expf(al.x), a1 = -__expf(al.y);
    const float a2 = -__expf(al.z), a3 = -__expf(al.w);
    const float Dd = Dp[d];

    const size_t trow = (size_t)b * LSEQ + (size_t)c * TC;
    const float* dp  = delta + trow * DINNER + d;
    const float* up  = u     + trow * DINNER + d;
    const float* rp  = sres  + trow * DINNER + d;
    const float* bcp = dbc   + trow * 96 + DTRANK + ng * 4;
    float*       yp  = Y     + trow * DINNER + d;

    size_t o = (((size_t)b * NCH + c) * DINNER + d) * DSTATE + ng * 4;
    float4 hv = *(const float4*)(HIN + o);
    float h0 = hv.x, h1 = hv.y, h2 = hv.z, h3 = hv.w;

    for (int t = 0; t < TC; t++) {
        float de = dp[(size_t)t * DINNER];
        float uu = up[(size_t)t * DINNER];
        float4 Bv = *(const float4*)(bcp + t * 96);
        float4 Cv = *(const float4*)(bcp + t * 96 + DSTATE);
        float dA0 = __expf(de * a0), dA1 = __expf(de * a1);
        float dA2 = __expf(de * a2), dA3 = __expf(de * a3);
        float du = de * uu;
        h0 = fmaf(dA0, h0, du * Bv.x);
        h1 = fmaf(dA1, h1, du * Bv.y);
        h2 = fmaf(dA2, h2, du * Bv.z);
        h3 = fmaf(dA3, h3, du * Bv.w);
        float pp = h0 * Cv.x + h1 * Cv.y + h2 * Cv.z + h3 * Cv.w;
        pp += __shfl_xor_sync(0xffffffffu, pp, 1);
        pp += __shfl_xor_sync(0xffffffffu, pp, 2);
        if (ng == 0)
            yp[(size_t)t * DINNER] = fmaf(uu, Dd, pp) * rp[(size_t)t * DINNER];
    }
}

// ---------------------------------------------------------------------------
// Launch
// ---------------------------------------------------------------------------
extern "C" void kernel_launch(void* const* d_in, const int* in_sizes, int n_in,
                              void* d_out, int out_size)
{
    (void)in_sizes; (void)n_in; (void)out_size;
    const float* x      = (const float*)d_in[0];
    const float* W_in   = (const float*)d_in[1];
    const float* conv_k = (const float*)d_in[2];
    const float* conv_b = (const float*)d_in[3];
    const float* W_x    = (const float*)d_in[4];
    const float* W_dt   = (const float*)d_in[5];
    const float* b_dt   = (const float*)d_in[6];
    const float* A_log  = (const float*)d_in[7];
    const float* Dvec   = (const float*)d_in[8];
    const float* W_out  = (const float*)d_in[9];
    float* out = (float*)d_out;

    h16 *xsh, *convTf;
    float *sres, *u, *dbc, *dbcp, *delta, *y, *winT, *woutT, *wdtT;
    float *scP, *scH, *scHi;
    cudaGetSymbolAddress((void**)&xsh,   g_xsh);
    cudaGetSymbolAddress((void**)&sres,  g_sres);
    cudaGetSymbolAddress((void**)&u,     g_u);
    cudaGetSymbolAddress((void**)&dbc,   g_dbc);
    cudaGetSymbolAddress((void**)&dbcp,  g_dbc_part);
    cudaGetSymbolAddress((void**)&delta, g_delta);
    cudaGetSymbolAddress((void**)&y,     g_y);
    cudaGetSymbolAddress((void**)&winT,  g_WinT);
    cudaGetSymbolAddress((void**)&convTf, g_convTf);
    cudaGetSymbolAddress((void**)&woutT, g_WoutT);
    cudaGetSymbolAddress((void**)&wdtT,  g_WdtT);
    cudaGetSymbolAddress((void**)&scP,   g_scanP);
    cudaGetSymbolAddress((void**)&scH,   g_scanH);
    cudaGetSymbolAddress((void**)&scHi,  g_scanHi);

    cudaFuncSetAttribute(conv_halo, cudaFuncAttributeMaxDynamicSharedMemorySize, CONV_SMEM);

    // 0) all weight preprocessing in ONE launch
    fused_transpose<<<dim3(128, 64, 7), dim3(32, 8)>>>(
        W_in, conv_k, W_out, W_dt, winT, convTf, woutT, wdtT);

    // 1) GEMM1 (fp16 2-product): xs -> fp16, silu(res) -> sres
    mma_gemm<3, 1><<<dim3(32, 32), 256>>>(
        x, DMODEL, winT, DMODEL, sres, DINNER, DMODEL, nullptr, xsh);

    // 2) halo-fused grouped causal conv (fp16 single-product) + bias + silu
    conv_halo<<<dim3(16, 32), 256, CONV_SMEM>>>(
        xsh, convTf, conv_b, u);

    // 3) dbc = u @ W_x
    gemm_n96_partial<<<dim3(64, 8), 256>>>(u, W_x, dbcp);
    gemm_n96_reduce<<<(BLROWS * 96 / 4) / 256, 256>>>(dbcp, dbc);

    // 4) delta = clip(softplus(dt_raw @ W_dt + b_dt))  (bf16x3, exact)
    mma_gemm<1, 0><<<dim3(16, 32), 256>>>(
        dbc, 96, wdtT, DTRANK, delta, DINNER, DTRANK, b_dt, nullptr);

    // 5) chunked parallel scan (+ fused gate) -> y fp32
    scan_pass1<<<dim3(32, NCH, 2), 256>>>(delta, u, dbc, A_log, scP, scH);
    scan_pass2<<<256, 256>>>(scP, scH, scHi);
    scan_pass3<<<dim3(32, NCH, 2), 256>>>(delta, u, dbc, A_log, Dvec, sres, scHi, y);

    // 6) out = y @ W_out  (fp16 2-product)
    mma_gemm<0, 1><<<dim3(8, 32), 256>>>(
        y, DINNER, woutT, DINNER, out, DMODEL, DINNER, nullptr, nullptr);
}

// round 14
// speedup vs baseline: 2.8339x; 1.0849x over previous
#include <cuda_runtime.h>
#include <cuda_bf16.h>
#include <cuda_fp16.h>
#include <cstdint>

// Problem constants
#define BLROWS 4096   // B*L = 2*2048
#define LSEQ   2048
#define DMODEL 1024
#define DINNER 2048
#define DSTATE 16
#define DTRANK 64
#define NCH    16     // scan chunks
#define TC     128    // chunk length

typedef __nv_bfloat16 bf16;
typedef __half h16;

// ---------------------------------------------------------------------------
// Scratch (device globals)
// ---------------------------------------------------------------------------
__device__ h16   g_xsh[(size_t)BLROWS * DINNER];     // xs fp16 (from GEMM1)
__device__ float g_sres[(size_t)BLROWS * DINNER];
__device__ float g_u  [(size_t)BLROWS * DINNER];
__device__ float g_dbc[(size_t)BLROWS * 96];
__device__ float g_dbc_part[(size_t)8 * BLROWS * 96];
__device__ float g_delta[(size_t)BLROWS * DINNER];
__device__ float g_y [(size_t)BLROWS * DINNER];
// scan chunk scratch: [b][c][d][n]
__device__ float g_scanP [(size_t)2 * NCH * DINNER * DSTATE];
__device__ float g_scanH [(size_t)2 * NCH * DINNER * DSTATE];
__device__ float g_scanHi[(size_t)2 * NCH * DINNER * DSTATE];
// Transposed weights
__device__ float g_WinT [(size_t)4096 * 1024];                 // fp32
__device__ h16   g_convTf[(size_t)4 * 2048 * 1024];            // fp16 single
__device__ float g_WoutT[(size_t)1024 * 2048];                 // fp32
__device__ float g_WdtT [(size_t)2048 * 64];                   // fp32

// ---------------------------------------------------------------------------
// PTX helpers
// ---------------------------------------------------------------------------
__device__ __forceinline__ uint32_t smem_u32(const void* p) {
    uint32_t a;
    asm("{ .reg .u64 t; cvta.to.shared.u64 t, %1; cvt.u32.u64 %0, t; }"
        : "=r"(a) : "l"(p));
    return a;
}
__device__ __forceinline__ void ldsm4(uint32_t* r, uint32_t addr) {
    asm volatile("ldmatrix.sync.aligned.m8n8.x4.shared.b16 {%0,%1,%2,%3}, [%4];"
        : "=r"(r[0]), "=r"(r[1]), "=r"(r[2]), "=r"(r[3]) : "r"(addr));
}
__device__ __forceinline__ void mma16816(
    float& d0, float& d1, float& d2, float& d3,
    uint32_t a0, uint32_t a1, uint32_t a2, uint32_t a3,
    uint32_t b0, uint32_t b1)
{
    asm volatile(
        "mma.sync.aligned.m16n8k16.row.col.f32.bf16.bf16.f32 "
        "{%0,%1,%2,%3}, {%4,%5,%6,%7}, {%8,%9}, {%0,%1,%2,%3};"
        : "+f"(d0), "+f"(d1), "+f"(d2), "+f"(d3)
        : "r"(a0), "r"(a1), "r"(a2), "r"(a3), "r"(b0), "r"(b1));
}
__device__ __forceinline__ void mma16816h(
    float& d0, float& d1, float& d2, float& d3,
    uint32_t a0, uint32_t a1, uint32_t a2, uint32_t a3,
    uint32_t b0, uint32_t b1)
{
    asm volatile(
        "mma.sync.aligned.m16n8k16.row.col.f32.f16.f16.f32 "
        "{%0,%1,%2,%3}, {%4,%5,%6,%7}, {%8,%9}, {%0,%1,%2,%3};"
        : "+f"(d0), "+f"(d1), "+f"(d2), "+f"(d3)
        : "r"(a0), "r"(a1), "r"(a2), "r"(a3), "r"(b0), "r"(b1));
}
// bf16 2-way split of two floats -> packed bf16x2 (hi, lo)
__device__ __forceinline__ void split2(float x, float y, uint32_t& hi, uint32_t& lo) {
    bf16 hx = __float2bfloat16_rn(x);
    bf16 hy = __float2bfloat16_rn(y);
    __nv_bfloat162 h; h.x = hx; h.y = hy;
    __nv_bfloat162 l = __floats2bfloat162_rn(x - __bfloat162float(hx),
                                             y - __bfloat162float(hy));
    hi = *reinterpret_cast<uint32_t*>(&h);
    lo = *reinterpret_cast<uint32_t*>(&l);
}
// fp16 2-way split
__device__ __forceinline__ void split2h(float x, float y, uint32_t& hi, uint32_t& lo) {
    h16 hx = __float2half_rn(x);
    h16 hy = __float2half_rn(y);
    __half2 h = __halves2half2(hx, hy);
    __half2 l = __floats2half2_rn(x - __half2float(hx), y - __half2float(hy));
    hi = *reinterpret_cast<uint32_t*>(&h);
    lo = *reinterpret_cast<uint32_t*>(&l);
}
__device__ __forceinline__ uint32_t pack_h2(float x, float y) {
    __half2 p = __floats2half2_rn(x, y);
    return *reinterpret_cast<uint32_t*>(&p);
}
// SMEM tile row = 64B (32 elems) in 4x16B chunks, xor-swizzled
__device__ __forceinline__ uint32_t swz(int row, int chunk) {
    return (uint32_t)((row << 6) + (((chunk ^ ((row >> 1) & 3)) & 3) << 4));
}
__device__ __forceinline__ float silu(float v) { return v / (1.f + __expf(-v)); }

// ---------------------------------------------------------------------------
// mma GEMM.  PREC=0: bf16x3.  PREC=1: fp16 A-split x2, fp16-single B.
// PREC=2: plain fp16 single-product (A single, B single).
// EPI: 0 fp32 store; 1 softplus+clip(+bias); 3 GEMM1 dual out (xs fp16).
// ---------------------------------------------------------------------------
template <int EPI, int PREC>
__global__ __launch_bounds__(256) void mma_gemm(
    const float* __restrict__ A, int lda,
    const float* __restrict__ Bt, int ldb,
    float* __restrict__ C, int ldc,
    int K, const float* __restrict__ bias,
    h16* __restrict__ xsh)
{
    __shared__ __align__(16) char sAhi[8192], sAlo[8192], sBhi[8192], sBlo[8192];

    const int tid  = threadIdx.x;
    const int lane = tid & 31;
    const int wid  = tid >> 5;
    const int wm   = wid & 1;
    const int wn   = wid >> 1;
    const int m0   = blockIdx.y * 128;
    const int n0   = blockIdx.x * 128;
    const int TOT  = K >> 5;

    const uint32_t aHiB = smem_u32(sAhi), aLoB = smem_u32(sAlo);
    const uint32_t bHiB = smem_u32(sBhi), bLoB = smem_u32(sBlo);

    const int a_r  = lane & 15;
    const int a_cx = lane >> 4;
    const int b_r  = (lane & 7) + ((lane >> 4) << 3);
    const int b_cx = (lane >> 3) & 1;

    float acc[4][4][4];
#pragma unroll
    for (int i = 0; i < 4; i++)
#pragma unroll
        for (int j = 0; j < 4; j++)
#pragma unroll
            for (int k = 0; k < 4; k++) acc[i][j][k] = 0.f;

    float4 pa[4], pb[4];

    auto load = [&](int kb) {
#pragma unroll
        for (int i = 0; i < 4; i++) {
            int idx = tid + i * 256;
            int row = idx >> 3, seg = idx & 7;
            pa[i] = *(const float4*)(A + (size_t)(m0 + row) * lda + kb * 32 + seg * 4);
            pb[i] = *(const float4*)(Bt + (size_t)(n0 + row) * ldb + kb * 32 + seg * 4);
        }
    };

    auto store = [&]() {
#pragma unroll
        for (int i = 0; i < 4; i++) {
            int idx = tid + i * 256;
            int row = idx >> 3, seg = idx & 7;
            uint32_t off = swz(row, seg >> 1) + (seg & 1) * 8;
            uint2 h, l;
            if (PREC == 0) {
                split2(pa[i].x, pa[i].y, h.x, l.x);
                split2(pa[i].z, pa[i].w, h.y, l.y);
                *(uint2*)(sAhi + off) = h;
                *(uint2*)(sAlo + off) = l;
                split2(pb[i].x, pb[i].y, h.x, l.x);
                split2(pb[i].z, pb[i].w, h.y, l.y);
                *(uint2*)(sBhi + off) = h;
                *(uint2*)(sBlo + off) = l;
            } else if (PREC == 1) {
                split2h(pa[i].x, pa[i].y, h.x, l.x);
                split2h(pa[i].z, pa[i].w, h.y, l.y);
                *(uint2*)(sAhi + off) = h;
                *(uint2*)(sAlo + off) = l;
                h.x = pack_h2(pb[i].x, pb[i].y);
                h.y = pack_h2(pb[i].z, pb[i].w);
                *(uint2*)(sBhi + off) = h;
            } else {   // PREC == 2: single fp16 both operands
                h.x = pack_h2(pa[i].x, pa[i].y);
                h.y = pack_h2(pa[i].z, pa[i].w);
                *(uint2*)(sAhi + off) = h;
                h.x = pack_h2(pb[i].x, pb[i].y);
                h.y = pack_h2(pb[i].z, pb[i].w);
                *(uint2*)(sBhi + off) = h;
            }
        }
    };

    auto mma_block = [&]() {
#pragma unroll
        for (int ks = 0; ks < 2; ks++) {
            uint32_t a[4][4], bh[4][2];
#pragma unroll
            for (int mf = 0; mf < 4; mf++) {
                int row = wm * 64 + mf * 16 + a_r;
                ldsm4(a[mf], aHiB + swz(row, ks * 2 + a_cx));
            }
#pragma unroll
            for (int p = 0; p < 2; p++) {
                int row = wn * 32 + p * 16 + b_r;
                uint32_t t[4];
                ldsm4(t, bHiB + swz(row, ks * 2 + b_cx));
                bh[p * 2][0] = t[0]; bh[p * 2][1] = t[1];
                bh[p * 2 + 1][0] = t[2]; bh[p * 2 + 1][1] = t[3];
            }
#pragma unroll
            for (int mf = 0; mf < 4; mf++)
#pragma unroll
                for (int nf = 0; nf < 4; nf++) {
                    if (PREC == 0)
                        mma16816(acc[mf][nf][0], acc[mf][nf][1], acc[mf][nf][2], acc[mf][nf][3],
                                 a[mf][0], a[mf][1], a[mf][2], a[mf][3], bh[nf][0], bh[nf][1]);
                    else
                        mma16816h(acc[mf][nf][0], acc[mf][nf][1], acc[mf][nf][2], acc[mf][nf][3],
                                  a[mf][0], a[mf][1], a[mf][2], a[mf][3], bh[nf][0], bh[nf][1]);
                }
            if (PREC == 0) {
                uint32_t bx[4][2];
#pragma unroll
                for (int p = 0; p < 2; p++) {
                    int row = wn * 32 + p * 16 + b_r;
                    uint32_t t[4];
                    ldsm4(t, bLoB + swz(row, ks * 2 + b_cx));
                    bx[p * 2][0] = t[0]; bx[p * 2][1] = t[1];
                    bx[p * 2 + 1][0] = t[2]; bx[p * 2 + 1][1] = t[3];
                }
#pragma unroll
                for (int mf = 0; mf < 4; mf++)
#pragma unroll
                    for (int nf = 0; nf < 4; nf++)
                        mma16816(acc[mf][nf][0], acc[mf][nf][1], acc[mf][nf][2], acc[mf][nf][3],
                                 a[mf][0], a[mf][1], a[mf][2], a[mf][3], bx[nf][0], bx[nf][1]);
            }
            if (PREC != 2) {
#pragma unroll
                for (int mf = 0; mf < 4; mf++) {
                    int row = wm * 64 + mf * 16 + a_r;
                    ldsm4(a[mf], aLoB + swz(row, ks * 2 + a_cx));
                }
#pragma unroll
                for (int mf = 0; mf < 4; mf++)
#pragma unroll
                    for (int nf = 0; nf < 4; nf++) {
                        if (PREC == 0)
                            mma16816(acc[mf][nf][0], acc[mf][nf][1], acc[mf][nf][2], acc[mf][nf][3],
                                     a[mf][0], a[mf][1], a[mf][2], a[mf][3], bh[nf][0], bh[nf][1]);
                        else
                            mma16816h(acc[mf][nf][0], acc[mf][nf][1], acc[mf][nf][2], acc[mf][nf][3],
                                      a[mf][0], a[mf][1], a[mf][2], a[mf][3], bh[nf][0], bh[nf][1]);
                    }
            }
        }
    };

    load(0);
    store();
    __syncthreads();
    for (int it = 1; it < TOT; it++) {
        load(it);
        mma_block();
        __syncthreads();
        store();
        __syncthreads();
    }
    mma_block();

    // Epilogue
#pragma unroll
    for (int mf = 0; mf < 4; mf++) {
        int r = m0 + wm * 64 + mf * 16 + (lane >> 2);
#pragma unroll
        for (int nf = 0; nf < 4; nf++) {
            int c = n0 + wn * 32 + nf * 8 + (lane & 3) * 2;
            float v0 = acc[mf][nf][0], v1 = acc[mf][nf][1];
            float v2 = acc[mf][nf][2], v3 = acc[mf][nf][3];
            if (EPI == 1) {
                float b0 = bias[c], b1 = bias[c + 1];
                float x0 = v0 + b0, x1 = v1 + b1, x2 = v2 + b0, x3 = v3 + b1;
                v0 = fminf(fmaxf(fmaxf(x0, 0.f) + log1pf(__expf(-fabsf(x0))), 1e-3f), 0.1f);
                v1 = fminf(fmaxf(fmaxf(x1, 0.f) + log1pf(__expf(-fabsf(x1))), 1e-3f), 0.1f);
                v2 = fminf(fmaxf(fmaxf(x2, 0.f) + log1pf(__expf(-fabsf(x2))), 1e-3f), 0.1f);
                v3 = fminf(fmaxf(fmaxf(x3, 0.f) + log1pf(__expf(-fabsf(x3))), 1e-3f), 0.1f);
            }
            if (EPI == 3) {
                if (n0 < 2048) {     // xs half -> fp16 for conv
                    *(uint32_t*)(xsh + (size_t)r * 2048 + c)       = pack_h2(v0, v1);
                    *(uint32_t*)(xsh + (size_t)(r + 8) * 2048 + c) = pack_h2(v2, v3);
                } else {             // res half -> silu -> sres fp32
                    int cc = c - 2048;
                    *(float2*)(C + (size_t)r * ldc + cc)
                        = make_float2(silu(v0), silu(v1));
                    *(float2*)(C + (size_t)(r + 8) * ldc + cc)
                        = make_float2(silu(v2), silu(v3));
                }
            } else {
                *(float2*)(C + (size_t)r * ldc + c)       = make_float2(v0, v1);
                *(float2*)(C + (size_t)(r + 8) * ldc + c) = make_float2(v2, v3);
            }
        }
    }
}

// ---------------------------------------------------------------------------
// Halo-fused grouped causal conv, fp16 single-product (R13-proven, unchanged)
// ---------------------------------------------------------------------------
#define CONV_STG  41472                      // 8704 (A) + 4*8192 (B)
#define CONV_SMEM (2 * CONV_STG + 1024)

__global__ __launch_bounds__(256) void conv_halo(
    const h16* __restrict__ Ah,            // xs fp16 [4096,2048]
    const h16* __restrict__ Bf,            // convT fp16 [4][2048,1024]
    const float* __restrict__ bias, float* __restrict__ U)
{
    extern __shared__ char dyn[];
    const uint32_t rawb = smem_u32(dyn);
    const uint32_t base = (rawb + 1023u) & ~1023u;
    char* tp = dyn + (base - rawb);

    const int tid  = threadIdx.x;
    const int lane = tid & 31;
    const int wid  = tid >> 5;
    const int wm   = wid & 1;
    const int wn   = wid >> 1;
    const int m0   = blockIdx.y * 128;
    const int n0   = blockIdx.x * 128;
    const int colbase = (n0 >= 1024) ? 1024 : 0;
    const bool headok = (m0 & (LSEQ - 1)) != 0;

    const int a_r  = lane & 15;
    const int a_cx = lane >> 4;
    const int b_r  = (lane & 7) + ((lane >> 4) << 3);
    const int b_cx = (lane >> 3) & 1;

    float acc[4][4][4];
#pragma unroll
    for (int i = 0; i < 4; i++)
#pragma unroll
        for (int j = 0; j < 4; j++)
#pragma unroll
            for (int k = 0; k < 4; k++) acc[i][j][k] = 0.f;

    uint4 sa[3], rb1[4], rb2[4];

    auto loadA = [&](int kb) {
#pragma unroll
        for (int i = 0; i < 3; i++) {
            int c = tid + i * 256;
            if (i < 2 || c < 524) {
                int row = c >> 2, seg = c & 3;
                bool valid = headok || (row >= 3);
                long grow = (long)m0 - 3 + row;
                sa[i] = valid
                    ? *(const uint4*)(Ah + grow * 2048 + colbase + kb * 32 + seg * 8)
                    : make_uint4(0, 0, 0, 0);
            }
        }
    };
    auto stsA = [&](int s) {
        char* sb = tp + s * CONV_STG;
#pragma unroll
        for (int i = 0; i < 3; i++) {
            int c = tid + i * 256;
            if (i < 2 || c < 524) {
                int row = c >> 2, seg = c & 3;
                *(uint4*)(sb + swz(row, seg)) = sa[i];
            }
        }
    };
    auto loadB = [&](int kb, int half, uint4* rb) {
#pragma unroll
        for (int i = 0; i < 4; i++) {
            int c = tid + i * 256;
            int tap = half * 2 + (c >> 9);
            int cc = c & 511;
            int row = cc >> 2, seg = cc & 3;
            rb[i] = *(const uint4*)(Bf + (size_t)tap * 2048 * 1024
                                       + (size_t)(n0 + row) * 1024 + kb * 32 + seg * 8);
        }
    };
    auto stsB = [&](int s, int half, uint4* rb) {
#pragma unroll
        for (int i = 0; i < 4; i++) {
            int c = tid + i * 256;
            int tap = half * 2 + (c >> 9);
            int cc = c & 511;
            int row = cc >> 2, seg = cc & 3;
            char* bb = tp + s * CONV_STG + 8704 + tap * 8192;
            *(uint4*)(bb + swz(row, seg)) = rb[i];
        }
    };
    auto mma_tap = [&](int s, int tap) {
        uint32_t aB = base + (uint32_t)s * CONV_STG;
        uint32_t bB = aB + 8704 + (uint32_t)tap * 8192;
#pragma unroll
        for (int ks = 0; ks < 2; ks++) {
            uint32_t a[4][4], bh[4][2];
#pragma unroll
            for (int mf = 0; mf < 4; mf++) {
                int row = wm * 64 + mf * 16 + a_r + tap;
                ldsm4(a[mf], aB + swz(row, ks * 2 + a_cx));
            }
#pragma unroll
            for (int p = 0; p < 2; p++) {
                int row = wn * 32 + p * 16 + b_r;
                uint32_t t[4];
                ldsm4(t, bB + swz(row, ks * 2 + b_cx));
                bh[p * 2][0] = t[0]; bh[p * 2][1] = t[1];
                bh[p * 2 + 1][0] = t[2]; bh[p * 2 + 1][1] = t[3];
            }
#pragma unroll
            for (int mf = 0; mf < 4; mf++)
#pragma unroll
                for (int nf = 0; nf < 4; nf++)
                    mma16816h(acc[mf][nf][0], acc[mf][nf][1], acc[mf][nf][2], acc[mf][nf][3],
                              a[mf][0], a[mf][1], a[mf][2], a[mf][3], bh[nf][0], bh[nf][1]);
        }
    };

    loadA(0); loadB(0, 0, rb1); loadB(0, 1, rb2);
    stsA(0); stsB(0, 0, rb1); stsB(0, 1, rb2);
    __syncthreads();

    for (int kb = 0; kb < 32; kb++) {
        int cur = kb & 1, nxt = cur ^ 1;
        bool more = (kb + 1) < 32;
        if (more) { loadA(kb + 1); loadB(kb + 1, 0, rb1); }
        mma_tap(cur, 0);
        mma_tap(cur, 1);
        if (more) { stsA(nxt); stsB(nxt, 0, rb1); loadB(kb + 1, 1, rb2); }
        mma_tap(cur, 2);
        mma_tap(cur, 3);
        if (more) stsB(nxt, 1, rb2);
        __syncthreads();
    }

#pragma unroll
    for (int mf = 0; mf < 4; mf++) {
        int r = m0 + wm * 64 + mf * 16 + (lane >> 2);
#pragma unroll
        for (int nf = 0; nf < 4; nf++) {
            int c = n0 + wn * 32 + nf * 8 + (lane & 3) * 2;
            float b0 = bias[c], b1 = bias[c + 1];
            float v0 = silu(acc[mf][nf][0] + b0);
            float v1 = silu(acc[mf][nf][1] + b1);
            float v2 = silu(acc[mf][nf][2] + b0);
            float v3 = silu(acc[mf][nf][3] + b1);
            *(float2*)(U + (size_t)r * DINNER + c)       = make_float2(v0, v1);
            *(float2*)(U + (size_t)(r + 8) * DINNER + c) = make_float2(v2, v3);
        }
    }
}

// ---------------------------------------------------------------------------
// Fused weight preprocessing (one launch)
// ---------------------------------------------------------------------------
__global__ __launch_bounds__(256) void fused_transpose(
    const float* __restrict__ Win, const float* __restrict__ convk,
    const float* __restrict__ Wout, const float* __restrict__ Wdt,
    float* __restrict__ winT, h16* __restrict__ cTf,
    float* __restrict__ woutT, float* __restrict__ wdtT)
{
    int z = blockIdx.z;
    const float* src; int R, C;
    if (z == 0)      { src = Win;  R = 1024; C = 4096; }
    else if (z <= 4) { src = convk + (size_t)(z - 1) * 1024 * 2048; R = 1024; C = 2048; }
    else if (z == 5) { src = Wout; R = 2048; C = 1024; }
    else             { src = Wdt;  R = 64;   C = 2048; }
    if (blockIdx.x * 32 >= C || blockIdx.y * 32 >= R) return;

    __shared__ float t[32][33];
    int x = blockIdx.x * 32 + threadIdx.x;
#pragma unroll
    for (int j = 0; j < 4; j++) {
        int y = blockIdx.y * 32 + threadIdx.y + j * 8;
        t[threadIdx.y + j * 8][threadIdx.x] = src[(size_t)y * C + x];
    }
    __syncthreads();
    int x2 = blockIdx.y * 32 + threadIdx.x;
#pragma unroll
    for (int j = 0; j < 4; j++) {
        int y2 = blockIdx.x * 32 + threadIdx.y + j * 8;
        float v = t[threadIdx.x][threadIdx.y + j * 8];
        if (z == 0) {
            winT[(size_t)y2 * R + x2] = v;
        } else if (z <= 4) {
            cTf[(size_t)(z - 1) * 2048 * 1024 + (size_t)y2 * R + x2] = __float2half_rn(v);
        } else if (z == 5) {
            woutT[(size_t)y2 * R + x2] = v;
        } else {
            wdtT[(size_t)y2 * R + x2] = v;
        }
    }
}

// ---------------------------------------------------------------------------
// Split-K narrow GEMM (R9-proven, unchanged)
// ---------------------------------------------------------------------------
__global__ __launch_bounds__(256) void gemm_n96_partial(
    const float* __restrict__ A, const float* __restrict__ B,
    float* __restrict__ P)
{
    const int BK = 32, NN = 96, KC = 256, BM = 64;
    __shared__ float As[BK][BM];
    __shared__ float Bs[BK][NN];

    const int m0 = blockIdx.x * BM;
    const int kc = blockIdx.y;
    const int kbeg = kc * KC;
    const int tid = threadIdx.x;
    const int tx = tid & 15;
    const int ty = tid >> 4;

    float acc[4][6];
#pragma unroll
    for (int r = 0; r < 4; r++)
#pragma unroll
        for (int j = 0; j < 6; j++) acc[r][j] = 0.f;

    for (int k0 = kbeg; k0 < kbeg + KC; k0 += BK) {
#pragma unroll
        for (int i = 0; i < 2; i++) {
            int idx = tid + i * 256;
            int row = idx >> 3;
            int cv  = (idx & 7) * 4;
            float4 a = *(const float4*)(A + (size_t)(m0 + row) * DINNER + k0 + cv);
            As[cv + 0][row] = a.x; As[cv + 1][row] = a.y;
            As[cv + 2][row] = a.z; As[cv + 3][row] = a.w;
        }
#pragma unroll
        for (int i = 0; i < 3; i++) {
            int idx  = tid + i * 256;
            int rowB = idx / 24;
            int cv   = (idx % 24) * 4;
            *(float4*)(&Bs[rowB][cv]) =
                *(const float4*)(B + (size_t)(k0 + rowB) * NN + cv);
        }
        __syncthreads();
#pragma unroll
        for (int k = 0; k < BK; k++) {
            float a[4];
            *(float4*)a = *(const float4*)(&As[k][ty * 4]);
            float b[6];
            *(float2*)(b)     = *(const float2*)(&Bs[k][tx * 6]);
            *(float2*)(b + 2) = *(const float2*)(&Bs[k][tx * 6 + 2]);
            *(float2*)(b + 4) = *(const float2*)(&Bs[k][tx * 6 + 4]);
#pragma unroll
            for (int r = 0; r < 4; r++)
#pragma unroll
                for (int j = 0; j < 6; j++)
                    acc[r][j] = fmaf(a[r], b[j], acc[r][j]);
        }
        __syncthreads();
    }
    float* out = P + (size_t)kc * BLROWS * 96;
#pragma unroll
    for (int r = 0; r < 4; r++) {
        int m = m0 + ty * 4 + r;
#pragma unroll
        for (int j = 0; j < 6; j++)
            out[(size_t)m * 96 + tx * 6 + j] = acc[r][j];
    }
}

__global__ __launch_bounds__(256) void gemm_n96_reduce(
    const float* __restrict__ P, float* __restrict__ C)
{
    size_t i = ((size_t)blockIdx.x * blockDim.x + threadIdx.x) * 4;
    const size_t S = (size_t)BLROWS * 96;
    float4 s = *(const float4*)(P + i);
#pragma unroll
    for (int kc = 1; kc < 8; kc++) {
        float4 v = *(const float4*)(P + kc * S + i);
        s.x += v.x; s.y += v.y; s.z += v.z; s.w += v.w;
    }
    *(float4*)(C + i) = s;
}

// ---------------------------------------------------------------------------
// Chunked parallel scan (R10-proven, unchanged)
// ---------------------------------------------------------------------------
__global__ __launch_bounds__(256) void scan_pass1(
    const float* __restrict__ delta, const float* __restrict__ u,
    const float* __restrict__ dbc, const float* __restrict__ A_log,
    float* __restrict__ P, float* __restrict__ H)
{
    const int tid  = threadIdx.x;
    const int lane = tid & 31;
    const int w    = tid >> 5;
    const int ng   = lane & 3;
    const int dl   = lane >> 2;
    const int d    = blockIdx.x * 64 + w * 8 + dl;
    const int c    = blockIdx.y;
    const int b    = blockIdx.z;

    float4 al = *(const float4*)(A_log + d * DSTATE + ng * 4);
    const float a0 = -__expf(al.x), a1 = -__expf(al.y);
    const float a2 = -__expf(al.z), a3 = -__expf(al.w);

    const size_t trow = (size_t)b * LSEQ + (size_t)c * TC;
    const float* dp  = delta + trow * DINNER + d;
    const float* up  = u     + trow * DINNER + d;
    const float* bcp = dbc   + trow * 96 + DTRANK + ng * 4;

    float h0 = 0.f, h1 = 0.f, h2 = 0.f, h3 = 0.f;
    float p0 = 1.f, p1 = 1.f, p2 = 1.f, p3 = 1.f;
    for (int t = 0; t < TC; t++) {
        float de = dp[(size_t)t * DINNER];
        float uu = up[(size_t)t * DINNER];
        float4 Bv = *(const float4*)(bcp + t * 96);
        float dA0 = __expf(de * a0), dA1 = __expf(de * a1);
        float dA2 = __expf(de * a2), dA3 = __expf(de * a3);
        float du = de * uu;
        p0 *= dA0; p1 *= dA1; p2 *= dA2; p3 *= dA3;
        h0 = fmaf(dA0, h0, du * Bv.x);
        h1 = fmaf(dA1, h1, du * Bv.y);
        h2 = fmaf(dA2, h2, du * Bv.z);
        h3 = fmaf(dA3, h3, du * Bv.w);
    }
    size_t o = (((size_t)b * NCH + c) * DINNER + d) * DSTATE + ng * 4;
    *(float4*)(P + o) = make_float4(p0, p1, p2, p3);
    *(float4*)(H + o) = make_float4(h0, h1, h2, h3);
}

__global__ __launch_bounds__(256) void scan_pass2(
    const float* __restrict__ P, const float* __restrict__ H,
    float* __restrict__ HIN)
{
    int idx = blockIdx.x * blockDim.x + threadIdx.x;
    int n = idx & 15;
    int d = (idx >> 4) & (DINNER - 1);
    int b = idx >> 15;
    float hin = 0.f;
#pragma unroll
    for (int c = 0; c < NCH; c++) {
        size_t o = (((size_t)b * NCH + c) * DINNER + d) * DSTATE + n;
        HIN[o] = hin;
        hin = fmaf(P[o], hin, H[o]);
    }
}

__global__ __launch_bounds__(256) void scan_pass3(
    const float* __restrict__ delta, const float* __restrict__ u,
    const float* __restrict__ dbc, const float* __restrict__ A_log,
    const float* __restrict__ Dp, const float* __restrict__ sres,
    const float* __restrict__ HIN, float* __restrict__ Y)
{
    const int tid  = threadIdx.x;
    const int lane = tid & 31;
    const int w    = tid >> 5;
    const int ng   = lane & 3;
    const int dl   = lane >> 2;
    const int d    = blockIdx.x * 64 + w * 8 + dl;
    const int c    = blockIdx.y;
    const int b    = blockIdx.z;

    float4 al = *(const float4*)(A_log + d * DSTATE + ng * 4);
    const float a0 = -__expf(al.x), a1 = -__expf(al.y);
    const float a2 = -__expf(al.z), a3 = -__expf(al.w);
    const float Dd = Dp[d];

    const size_t trow = (size_t)b * LSEQ + (size_t)c * TC;
    const float* dp  = delta + trow * DINNER + d;
    const float* up  = u     + trow * DINNER + d;
    const float* rp  = sres  + trow * DINNER + d;
    const float* bcp = dbc   + trow * 96 + DTRANK + ng * 4;
    float*       yp  = Y     + trow * DINNER + d;

    size_t o = (((size_t)b * NCH + c) * DINNER + d) * DSTATE + ng * 4;
    float4 hv = *(const float4*)(HIN + o);
    float h0 = hv.x, h1 = hv.y, h2 = hv.z, h3 = hv.w;

    for (int t = 0; t < TC; t++) {
        float de = dp[(size_t)t * DINNER];
        float uu = up[(size_t)t * DINNER];
        float4 Bv = *(const float4*)(bcp + t * 96);
        float4 Cv = *(const float4*)(bcp + t * 96 + DSTATE);
        float dA0 = __expf(de * a0), dA1 = __expf(de * a1);
        float dA2 = __expf(de * a2), dA3 = __expf(de * a3);
        float du = de * uu;
        h0 = fmaf(dA0, h0, du * Bv.x);
        h1 = fmaf(dA1, h1, du * Bv.y);
        h2 = fmaf(dA2, h2, du * Bv.z);
        h3 = fmaf(dA3, h3, du * Bv.w);
        float pp = h0 * Cv.x + h1 * Cv.y + h2 * Cv.z + h3 * Cv.w;
        pp += __shfl_xor_sync(0xffffffffu, pp, 1);
        pp += __shfl_xor_sync(0xffffffffu, pp, 2);
        if (ng == 0)
            yp[(size_t)t * DINNER] = fmaf(uu, Dd, pp) * rp[(size_t)t * DINNER];
    }
}

// ---------------------------------------------------------------------------
// Launch
// ---------------------------------------------------------------------------
extern "C" void kernel_launch(void* const* d_in, const int* in_sizes, int n_in,
                              void* d_out, int out_size)
{
    (void)in_sizes; (void)n_in; (void)out_size;
    const float* x      = (const float*)d_in[0];
    const float* W_in   = (const float*)d_in[1];
    const float* conv_k = (const float*)d_in[2];
    const float* conv_b = (const float*)d_in[3];
    const float* W_x    = (const float*)d_in[4];
    const float* W_dt   = (const float*)d_in[5];
    const float* b_dt   = (const float*)d_in[6];
    const float* A_log  = (const float*)d_in[7];
    const float* Dvec   = (const float*)d_in[8];
    const float* W_out  = (const float*)d_in[9];
    float* out = (float*)d_out;

    h16 *xsh, *convTf;
    float *sres, *u, *dbc, *dbcp, *delta, *y, *winT, *woutT, *wdtT;
    float *scP, *scH, *scHi;
    cudaGetSymbolAddress((void**)&xsh,   g_xsh);
    cudaGetSymbolAddress((void**)&sres,  g_sres);
    cudaGetSymbolAddress((void**)&u,     g_u);
    cudaGetSymbolAddress((void**)&dbc,   g_dbc);
    cudaGetSymbolAddress((void**)&dbcp,  g_dbc_part);
    cudaGetSymbolAddress((void**)&delta, g_delta);
    cudaGetSymbolAddress((void**)&y,     g_y);
    cudaGetSymbolAddress((void**)&winT,  g_WinT);
    cudaGetSymbolAddress((void**)&convTf, g_convTf);
    cudaGetSymbolAddress((void**)&woutT, g_WoutT);
    cudaGetSymbolAddress((void**)&wdtT,  g_WdtT);
    cudaGetSymbolAddress((void**)&scP,   g_scanP);
    cudaGetSymbolAddress((void**)&scH,   g_scanH);
    cudaGetSymbolAddress((void**)&scHi,  g_scanHi);

    cudaFuncSetAttribute(conv_halo, cudaFuncAttributeMaxDynamicSharedMemorySize, CONV_SMEM);

    // 0) all weight preprocessing in ONE launch
    fused_transpose<<<dim3(128, 64, 7), dim3(32, 8)>>>(
        W_in, conv_k, W_out, W_dt, winT, convTf, woutT, wdtT);

    // 1) GEMM1 (fp16 single-product): xs -> fp16, silu(res) -> sres
    mma_gemm<3, 2><<<dim3(32, 32), 256>>>(
        x, DMODEL, winT, DMODEL, sres, DINNER, DMODEL, nullptr, xsh);

    // 2) halo-fused grouped causal conv (fp16 single-product) + bias + silu
    conv_halo<<<dim3(16, 32), 256, CONV_SMEM>>>(
        xsh, convTf, conv_b, u);

    // 3) dbc = u @ W_x
    gemm_n96_partial<<<dim3(64, 8), 256>>>(u, W_x, dbcp);
    gemm_n96_reduce<<<(BLROWS * 96 / 4) / 256, 256>>>(dbcp, dbc);

    // 4) delta = clip(softplus(dt_raw @ W_dt + b_dt))  (bf16x3, exact)
    mma_gemm<1, 0><<<dim3(16, 32), 256>>>(
        dbc, 96, wdtT, DTRANK, delta, DINNER, DTRANK, b_dt, nullptr);

    // 5) chunked parallel scan (+ fused gate) -> y fp32
    scan_pass1<<<dim3(32, NCH, 2), 256>>>(delta, u, dbc, A_log, scP, scH);
    scan_pass2<<<256, 256>>>(scP, scH, scHi);
    scan_pass3<<<dim3(32, NCH, 2), 256>>>(delta, u, dbc, A_log, Dvec, sres, scHi, y);

    // 6) out = y @ W_out  (fp16 single-product)
    mma_gemm<0, 2><<<dim3(8, 32), 256>>>(
        y, DINNER, woutT, DINNER, out, DMODEL, DINNER, nullptr, nullptr);
}

// round 15
// speedup vs baseline: 2.9853x; 1.0534x over previous
#include <cuda_runtime.h>
#include <cuda_bf16.h>
#include <cuda_fp16.h>
#include <cstdint>

// Problem constants
#define BLROWS 4096   // B*L = 2*2048
#define LSEQ   2048
#define DMODEL 1024
#define DINNER 2048
#define DSTATE 16
#define DTRANK 64
#define NCH    16     // scan chunks
#define TC     128    // chunk length

typedef __nv_bfloat16 bf16;
typedef __half h16;

// ---------------------------------------------------------------------------
// Scratch (device globals)
// ---------------------------------------------------------------------------
__device__ h16   g_xh16[(size_t)BLROWS * DMODEL];    // x pre-converted fp16
__device__ h16   g_xsh[(size_t)BLROWS * DINNER];     // xs fp16 (from GEMM1)
__device__ float g_sres[(size_t)BLROWS * DINNER];
__device__ float g_u  [(size_t)BLROWS * DINNER];
__device__ float g_dbc[(size_t)BLROWS * 96];
__device__ float g_dbc_part[(size_t)8 * BLROWS * 96];
__device__ float g_delta[(size_t)BLROWS * DINNER];
__device__ float g_y [(size_t)BLROWS * DINNER];
// scan chunk scratch: [b][c][d][n]
__device__ float g_scanP [(size_t)2 * NCH * DINNER * DSTATE];
__device__ float g_scanH [(size_t)2 * NCH * DINNER * DSTATE];
__device__ float g_scanHi[(size_t)2 * NCH * DINNER * DSTATE];
// Transposed weights
__device__ h16   g_WinT [(size_t)4096 * 1024];                 // fp16
__device__ h16   g_convTf[(size_t)4 * 2048 * 1024];            // fp16
__device__ h16   g_WoutT[(size_t)1024 * 2048];                 // fp16
__device__ float g_WdtT [(size_t)2048 * 64];                   // fp32 (bf16x3)

// ---------------------------------------------------------------------------
// PTX helpers
// ---------------------------------------------------------------------------
__device__ __forceinline__ uint32_t smem_u32(const void* p) {
    uint32_t a;
    asm("{ .reg .u64 t; cvta.to.shared.u64 t, %1; cvt.u32.u64 %0, t; }"
        : "=r"(a) : "l"(p));
    return a;
}
__device__ __forceinline__ void ldsm4(uint32_t* r, uint32_t addr) {
    asm volatile("ldmatrix.sync.aligned.m8n8.x4.shared.b16 {%0,%1,%2,%3}, [%4];"
        : "=r"(r[0]), "=r"(r[1]), "=r"(r[2]), "=r"(r[3]) : "r"(addr));
}
__device__ __forceinline__ void mma16816(
    float& d0, float& d1, float& d2, float& d3,
    uint32_t a0, uint32_t a1, uint32_t a2, uint32_t a3,
    uint32_t b0, uint32_t b1)
{
    asm volatile(
        "mma.sync.aligned.m16n8k16.row.col.f32.bf16.bf16.f32 "
        "{%0,%1,%2,%3}, {%4,%5,%6,%7}, {%8,%9}, {%0,%1,%2,%3};"
        : "+f"(d0), "+f"(d1), "+f"(d2), "+f"(d3)
        : "r"(a0), "r"(a1), "r"(a2), "r"(a3), "r"(b0), "r"(b1));
}
__device__ __forceinline__ void mma16816h(
    float& d0, float& d1, float& d2, float& d3,
    uint32_t a0, uint32_t a1, uint32_t a2, uint32_t a3,
    uint32_t b0, uint32_t b1)
{
    asm volatile(
        "mma.sync.aligned.m16n8k16.row.col.f32.f16.f16.f32 "
        "{%0,%1,%2,%3}, {%4,%5,%6,%7}, {%8,%9}, {%0,%1,%2,%3};"
        : "+f"(d0), "+f"(d1), "+f"(d2), "+f"(d3)
        : "r"(a0), "r"(a1), "r"(a2), "r"(a3), "r"(b0), "r"(b1));
}
// bf16 2-way split of two floats -> packed bf16x2 (hi, lo)
__device__ __forceinline__ void split2(float x, float y, uint32_t& hi, uint32_t& lo) {
    bf16 hx = __float2bfloat16_rn(x);
    bf16 hy = __float2bfloat16_rn(y);
    __nv_bfloat162 h; h.x = hx; h.y = hy;
    __nv_bfloat162 l = __floats2bfloat162_rn(x - __bfloat162float(hx),
                                             y - __bfloat162float(hy));
    hi = *reinterpret_cast<uint32_t*>(&h);
    lo = *reinterpret_cast<uint32_t*>(&l);
}
__device__ __forceinline__ uint32_t pack_h2(float x, float y) {
    __half2 p = __floats2half2_rn(x, y);
    return *reinterpret_cast<uint32_t*>(&p);
}
// SMEM tile row = 64B (32 elems) in 4x16B chunks, xor-swizzled
__device__ __forceinline__ uint32_t swz(int row, int chunk) {
    return (uint32_t)((row << 6) + (((chunk ^ ((row >> 1) & 3)) & 3) << 4));
}
__device__ __forceinline__ float silu(float v) { return v / (1.f + __expf(-v)); }

// ---------------------------------------------------------------------------
// mma GEMM.  PREC=0: bf16x3 (fp32 in).  PREC=2: fp16 single-product.
// A16/B16: operand already fp16 in gmem (load direct, no cvt).
// EPI: 0 fp32 store; 1 softplus+clip(+bias); 3 GEMM1 dual out (xs fp16).
// ---------------------------------------------------------------------------
template <int EPI, int PREC, int A16, int B16>
__global__ __launch_bounds__(256) void mma_gemm(
    const void* __restrict__ Av, int lda,
    const void* __restrict__ Bv, int ldb,
    float* __restrict__ C, int ldc,
    int K, const float* __restrict__ bias,
    h16* __restrict__ xsh)
{
    __shared__ __align__(16) char sAhi[8192], sAlo[8192], sBhi[8192], sBlo[8192];

    const int tid  = threadIdx.x;
    const int lane = tid & 31;
    const int wid  = tid >> 5;
    const int wm   = wid & 1;
    const int wn   = wid >> 1;
    const int m0   = blockIdx.y * 128;
    const int n0   = blockIdx.x * 128;
    const int TOT  = K >> 5;

    const uint32_t aHiB = smem_u32(sAhi), aLoB = smem_u32(sAlo);
    const uint32_t bHiB = smem_u32(sBhi), bLoB = smem_u32(sBlo);

    const int a_r  = lane & 15;
    const int a_cx = lane >> 4;
    const int b_r  = (lane & 7) + ((lane >> 4) << 3);
    const int b_cx = (lane >> 3) & 1;

    float acc[4][4][4];
#pragma unroll
    for (int i = 0; i < 4; i++)
#pragma unroll
        for (int j = 0; j < 4; j++)
#pragma unroll
            for (int k = 0; k < 4; k++) acc[i][j][k] = 0.f;

    float4 pa[4], pb[4];
    uint4  qa[2], qb[2];

    auto load = [&](int kb) {
        if (A16) {
#pragma unroll
            for (int i = 0; i < 2; i++) {
                int c = tid + i * 256;
                int row = c >> 2, seg = c & 3;
                qa[i] = *(const uint4*)((const h16*)Av + (size_t)(m0 + row) * lda + kb * 32 + seg * 8);
            }
        } else {
#pragma unroll
            for (int i = 0; i < 4; i++) {
                int idx = tid + i * 256;
                int row = idx >> 3, seg = idx & 7;
                pa[i] = *(const float4*)((const float*)Av + (size_t)(m0 + row) * lda + kb * 32 + seg * 4);
            }
        }
        if (B16) {
#pragma unroll
            for (int i = 0; i < 2; i++) {
                int c = tid + i * 256;
                int row = c >> 2, seg = c & 3;
                qb[i] = *(const uint4*)((const h16*)Bv + (size_t)(n0 + row) * ldb + kb * 32 + seg * 8);
            }
        } else {
#pragma unroll
            for (int i = 0; i < 4; i++) {
                int idx = tid + i * 256;
                int row = idx >> 3, seg = idx & 7;
                pb[i] = *(const float4*)((const float*)Bv + (size_t)(n0 + row) * ldb + kb * 32 + seg * 4);
            }
        }
    };

    auto store = [&]() {
        if (A16) {
#pragma unroll
            for (int i = 0; i < 2; i++) {
                int c = tid + i * 256;
                int row = c >> 2, seg = c & 3;
                *(uint4*)(sAhi + swz(row, seg)) = qa[i];
            }
        } else {
#pragma unroll
            for (int i = 0; i < 4; i++) {
                int idx = tid + i * 256;
                int row = idx >> 3, seg = idx & 7;
                uint32_t off = swz(row, seg >> 1) + (seg & 1) * 8;
                uint2 h, l;
                if (PREC == 0) {
                    split2(pa[i].x, pa[i].y, h.x, l.x);
                    split2(pa[i].z, pa[i].w, h.y, l.y);
                    *(uint2*)(sAhi + off) = h;
                    *(uint2*)(sAlo + off) = l;
                } else {
                    h.x = pack_h2(pa[i].x, pa[i].y);
                    h.y = pack_h2(pa[i].z, pa[i].w);
                    *(uint2*)(sAhi + off) = h;
                }
            }
        }
        if (B16) {
#pragma unroll
            for (int i = 0; i < 2; i++) {
                int c = tid + i * 256;
                int row = c >> 2, seg = c & 3;
                *(uint4*)(sBhi + swz(row, seg)) = qb[i];
            }
        } else {
#pragma unroll
            for (int i = 0; i < 4; i++) {
                int idx = tid + i * 256;
                int row = idx >> 3, seg = idx & 7;
                uint32_t off = swz(row, seg >> 1) + (seg & 1) * 8;
                uint2 h, l;
                if (PREC == 0) {
                    split2(pb[i].x, pb[i].y, h.x, l.x);
                    split2(pb[i].z, pb[i].w, h.y, l.y);
                    *(uint2*)(sBhi + off) = h;
                    *(uint2*)(sBlo + off) = l;
                } else {
                    h.x = pack_h2(pb[i].x, pb[i].y);
                    h.y = pack_h2(pb[i].z, pb[i].w);
                    *(uint2*)(sBhi + off) = h;
                }
            }
        }
    };

    auto mma_block = [&]() {
#pragma unroll
        for (int ks = 0; ks < 2; ks++) {
            uint32_t a[4][4], bh[4][2];
#pragma unroll
            for (int mf = 0; mf < 4; mf++) {
                int row = wm * 64 + mf * 16 + a_r;
                ldsm4(a[mf], aHiB + swz(row, ks * 2 + a_cx));
            }
#pragma unroll
            for (int p = 0; p < 2; p++) {
                int row = wn * 32 + p * 16 + b_r;
                uint32_t t[4];
                ldsm4(t, bHiB + swz(row, ks * 2 + b_cx));
                bh[p * 2][0] = t[0]; bh[p * 2][1] = t[1];
                bh[p * 2 + 1][0] = t[2]; bh[p * 2 + 1][1] = t[3];
            }
#pragma unroll
            for (int mf = 0; mf < 4; mf++)
#pragma unroll
                for (int nf = 0; nf < 4; nf++) {
                    if (PREC == 0)
                        mma16816(acc[mf][nf][0], acc[mf][nf][1], acc[mf][nf][2], acc[mf][nf][3],
                                 a[mf][0], a[mf][1], a[mf][2], a[mf][3], bh[nf][0], bh[nf][1]);
                    else
                        mma16816h(acc[mf][nf][0], acc[mf][nf][1], acc[mf][nf][2], acc[mf][nf][3],
                                  a[mf][0], a[mf][1], a[mf][2], a[mf][3], bh[nf][0], bh[nf][1]);
                }
            if (PREC == 0) {
                uint32_t bx[4][2];
#pragma unroll
                for (int p = 0; p < 2; p++) {
                    int row = wn * 32 + p * 16 + b_r;
                    uint32_t t[4];
                    ldsm4(t, bLoB + swz(row, ks * 2 + b_cx));
                    bx[p * 2][0] = t[0]; bx[p * 2][1] = t[1];
                    bx[p * 2 + 1][0] = t[2]; bx[p * 2 + 1][1] = t[3];
                }
#pragma unroll
                for (int mf = 0; mf < 4; mf++)
#pragma unroll
                    for (int nf = 0; nf < 4; nf++)
                        mma16816(acc[mf][nf][0], acc[mf][nf][1], acc[mf][nf][2], acc[mf][nf][3],
                                 a[mf][0], a[mf][1], a[mf][2], a[mf][3], bx[nf][0], bx[nf][1]);
#pragma unroll
                for (int mf = 0; mf < 4; mf++) {
                    int row = wm * 64 + mf * 16 + a_r;
                    ldsm4(a[mf], aLoB + swz(row, ks * 2 + a_cx));
                }
#pragma unroll
                for (int mf = 0; mf < 4; mf++)
#pragma unroll
                    for (int nf = 0; nf < 4; nf++)
                        mma16816(acc[mf][nf][0], acc[mf][nf][1], acc[mf][nf][2], acc[mf][nf][3],
                                 a[mf][0], a[mf][1], a[mf][2], a[mf][3], bh[nf][0], bh[nf][1]);
            }
        }
    };

    load(0);
    store();
    __syncthreads();
    for (int it = 1; it < TOT; it++) {
        load(it);
        mma_block();
        __syncthreads();
        store();
        __syncthreads();
    }
    mma_block();

    // Epilogue
#pragma unroll
    for (int mf = 0; mf < 4; mf++) {
        int r = m0 + wm * 64 + mf * 16 + (lane >> 2);
#pragma unroll
        for (int nf = 0; nf < 4; nf++) {
            int c = n0 + wn * 32 + nf * 8 + (lane & 3) * 2;
            float v0 = acc[mf][nf][0], v1 = acc[mf][nf][1];
            float v2 = acc[mf][nf][2], v3 = acc[mf][nf][3];
            if (EPI == 1) {
                float b0 = bias[c], b1 = bias[c + 1];
                float x0 = v0 + b0, x1 = v1 + b1, x2 = v2 + b0, x3 = v3 + b1;
                v0 = fminf(fmaxf(fmaxf(x0, 0.f) + log1pf(__expf(-fabsf(x0))), 1e-3f), 0.1f);
                v1 = fminf(fmaxf(fmaxf(x1, 0.f) + log1pf(__expf(-fabsf(x1))), 1e-3f), 0.1f);
                v2 = fminf(fmaxf(fmaxf(x2, 0.f) + log1pf(__expf(-fabsf(x2))), 1e-3f), 0.1f);
                v3 = fminf(fmaxf(fmaxf(x3, 0.f) + log1pf(__expf(-fabsf(x3))), 1e-3f), 0.1f);
            }
            if (EPI == 3) {
                if (n0 < 2048) {     // xs half -> fp16 for conv
                    *(uint32_t*)(xsh + (size_t)r * 2048 + c)       = pack_h2(v0, v1);
                    *(uint32_t*)(xsh + (size_t)(r + 8) * 2048 + c) = pack_h2(v2, v3);
                } else {             // res half -> silu -> sres fp32
                    int cc = c - 2048;
                    *(float2*)(C + (size_t)r * ldc + cc)
                        = make_float2(silu(v0), silu(v1));
                    *(float2*)(C + (size_t)(r + 8) * ldc + cc)
                        = make_float2(silu(v2), silu(v3));
                }
            } else {
                *(float2*)(C + (size_t)r * ldc + c)       = make_float2(v0, v1);
                *(float2*)(C + (size_t)(r + 8) * ldc + c) = make_float2(v2, v3);
            }
        }
    }
}

// ---------------------------------------------------------------------------
// Halo-fused grouped causal conv, fp16 single-product (R13-proven, unchanged)
// ---------------------------------------------------------------------------
#define CONV_STG  41472                      // 8704 (A) + 4*8192 (B)
#define CONV_SMEM (2 * CONV_STG + 1024)

__global__ __launch_bounds__(256) void conv_halo(
    const h16* __restrict__ Ah,            // xs fp16 [4096,2048]
    const h16* __restrict__ Bf,            // convT fp16 [4][2048,1024]
    const float* __restrict__ bias, float* __restrict__ U)
{
    extern __shared__ char dyn[];
    const uint32_t rawb = smem_u32(dyn);
    const uint32_t base = (rawb + 1023u) & ~1023u;
    char* tp = dyn + (base - rawb);

    const int tid  = threadIdx.x;
    const int lane = tid & 31;
    const int wid  = tid >> 5;
    const int wm   = wid & 1;
    const int wn   = wid >> 1;
    const int m0   = blockIdx.y * 128;
    const int n0   = blockIdx.x * 128;
    const int colbase = (n0 >= 1024) ? 1024 : 0;
    const bool headok = (m0 & (LSEQ - 1)) != 0;

    const int a_r  = lane & 15;
    const int a_cx = lane >> 4;
    const int b_r  = (lane & 7) + ((lane >> 4) << 3);
    const int b_cx = (lane >> 3) & 1;

    float acc[4][4][4];
#pragma unroll
    for (int i = 0; i < 4; i++)
#pragma unroll
        for (int j = 0; j < 4; j++)
#pragma unroll
            for (int k = 0; k < 4; k++) acc[i][j][k] = 0.f;

    uint4 sa[3], rb1[4], rb2[4];

    auto loadA = [&](int kb) {
#pragma unroll
        for (int i = 0; i < 3; i++) {
            int c = tid + i * 256;
            if (i < 2 || c < 524) {
                int row = c >> 2, seg = c & 3;
                bool valid = headok || (row >= 3);
                long grow = (long)m0 - 3 + row;
                sa[i] = valid
                    ? *(const uint4*)(Ah + grow * 2048 + colbase + kb * 32 + seg * 8)
                    : make_uint4(0, 0, 0, 0);
            }
        }
    };
    auto stsA = [&](int s) {
        char* sb = tp + s * CONV_STG;
#pragma unroll
        for (int i = 0; i < 3; i++) {
            int c = tid + i * 256;
            if (i < 2 || c < 524) {
                int row = c >> 2, seg = c & 3;
                *(uint4*)(sb + swz(row, seg)) = sa[i];
            }
        }
    };
    auto loadB = [&](int kb, int half, uint4* rb) {
#pragma unroll
        for (int i = 0; i < 4; i++) {
            int c = tid + i * 256;
            int tap = half * 2 + (c >> 9);
            int cc = c & 511;
            int row = cc >> 2, seg = cc & 3;
            rb[i] = *(const uint4*)(Bf + (size_t)tap * 2048 * 1024
                                       + (size_t)(n0 + row) * 1024 + kb * 32 + seg * 8);
        }
    };
    auto stsB = [&](int s, int half, uint4* rb) {
#pragma unroll
        for (int i = 0; i < 4; i++) {
            int c = tid + i * 256;
            int tap = half * 2 + (c >> 9);
            int cc = c & 511;
            int row = cc >> 2, seg = cc & 3;
            char* bb = tp + s * CONV_STG + 8704 + tap * 8192;
            *(uint4*)(bb + swz(row, seg)) = rb[i];
        }
    };
    auto mma_tap = [&](int s, int tap) {
        uint32_t aB = base + (uint32_t)s * CONV_STG;
        uint32_t bB = aB + 8704 + (uint32_t)tap * 8192;
#pragma unroll
        for (int ks = 0; ks < 2; ks++) {
            uint32_t a[4][4], bh[4][2];
#pragma unroll
            for (int mf = 0; mf < 4; mf++) {
                int row = wm * 64 + mf * 16 + a_r + tap;
                ldsm4(a[mf], aB + swz(row, ks * 2 + a_cx));
            }
#pragma unroll
            for (int p = 0; p < 2; p++) {
                int row = wn * 32 + p * 16 + b_r;
                uint32_t t[4];
                ldsm4(t, bB + swz(row, ks * 2 + b_cx));
                bh[p * 2][0] = t[0]; bh[p * 2][1] = t[1];
                bh[p * 2 + 1][0] = t[2]; bh[p * 2 + 1][1] = t[3];
            }
#pragma unroll
            for (int mf = 0; mf < 4; mf++)
#pragma unroll
                for (int nf = 0; nf < 4; nf++)
                    mma16816h(acc[mf][nf][0], acc[mf][nf][1], acc[mf][nf][2], acc[mf][nf][3],
                              a[mf][0], a[mf][1], a[mf][2], a[mf][3], bh[nf][0], bh[nf][1]);
        }
    };

    loadA(0); loadB(0, 0, rb1); loadB(0, 1, rb2);
    stsA(0); stsB(0, 0, rb1); stsB(0, 1, rb2);
    __syncthreads();

    for (int kb = 0; kb < 32; kb++) {
        int cur = kb & 1, nxt = cur ^ 1;
        bool more = (kb + 1) < 32;
        if (more) { loadA(kb + 1); loadB(kb + 1, 0, rb1); }
        mma_tap(cur, 0);
        mma_tap(cur, 1);
        if (more) { stsA(nxt); stsB(nxt, 0, rb1); loadB(kb + 1, 1, rb2); }
        mma_tap(cur, 2);
        mma_tap(cur, 3);
        if (more) stsB(nxt, 1, rb2);
        __syncthreads();
    }

#pragma unroll
    for (int mf = 0; mf < 4; mf++) {
        int r = m0 + wm * 64 + mf * 16 + (lane >> 2);
#pragma unroll
        for (int nf = 0; nf < 4; nf++) {
            int c = n0 + wn * 32 + nf * 8 + (lane & 3) * 2;
            float b0 = bias[c], b1 = bias[c + 1];
            float v0 = silu(acc[mf][nf][0] + b0);
            float v1 = silu(acc[mf][nf][1] + b1);
            float v2 = silu(acc[mf][nf][2] + b0);
            float v3 = silu(acc[mf][nf][3] + b1);
            *(float2*)(U + (size_t)r * DINNER + c)       = make_float2(v0, v1);
            *(float2*)(U + (size_t)(r + 8) * DINNER + c) = make_float2(v2, v3);
        }
    }
}

// ---------------------------------------------------------------------------
// Fused weight preprocessing (one launch); Win/Wout now stored fp16
// ---------------------------------------------------------------------------
__global__ __launch_bounds__(256) void fused_transpose(
    const float* __restrict__ Win, const float* __restrict__ convk,
    const float* __restrict__ Wout, const float* __restrict__ Wdt,
    h16* __restrict__ winT, h16* __restrict__ cTf,
    h16* __restrict__ woutT, float* __restrict__ wdtT)
{
    int z = blockIdx.z;
    const float* src; int R, C;
    if (z == 0)      { src = Win;  R = 1024; C = 4096; }
    else if (z <= 4) { src = convk + (size_t)(z - 1) * 1024 * 2048; R = 1024; C = 2048; }
    else if (z == 5) { src = Wout; R = 2048; C = 1024; }
    else             { src = Wdt;  R = 64;   C = 2048; }
    if (blockIdx.x * 32 >= C || blockIdx.y * 32 >= R) return;

    __shared__ float t[32][33];
    int x = blockIdx.x * 32 + threadIdx.x;
#pragma unroll
    for (int j = 0; j < 4; j++) {
        int y = blockIdx.y * 32 + threadIdx.y + j * 8;
        t[threadIdx.y + j * 8][threadIdx.x] = src[(size_t)y * C + x];
    }
    __syncthreads();
    int x2 = blockIdx.y * 32 + threadIdx.x;
#pragma unroll
    for (int j = 0; j < 4; j++) {
        int y2 = blockIdx.x * 32 + threadIdx.y + j * 8;
        float v = t[threadIdx.x][threadIdx.y + j * 8];
        if (z == 0) {
            winT[(size_t)y2 * R + x2] = __float2half_rn(v);
        } else if (z <= 4) {
            cTf[(size_t)(z - 1) * 2048 * 1024 + (size_t)y2 * R + x2] = __float2half_rn(v);
        } else if (z == 5) {
            woutT[(size_t)y2 * R + x2] = __float2half_rn(v);
        } else {
            wdtT[(size_t)y2 * R + x2] = v;
        }
    }
}

// x fp32 -> fp16 (same rounding as the old in-kernel conversion)
__global__ __launch_bounds__(256) void convert_x_kernel(
    const float* __restrict__ src, h16* __restrict__ dst)
{
    size_t i = ((size_t)blockIdx.x * blockDim.x + threadIdx.x) * 8;
    float4 a = *(const float4*)(src + i);
    float4 b = *(const float4*)(src + i + 4);
    uint4 o;
    o.x = pack_h2(a.x, a.y);
    o.y = pack_h2(a.z, a.w);
    o.z = pack_h2(b.x, b.y);
    o.w = pack_h2(b.z, b.w);
    *(uint4*)(dst + i) = o;
}

// ---------------------------------------------------------------------------
// Split-K narrow GEMM (R9-proven, unchanged)
// ---------------------------------------------------------------------------
__global__ __launch_bounds__(256) void gemm_n96_partial(
    const float* __restrict__ A, const float* __restrict__ B,
    float* __restrict__ P)
{
    const int BK = 32, NN = 96, KC = 256, BM = 64;
    __shared__ float As[BK][BM];
    __shared__ float Bs[BK][NN];

    const int m0 = blockIdx.x * BM;
    const int kc = blockIdx.y;
    const int kbeg = kc * KC;
    const int tid = threadIdx.x;
    const int tx = tid & 15;
    const int ty = tid >> 4;

    float acc[4][6];
#pragma unroll
    for (int r = 0; r < 4; r++)
#pragma unroll
        for (int j = 0; j < 6; j++) acc[r][j] = 0.f;

    for (int k0 = kbeg; k0 < kbeg + KC; k0 += BK) {
#pragma unroll
        for (int i = 0; i < 2; i++) {
            int idx = tid + i * 256;
            int row = idx >> 3;
            int cv  = (idx & 7) * 4;
            float4 a = *(const float4*)(A + (size_t)(m0 + row) * DINNER + k0 + cv);
            As[cv + 0][row] = a.x; As[cv + 1][row] = a.y;
            As[cv + 2][row] = a.z; As[cv + 3][row] = a.w;
        }
#pragma unroll
        for (int i = 0; i < 3; i++) {
            int idx  = tid + i * 256;
            int rowB = idx / 24;
            int cv   = (idx % 24) * 4;
            *(float4*)(&Bs[rowB][cv]) =
                *(const float4*)(B + (size_t)(k0 + rowB) * NN + cv);
        }
        __syncthreads();
#pragma unroll
        for (int k = 0; k < BK; k++) {
            float a[4];
            *(float4*)a = *(const float4*)(&As[k][ty * 4]);
            float b[6];
            *(float2*)(b)     = *(const float2*)(&Bs[k][tx * 6]);
            *(float2*)(b + 2) = *(const float2*)(&Bs[k][tx * 6 + 2]);
            *(float2*)(b + 4) = *(const float2*)(&Bs[k][tx * 6 + 4]);
#pragma unroll
            for (int r = 0; r < 4; r++)
#pragma unroll
                for (int j = 0; j < 6; j++)
                    acc[r][j] = fmaf(a[r], b[j], acc[r][j]);
        }
        __syncthreads();
    }
    float* out = P + (size_t)kc * BLROWS * 96;
#pragma unroll
    for (int r = 0; r < 4; r++) {
        int m = m0 + ty * 4 + r;
#pragma unroll
        for (int j = 0; j < 6; j++)
            out[(size_t)m * 96 + tx * 6 + j] = acc[r][j];
    }
}

__global__ __launch_bounds__(256) void gemm_n96_reduce(
    const float* __restrict__ P, float* __restrict__ C)
{
    size_t i = ((size_t)blockIdx.x * blockDim.x + threadIdx.x) * 4;
    const size_t S = (size_t)BLROWS * 96;
    float4 s = *(const float4*)(P + i);
#pragma unroll
    for (int kc = 1; kc < 8; kc++) {
        float4 v = *(const float4*)(P + kc * S + i);
        s.x += v.x; s.y += v.y; s.z += v.z; s.w += v.w;
    }
    *(float4*)(C + i) = s;
}

// ---------------------------------------------------------------------------
// Chunked parallel scan (R10-proven, unchanged)
// ---------------------------------------------------------------------------
__global__ __launch_bounds__(256) void scan_pass1(
    const float* __restrict__ delta, const float* __restrict__ u,
    const float* __restrict__ dbc, const float* __restrict__ A_log,
    float* __restrict__ P, float* __restrict__ H)
{
    const int tid  = threadIdx.x;
    const int lane = tid & 31;
    const int w    = tid >> 5;
    const int ng   = lane & 3;
    const int dl   = lane >> 2;
    const int d    = blockIdx.x * 64 + w * 8 + dl;
    const int c    = blockIdx.y;
    const int b    = blockIdx.z;

    float4 al = *(const float4*)(A_log + d * DSTATE + ng * 4);
    const float a0 = -__expf(al.x), a1 = -__expf(al.y);
    const float a2 = -__expf(al.z), a3 = -__expf(al.w);

    const size_t trow = (size_t)b * LSEQ + (size_t)c * TC;
    const float* dp  = delta + trow * DINNER + d;
    const float* up  = u     + trow * DINNER + d;
    const float* bcp = dbc   + trow * 96 + DTRANK + ng * 4;

    float h0 = 0.f, h1 = 0.f, h2 = 0.f, h3 = 0.f;
    float p0 = 1.f, p1 = 1.f, p2 = 1.f, p3 = 1.f;
    for (int t = 0; t < TC; t++) {
        float de = dp[(size_t)t * DINNER];
        float uu = up[(size_t)t * DINNER];
        float4 Bv = *(const float4*)(bcp + t * 96);
        float dA0 = __expf(de * a0), dA1 = __expf(de * a1);
        float dA2 = __expf(de * a2), dA3 = __expf(de * a3);
        float du = de * uu;
        p0 *= dA0; p1 *= dA1; p2 *= dA2; p3 *= dA3;
        h0 = fmaf(dA0, h0, du * Bv.x);
        h1 = fmaf(dA1, h1, du * Bv.y);
        h2 = fmaf(dA2, h2, du * Bv.z);
        h3 = fmaf(dA3, h3, du * Bv.w);
    }
    size_t o = (((size_t)b * NCH + c) * DINNER + d) * DSTATE + ng * 4;
    *(float4*)(P + o) = make_float4(p0, p1, p2, p3);
    *(float4*)(H + o) = make_float4(h0, h1, h2, h3);
}

__global__ __launch_bounds__(256) void scan_pass2(
    const float* __restrict__ P, const float* __restrict__ H,
    float* __restrict__ HIN)
{
    int idx = blockIdx.x * blockDim.x + threadIdx.x;
    int n = idx & 15;
    int d = (idx >> 4) & (DINNER - 1);
    int b = idx >> 15;
    float hin = 0.f;
#pragma unroll
    for (int c = 0; c < NCH; c++) {
        size_t o = (((size_t)b * NCH + c) * DINNER + d) * DSTATE + n;
        HIN[o] = hin;
        hin = fmaf(P[o], hin, H[o]);
    }
}

__global__ __launch_bounds__(256) void scan_pass3(
    const float* __restrict__ delta, const float* __restrict__ u,
    const float* __restrict__ dbc, const float* __restrict__ A_log,
    const float* __restrict__ Dp, const float* __restrict__ sres,
    const float* __restrict__ HIN, float* __restrict__ Y)
{
    const int tid  = threadIdx.x;
    const int lane = tid & 31;
    const int w    = tid >> 5;
    const int ng   = lane & 3;
    const int dl   = lane >> 2;
    const int d    = blockIdx.x * 64 + w * 8 + dl;
    const int c    = blockIdx.y;
    const int b    = blockIdx.z;

    float4 al = *(const float4*)(A_log + d * DSTATE + ng * 4);
    const float a0 = -__expf(al.x), a1 = -__expf(al.y);
    const float a2 = -__expf(al.z), a3 = -__expf(al.w);
    const float Dd = Dp[d];

    const size_t trow = (size_t)b * LSEQ + (size_t)c * TC;
    const float* dp  = delta + trow * DINNER + d;
    const float* up  = u     + trow * DINNER + d;
    const float* rp  = sres  + trow * DINNER + d;
    const float* bcp = dbc   + trow * 96 + DTRANK + ng * 4;
    float*       yp  = Y     + trow * DINNER + d;

    size_t o = (((size_t)b * NCH + c) * DINNER + d) * DSTATE + ng * 4;
    float4 hv = *(const float4*)(HIN + o);
    float h0 = hv.x, h1 = hv.y, h2 = hv.z, h3 = hv.w;

    for (int t = 0; t < TC; t++) {
        float de = dp[(size_t)t * DINNER];
        float uu = up[(size_t)t * DINNER];
        float4 Bv = *(const float4*)(bcp + t * 96);
        float4 Cv = *(const float4*)(bcp + t * 96 + DSTATE);
        float dA0 = __expf(de * a0), dA1 = __expf(de * a1);
        float dA2 = __expf(de * a2), dA3 = __expf(de * a3);
        float du = de * uu;
        h0 = fmaf(dA0, h0, du * Bv.x);
        h1 = fmaf(dA1, h1, du * Bv.y);
        h2 = fmaf(dA2, h2, du * Bv.z);
        h3 = fmaf(dA3, h3, du * Bv.w);
        float pp = h0 * Cv.x + h1 * Cv.y + h2 * Cv.z + h3 * Cv.w;
        pp += __shfl_xor_sync(0xffffffffu, pp, 1);
        pp += __shfl_xor_sync(0xffffffffu, pp, 2);
        if (ng == 0)
            yp[(size_t)t * DINNER] = fmaf(uu, Dd, pp) * rp[(size_t)t * DINNER];
    }
}

// ---------------------------------------------------------------------------
// Launch
// ---------------------------------------------------------------------------
extern "C" void kernel_launch(void* const* d_in, const int* in_sizes, int n_in,
                              void* d_out, int out_size)
{
    (void)in_sizes; (void)n_in; (void)out_size;
    const float* x      = (const float*)d_in[0];
    const float* W_in   = (const float*)d_in[1];
    const float* conv_k = (const float*)d_in[2];
    const float* conv_b = (const float*)d_in[3];
    const float* W_x    = (const float*)d_in[4];
    const float* W_dt   = (const float*)d_in[5];
    const float* b_dt   = (const float*)d_in[6];
    const float* A_log  = (const float*)d_in[7];
    const float* Dvec   = (const float*)d_in[8];
    const float* W_out  = (const float*)d_in[9];
    float* out = (float*)d_out;

    h16 *xh16, *xsh, *convTf, *winT, *woutT;
    float *sres, *u, *dbc, *dbcp, *delta, *y, *wdtT;
    float *scP, *scH, *scHi;
    cudaGetSymbolAddress((void**)&xh16,  g_xh16);
    cudaGetSymbolAddress((void**)&xsh,   g_xsh);
    cudaGetSymbolAddress((void**)&sres,  g_sres);
    cudaGetSymbolAddress((void**)&u,     g_u);
    cudaGetSymbolAddress((void**)&dbc,   g_dbc);
    cudaGetSymbolAddress((void**)&dbcp,  g_dbc_part);
    cudaGetSymbolAddress((void**)&delta, g_delta);
    cudaGetSymbolAddress((void**)&y,     g_y);
    cudaGetSymbolAddress((void**)&winT,  g_WinT);
    cudaGetSymbolAddress((void**)&convTf, g_convTf);
    cudaGetSymbolAddress((void**)&woutT, g_WoutT);
    cudaGetSymbolAddress((void**)&wdtT,  g_WdtT);
    cudaGetSymbolAddress((void**)&scP,   g_scanP);
    cudaGetSymbolAddress((void**)&scH,   g_scanH);
    cudaGetSymbolAddress((void**)&scHi,  g_scanHi);

    cudaFuncSetAttribute(conv_halo, cudaFuncAttributeMaxDynamicSharedMemorySize, CONV_SMEM);

    // 0) weight preprocessing + x fp16 conversion
    fused_transpose<<<dim3(128, 64, 7), dim3(32, 8)>>>(
        W_in, conv_k, W_out, W_dt, winT, convTf, woutT, wdtT);
    convert_x_kernel<<<(BLROWS * DMODEL / 8) / 256, 256>>>(x, xh16);

    // 1) GEMM1 (fp16 single, fp16 inputs): xs -> fp16, silu(res) -> sres
    mma_gemm<3, 2, 1, 1><<<dim3(32, 32), 256>>>(
        xh16, DMODEL, winT, DMODEL, sres, DINNER, DMODEL, nullptr, xsh);

    // 2) halo-fused grouped causal conv (fp16 single) + bias + silu
    conv_halo<<<dim3(16, 32), 256, CONV_SMEM>>>(
        xsh, convTf, conv_b, u);

    // 3) dbc = u @ W_x
    gemm_n96_partial<<<dim3(64, 8), 256>>>(u, W_x, dbcp);
    gemm_n96_reduce<<<(BLROWS * 96 / 4) / 256, 256>>>(dbcp, dbc);

    // 4) delta = clip(softplus(dt_raw @ W_dt + b_dt))  (bf16x3, exact)
    mma_gemm<1, 0, 0, 0><<<dim3(16, 32), 256>>>(
        dbc, 96, wdtT, DTRANK, delta, DINNER, DTRANK, b_dt, nullptr);

    // 5) chunked parallel scan (+ fused gate) -> y fp32
    scan_pass1<<<dim3(32, NCH, 2), 256>>>(delta, u, dbc, A_log, scP, scH);
    scan_pass2<<<256, 256>>>(scP, scH, scHi);
    scan_pass3<<<dim3(32, NCH, 2), 256>>>(delta, u, dbc, A_log, Dvec, sres, scHi, y);

    // 6) out = y @ W_out  (fp16 single; A fp32 y, B fp16)
    mma_gemm<0, 2, 0, 1><<<dim3(8, 32), 256>>>(
        y, DINNER, woutT, DINNER, out, DMODEL, DINNER, nullptr, nullptr);
}

// round 16
// speedup vs baseline: 3.1309x; 1.0488x over previous
#include <cuda_runtime.h>
#include <cuda_bf16.h>
#include <cuda_fp16.h>
#include <cstdint>

// Problem constants
#define BLROWS 4096   // B*L = 2*2048
#define LSEQ   2048
#define DMODEL 1024
#define DINNER 2048
#define DSTATE 16
#define DTRANK 64
#define NCH    16     // scan chunks
#define TC     128    // chunk length

typedef __nv_bfloat16 bf16;
typedef __half h16;

// ---------------------------------------------------------------------------
// Scratch (device globals)
// ---------------------------------------------------------------------------
__device__ h16   g_xh16[(size_t)BLROWS * DMODEL];    // x pre-converted fp16
__device__ h16   g_xsh[(size_t)BLROWS * DINNER];     // xs fp16 (from GEMM1)
__device__ float g_sres[(size_t)BLROWS * DINNER];
__device__ float g_u  [(size_t)BLROWS * DINNER];
__device__ float g_dbc[(size_t)BLROWS * 96];
__device__ float g_dbc_part[(size_t)8 * BLROWS * 96];
__device__ float g_delta[(size_t)BLROWS * DINNER];
__device__ float g_y [(size_t)BLROWS * DINNER];
// scan chunk scratch: [b][c][d][n]
__device__ float g_scanP [(size_t)2 * NCH * DINNER * DSTATE];
__device__ float g_scanH [(size_t)2 * NCH * DINNER * DSTATE];
__device__ float g_scanHi[(size_t)2 * NCH * DINNER * DSTATE];
// Transposed weights
__device__ h16   g_WinT [(size_t)4096 * 1024];                 // fp16
__device__ h16   g_convTf[(size_t)4 * 2048 * 1024];            // fp16
__device__ h16   g_WoutT[(size_t)1024 * 2048];                 // fp16
__device__ float g_WdtT [(size_t)2048 * 64];                   // fp32 (bf16x3)

// ---------------------------------------------------------------------------
// PTX helpers
// ---------------------------------------------------------------------------
__device__ __forceinline__ uint32_t smem_u32(const void* p) {
    uint32_t a;
    asm("{ .reg .u64 t; cvta.to.shared.u64 t, %1; cvt.u32.u64 %0, t; }"
        : "=r"(a) : "l"(p));
    return a;
}
__device__ __forceinline__ void ldsm4(uint32_t* r, uint32_t addr) {
    asm volatile("ldmatrix.sync.aligned.m8n8.x4.shared.b16 {%0,%1,%2,%3}, [%4];"
        : "=r"(r[0]), "=r"(r[1]), "=r"(r[2]), "=r"(r[3]) : "r"(addr));
}
__device__ __forceinline__ void mma16816(
    float& d0, float& d1, float& d2, float& d3,
    uint32_t a0, uint32_t a1, uint32_t a2, uint32_t a3,
    uint32_t b0, uint32_t b1)
{
    asm volatile(
        "mma.sync.aligned.m16n8k16.row.col.f32.bf16.bf16.f32 "
        "{%0,%1,%2,%3}, {%4,%5,%6,%7}, {%8,%9}, {%0,%1,%2,%3};"
        : "+f"(d0), "+f"(d1), "+f"(d2), "+f"(d3)
        : "r"(a0), "r"(a1), "r"(a2), "r"(a3), "r"(b0), "r"(b1));
}
__device__ __forceinline__ void mma16816h(
    float& d0, float& d1, float& d2, float& d3,
    uint32_t a0, uint32_t a1, uint32_t a2, uint32_t a3,
    uint32_t b0, uint32_t b1)
{
    asm volatile(
        "mma.sync.aligned.m16n8k16.row.col.f32.f16.f16.f32 "
        "{%0,%1,%2,%3}, {%4,%5,%6,%7}, {%8,%9}, {%0,%1,%2,%3};"
        : "+f"(d0), "+f"(d1), "+f"(d2), "+f"(d3)
        : "r"(a0), "r"(a1), "r"(a2), "r"(a3), "r"(b0), "r"(b1));
}
// bf16 2-way split of two floats -> packed bf16x2 (hi, lo)
__device__ __forceinline__ void split2(float x, float y, uint32_t& hi, uint32_t& lo) {
    bf16 hx = __float2bfloat16_rn(x);
    bf16 hy = __float2bfloat16_rn(y);
    __nv_bfloat162 h; h.x = hx; h.y = hy;
    __nv_bfloat162 l = __floats2bfloat162_rn(x - __bfloat162float(hx),
                                             y - __bfloat162float(hy));
    hi = *reinterpret_cast<uint32_t*>(&h);
    lo = *reinterpret_cast<uint32_t*>(&l);
}
__device__ __forceinline__ uint32_t pack_h2(float x, float y) {
    __half2 p = __floats2half2_rn(x, y);
    return *reinterpret_cast<uint32_t*>(&p);
}
// SMEM tile row = 64B (32 elems) in 4x16B chunks, xor-swizzled
__device__ __forceinline__ uint32_t swz(int row, int chunk) {
    return (uint32_t)((row << 6) + (((chunk ^ ((row >> 1) & 3)) & 3) << 4));
}
__device__ __forceinline__ float silu(float v) { return v / (1.f + __expf(-v)); }

// ---------------------------------------------------------------------------
// mma GEMM.  PREC=0: bf16x3 (fp32 in).  PREC=2: fp16 single-product.
// A16/B16: operand already fp16 in gmem (load direct, no cvt).
// EPI: 0 fp32 store; 1 softplus+clip(+bias); 3 GEMM1 dual out (xs fp16).
// ---------------------------------------------------------------------------
template <int EPI, int PREC, int A16, int B16>
__global__ __launch_bounds__(256) void mma_gemm(
    const void* __restrict__ Av, int lda,
    const void* __restrict__ Bv, int ldb,
    float* __restrict__ C, int ldc,
    int K, const float* __restrict__ bias,
    h16* __restrict__ xsh)
{
    __shared__ __align__(16) char sAhi[8192], sAlo[8192], sBhi[8192], sBlo[8192];

    const int tid  = threadIdx.x;
    const int lane = tid & 31;
    const int wid  = tid >> 5;
    const int wm   = wid & 1;
    const int wn   = wid >> 1;
    const int m0   = blockIdx.y * 128;
    const int n0   = blockIdx.x * 128;
    const int TOT  = K >> 5;

    const uint32_t aHiB = smem_u32(sAhi), aLoB = smem_u32(sAlo);
    const uint32_t bHiB = smem_u32(sBhi), bLoB = smem_u32(sBlo);

    const int a_r  = lane & 15;
    const int a_cx = lane >> 4;
    const int b_r  = (lane & 7) + ((lane >> 4) << 3);
    const int b_cx = (lane >> 3) & 1;

    float acc[4][4][4];
#pragma unroll
    for (int i = 0; i < 4; i++)
#pragma unroll
        for (int j = 0; j < 4; j++)
#pragma unroll
            for (int k = 0; k < 4; k++) acc[i][j][k] = 0.f;

    float4 pa[4], pb[4];
    uint4  qa[2], qb[2];

    auto load = [&](int kb) {
        if (A16) {
#pragma unroll
            for (int i = 0; i < 2; i++) {
                int c = tid + i * 256;
                int row = c >> 2, seg = c & 3;
                qa[i] = *(const uint4*)((const h16*)Av + (size_t)(m0 + row) * lda + kb * 32 + seg * 8);
            }
        } else {
#pragma unroll
            for (int i = 0; i < 4; i++) {
                int idx = tid + i * 256;
                int row = idx >> 3, seg = idx & 7;
                pa[i] = *(const float4*)((const float*)Av + (size_t)(m0 + row) * lda + kb * 32 + seg * 4);
            }
        }
        if (B16) {
#pragma unroll
            for (int i = 0; i < 2; i++) {
                int c = tid + i * 256;
                int row = c >> 2, seg = c & 3;
                qb[i] = *(const uint4*)((const h16*)Bv + (size_t)(n0 + row) * ldb + kb * 32 + seg * 8);
            }
        } else {
#pragma unroll
            for (int i = 0; i < 4; i++) {
                int idx = tid + i * 256;
                int row = idx >> 3, seg = idx & 7;
                pb[i] = *(const float4*)((const float*)Bv + (size_t)(n0 + row) * ldb + kb * 32 + seg * 4);
            }
        }
    };

    auto store = [&]() {
        if (A16) {
#pragma unroll
            for (int i = 0; i < 2; i++) {
                int c = tid + i * 256;
                int row = c >> 2, seg = c & 3;
                *(uint4*)(sAhi + swz(row, seg)) = qa[i];
            }
        } else {
#pragma unroll
            for (int i = 0; i < 4; i++) {
                int idx = tid + i * 256;
                int row = idx >> 3, seg = idx & 7;
                uint32_t off = swz(row, seg >> 1) + (seg & 1) * 8;
                uint2 h, l;
                if (PREC == 0) {
                    split2(pa[i].x, pa[i].y, h.x, l.x);
                    split2(pa[i].z, pa[i].w, h.y, l.y);
                    *(uint2*)(sAhi + off) = h;
                    *(uint2*)(sAlo + off) = l;
                } else {
                    h.x = pack_h2(pa[i].x, pa[i].y);
                    h.y = pack_h2(pa[i].z, pa[i].w);
                    *(uint2*)(sAhi + off) = h;
                }
            }
        }
        if (B16) {
#pragma unroll
            for (int i = 0; i < 2; i++) {
                int c = tid + i * 256;
                int row = c >> 2, seg = c & 3;
                *(uint4*)(sBhi + swz(row, seg)) = qb[i];
            }
        } else {
#pragma unroll
            for (int i = 0; i < 4; i++) {
                int idx = tid + i * 256;
                int row = idx >> 3, seg = idx & 7;
                uint32_t off = swz(row, seg >> 1) + (seg & 1) * 8;
                uint2 h, l;
                if (PREC == 0) {
                    split2(pb[i].x, pb[i].y, h.x, l.x);
                    split2(pb[i].z, pb[i].w, h.y, l.y);
                    *(uint2*)(sBhi + off) = h;
                    *(uint2*)(sBlo + off) = l;
                } else {
                    h.x = pack_h2(pb[i].x, pb[i].y);
                    h.y = pack_h2(pb[i].z, pb[i].w);
                    *(uint2*)(sBhi + off) = h;
                }
            }
        }
    };

    auto mma_block = [&]() {
#pragma unroll
        for (int ks = 0; ks < 2; ks++) {
            uint32_t a[4][4], bh[4][2];
#pragma unroll
            for (int mf = 0; mf < 4; mf++) {
                int row = wm * 64 + mf * 16 + a_r;
                ldsm4(a[mf], aHiB + swz(row, ks * 2 + a_cx));
            }
#pragma unroll
            for (int p = 0; p < 2; p++) {
                int row = wn * 32 + p * 16 + b_r;
                uint32_t t[4];
                ldsm4(t, bHiB + swz(row, ks * 2 + b_cx));
                bh[p * 2][0] = t[0]; bh[p * 2][1] = t[1];
                bh[p * 2 + 1][0] = t[2]; bh[p * 2 + 1][1] = t[3];
            }
#pragma unroll
            for (int mf = 0; mf < 4; mf++)
#pragma unroll
                for (int nf = 0; nf < 4; nf++) {
                    if (PREC == 0)
                        mma16816(acc[mf][nf][0], acc[mf][nf][1], acc[mf][nf][2], acc[mf][nf][3],
                                 a[mf][0], a[mf][1], a[mf][2], a[mf][3], bh[nf][0], bh[nf][1]);
                    else
                        mma16816h(acc[mf][nf][0], acc[mf][nf][1], acc[mf][nf][2], acc[mf][nf][3],
                                  a[mf][0], a[mf][1], a[mf][2], a[mf][3], bh[nf][0], bh[nf][1]);
                }
            if (PREC == 0) {
                uint32_t bx[4][2];
#pragma unroll
                for (int p = 0; p < 2; p++) {
                    int row = wn * 32 + p * 16 + b_r;
                    uint32_t t[4];
                    ldsm4(t, bLoB + swz(row, ks * 2 + b_cx));
                    bx[p * 2][0] = t[0]; bx[p * 2][1] = t[1];
                    bx[p * 2 + 1][0] = t[2]; bx[p * 2 + 1][1] = t[3];
                }
#pragma unroll
                for (int mf = 0; mf < 4; mf++)
#pragma unroll
                    for (int nf = 0; nf < 4; nf++)
                        mma16816(acc[mf][nf][0], acc[mf][nf][1], acc[mf][nf][2], acc[mf][nf][3],
                                 a[mf][0], a[mf][1], a[mf][2], a[mf][3], bx[nf][0], bx[nf][1]);
#pragma unroll
                for (int mf = 0; mf < 4; mf++) {
                    int row = wm * 64 + mf * 16 + a_r;
                    ldsm4(a[mf], aLoB + swz(row, ks * 2 + a_cx));
                }
#pragma unroll
                for (int mf = 0; mf < 4; mf++)
#pragma unroll
                    for (int nf = 0; nf < 4; nf++)
                        mma16816(acc[mf][nf][0], acc[mf][nf][1], acc[mf][nf][2], acc[mf][nf][3],
                                 a[mf][0], a[mf][1], a[mf][2], a[mf][3], bh[nf][0], bh[nf][1]);
            }
        }
    };

    load(0);
    store();
    __syncthreads();
    for (int it = 1; it < TOT; it++) {
        load(it);
        mma_block();
        __syncthreads();
        store();
        __syncthreads();
    }
    mma_block();

    // Epilogue
#pragma unroll
    for (int mf = 0; mf < 4; mf++) {
        int r = m0 + wm * 64 + mf * 16 + (lane >> 2);
#pragma unroll
        for (int nf = 0; nf < 4; nf++) {
            int c = n0 + wn * 32 + nf * 8 + (lane & 3) * 2;
            float v0 = acc[mf][nf][0], v1 = acc[mf][nf][1];
            float v2 = acc[mf][nf][2], v3 = acc[mf][nf][3];
            if (EPI == 1) {
                float b0 = bias[c], b1 = bias[c + 1];
                float x0 = v0 + b0, x1 = v1 + b1, x2 = v2 + b0, x3 = v3 + b1;
                v0 = fminf(fmaxf(fmaxf(x0, 0.f) + log1pf(__expf(-fabsf(x0))), 1e-3f), 0.1f);
                v1 = fminf(fmaxf(fmaxf(x1, 0.f) + log1pf(__expf(-fabsf(x1))), 1e-3f), 0.1f);
                v2 = fminf(fmaxf(fmaxf(x2, 0.f) + log1pf(__expf(-fabsf(x2))), 1e-3f), 0.1f);
                v3 = fminf(fmaxf(fmaxf(x3, 0.f) + log1pf(__expf(-fabsf(x3))), 1e-3f), 0.1f);
            }
            if (EPI == 3) {
                if (n0 < 2048) {     // xs half -> fp16 for conv
                    *(uint32_t*)(xsh + (size_t)r * 2048 + c)       = pack_h2(v0, v1);
                    *(uint32_t*)(xsh + (size_t)(r + 8) * 2048 + c) = pack_h2(v2, v3);
                } else {             // res half -> silu -> sres fp32
                    int cc = c - 2048;
                    *(float2*)(C + (size_t)r * ldc + cc)
                        = make_float2(silu(v0), silu(v1));
                    *(float2*)(C + (size_t)(r + 8) * ldc + cc)
                        = make_float2(silu(v2), silu(v3));
                }
            } else {
                *(float2*)(C + (size_t)r * ldc + c)       = make_float2(v0, v1);
                *(float2*)(C + (size_t)(r + 8) * ldc + c) = make_float2(v2, v3);
            }
        }
    }
}

// ---------------------------------------------------------------------------
// Halo-fused grouped causal conv, fp16 single-product.
// R16: tile 128m x 64n, 2 CTAs/SM (grid 32x32), acc[4][2][4].
// ---------------------------------------------------------------------------
#define CONV_STG  25088                      // 8704 (A) + 4*4096 (B)
#define CONV_SMEM (2 * CONV_STG + 1024)

__global__ __launch_bounds__(256, 2) void conv_halo(
    const h16* __restrict__ Ah,            // xs fp16 [4096,2048]
    const h16* __restrict__ Bf,            // convT fp16 [4][2048,1024]
    const float* __restrict__ bias, float* __restrict__ U)
{
    extern __shared__ char dyn[];
    const uint32_t rawb = smem_u32(dyn);
    const uint32_t base = (rawb + 1023u) & ~1023u;
    char* tp = dyn + (base - rawb);

    const int tid  = threadIdx.x;
    const int lane = tid & 31;
    const int wid  = tid >> 5;
    const int wm   = wid & 1;        // 2 warp-rows x 64 m
    const int wn   = wid >> 1;       // 4 warp-cols x 16 n
    const int m0   = blockIdx.y * 128;
    const int n0   = blockIdx.x * 64;
    const int colbase = (n0 >= 1024) ? 1024 : 0;
    const bool headok = (m0 & (LSEQ - 1)) != 0;

    const int a_r  = lane & 15;
    const int a_cx = lane >> 4;
    const int b_r  = (lane & 7) + ((lane >> 4) << 3);
    const int b_cx = (lane >> 3) & 1;

    float acc[4][2][4];
#pragma unroll
    for (int i = 0; i < 4; i++)
#pragma unroll
        for (int j = 0; j < 2; j++)
#pragma unroll
            for (int k = 0; k < 4; k++) acc[i][j][k] = 0.f;

    uint4 sa[3], rb1[2], rb2[2];

    auto loadA = [&](int kb) {
#pragma unroll
        for (int i = 0; i < 3; i++) {
            int c = tid + i * 256;
            if (i < 2 || c < 524) {
                int row = c >> 2, seg = c & 3;
                bool valid = headok || (row >= 3);
                long grow = (long)m0 - 3 + row;
                sa[i] = valid
                    ? *(const uint4*)(Ah + grow * 2048 + colbase + kb * 32 + seg * 8)
                    : make_uint4(0, 0, 0, 0);
            }
        }
    };
    auto stsA = [&](int s) {
        char* sb = tp + s * CONV_STG;
#pragma unroll
        for (int i = 0; i < 3; i++) {
            int c = tid + i * 256;
            if (i < 2 || c < 524) {
                int row = c >> 2, seg = c & 3;
                *(uint4*)(sb + swz(row, seg)) = sa[i];
            }
        }
    };
    // per half: 2 taps x (64 rows x 4 segs) = 512 chunks -> 2 per thread
    auto loadB = [&](int kb, int half, uint4* rb) {
#pragma unroll
        for (int i = 0; i < 2; i++) {
            int c = tid + i * 256;
            int tap = half * 2 + (c >> 8);
            int cc = c & 255;
            int row = cc >> 2, seg = cc & 3;
            rb[i] = *(const uint4*)(Bf + (size_t)tap * 2048 * 1024
                                       + (size_t)(n0 + row) * 1024 + kb * 32 + seg * 8);
        }
    };
    auto stsB = [&](int s, int half, uint4* rb) {
#pragma unroll
        for (int i = 0; i < 2; i++) {
            int c = tid + i * 256;
            int tap = half * 2 + (c >> 8);
            int cc = c & 255;
            int row = cc >> 2, seg = cc & 3;
            char* bb = tp + s * CONV_STG + 8704 + tap * 4096;
            *(uint4*)(bb + swz(row, seg)) = rb[i];
        }
    };
    auto mma_tap = [&](int s, int tap) {
        uint32_t aB = base + (uint32_t)s * CONV_STG;
        uint32_t bB = aB + 8704 + (uint32_t)tap * 4096;
#pragma unroll
        for (int ks = 0; ks < 2; ks++) {
            uint32_t a[4][4], bh[2][2];
#pragma unroll
            for (int mf = 0; mf < 4; mf++) {
                int row = wm * 64 + mf * 16 + a_r + tap;
                ldsm4(a[mf], aB + swz(row, ks * 2 + a_cx));
            }
            {
                int row = wn * 16 + b_r;
                uint32_t t[4];
                ldsm4(t, bB + swz(row, ks * 2 + b_cx));
                bh[0][0] = t[0]; bh[0][1] = t[1];
                bh[1][0] = t[2]; bh[1][1] = t[3];
            }
#pragma unroll
            for (int mf = 0; mf < 4; mf++)
#pragma unroll
                for (int nf = 0; nf < 2; nf++)
                    mma16816h(acc[mf][nf][0], acc[mf][nf][1], acc[mf][nf][2], acc[mf][nf][3],
                              a[mf][0], a[mf][1], a[mf][2], a[mf][3], bh[nf][0], bh[nf][1]);
        }
    };

    loadA(0); loadB(0, 0, rb1); loadB(0, 1, rb2);
    stsA(0); stsB(0, 0, rb1); stsB(0, 1, rb2);
    __syncthreads();

    for (int kb = 0; kb < 32; kb++) {
        int cur = kb & 1, nxt = cur ^ 1;
        bool more = (kb + 1) < 32;
        if (more) { loadA(kb + 1); loadB(kb + 1, 0, rb1); }
        mma_tap(cur, 0);
        mma_tap(cur, 1);
        if (more) { stsA(nxt); stsB(nxt, 0, rb1); loadB(kb + 1, 1, rb2); }
        mma_tap(cur, 2);
        mma_tap(cur, 3);
        if (more) stsB(nxt, 1, rb2);
        __syncthreads();
    }

#pragma unroll
    for (int mf = 0; mf < 4; mf++) {
        int r = m0 + wm * 64 + mf * 16 + (lane >> 2);
#pragma unroll
        for (int nf = 0; nf < 2; nf++) {
            int c = n0 + wn * 16 + nf * 8 + (lane & 3) * 2;
            float b0 = bias[c], b1 = bias[c + 1];
            float v0 = silu(acc[mf][nf][0] + b0);
            float v1 = silu(acc[mf][nf][1] + b1);
            float v2 = silu(acc[mf][nf][2] + b0);
            float v3 = silu(acc[mf][nf][3] + b1);
            *(float2*)(U + (size_t)r * DINNER + c)       = make_float2(v0, v1);
            *(float2*)(U + (size_t)(r + 8) * DINNER + c) = make_float2(v2, v3);
        }
    }
}

// ---------------------------------------------------------------------------
// Fused weight preprocessing (one launch); Win/Wout stored fp16
// ---------------------------------------------------------------------------
__global__ __launch_bounds__(256) void fused_transpose(
    const float* __restrict__ Win, const float* __restrict__ convk,
    const float* __restrict__ Wout, const float* __restrict__ Wdt,
    h16* __restrict__ winT, h16* __restrict__ cTf,
    h16* __restrict__ woutT, float* __restrict__ wdtT)
{
    int z = blockIdx.z;
    const float* src; int R, C;
    if (z == 0)      { src = Win;  R = 1024; C = 4096; }
    else if (z <= 4) { src = convk + (size_t)(z - 1) * 1024 * 2048; R = 1024; C = 2048; }
    else if (z == 5) { src = Wout; R = 2048; C = 1024; }
    else             { src = Wdt;  R = 64;   C = 2048; }
    if (blockIdx.x * 32 >= C || blockIdx.y * 32 >= R) return;

    __shared__ float t[32][33];
    int x = blockIdx.x * 32 + threadIdx.x;
#pragma unroll
    for (int j = 0; j < 4; j++) {
        int y = blockIdx.y * 32 + threadIdx.y + j * 8;
        t[threadIdx.y + j * 8][threadIdx.x] = src[(size_t)y * C + x];
    }
    __syncthreads();
    int x2 = blockIdx.y * 32 + threadIdx.x;
#pragma unroll
    for (int j = 0; j < 4; j++) {
        int y2 = blockIdx.x * 32 + threadIdx.y + j * 8;
        float v = t[threadIdx.x][threadIdx.y + j * 8];
        if (z == 0) {
            winT[(size_t)y2 * R + x2] = __float2half_rn(v);
        } else if (z <= 4) {
            cTf[(size_t)(z - 1) * 2048 * 1024 + (size_t)y2 * R + x2] = __float2half_rn(v);
        } else if (z == 5) {
            woutT[(size_t)y2 * R + x2] = __float2half_rn(v);
        } else {
            wdtT[(size_t)y2 * R + x2] = v;
        }
    }
}

// x fp32 -> fp16
__global__ __launch_bounds__(256) void convert_x_kernel(
    const float* __restrict__ src, h16* __restrict__ dst)
{
    size_t i = ((size_t)blockIdx.x * blockDim.x + threadIdx.x) * 8;
    float4 a = *(const float4*)(src + i);
    float4 b = *(const float4*)(src + i + 4);
    uint4 o;
    o.x = pack_h2(a.x, a.y);
    o.y = pack_h2(a.z, a.w);
    o.z = pack_h2(b.x, b.y);
    o.w = pack_h2(b.z, b.w);
    *(uint4*)(dst + i) = o;
}

// ---------------------------------------------------------------------------
// Split-K narrow GEMM (R9-proven, unchanged)
// ---------------------------------------------------------------------------
__global__ __launch_bounds__(256) void gemm_n96_partial(
    const float* __restrict__ A, const float* __restrict__ B,
    float* __restrict__ P)
{
    const int BK = 32, NN = 96, KC = 256, BM = 64;
    __shared__ float As[BK][BM];
    __shared__ float Bs[BK][NN];

    const int m0 = blockIdx.x * BM;
    const int kc = blockIdx.y;
    const int kbeg = kc * KC;
    const int tid = threadIdx.x;
    const int tx = tid & 15;
    const int ty = tid >> 4;

    float acc[4][6];
#pragma unroll
    for (int r = 0; r < 4; r++)
#pragma unroll
        for (int j = 0; j < 6; j++) acc[r][j] = 0.f;

    for (int k0 = kbeg; k0 < kbeg + KC; k0 += BK) {
#pragma unroll
        for (int i = 0; i < 2; i++) {
            int idx = tid + i * 256;
            int row = idx >> 3;
            int cv  = (idx & 7) * 4;
            float4 a = *(const float4*)(A + (size_t)(m0 + row) * DINNER + k0 + cv);
            As[cv + 0][row] = a.x; As[cv + 1][row] = a.y;
            As[cv + 2][row] = a.z; As[cv + 3][row] = a.w;
        }
#pragma unroll
        for (int i = 0; i < 3; i++) {
            int idx  = tid + i * 256;
            int rowB = idx / 24;
            int cv   = (idx % 24) * 4;
            *(float4*)(&Bs[rowB][cv]) =
                *(const float4*)(B + (size_t)(k0 + rowB) * NN + cv);
        }
        __syncthreads();
#pragma unroll
        for (int k = 0; k < BK; k++) {
            float a[4];
            *(float4*)a = *(const float4*)(&As[k][ty * 4]);
            float b[6];
            *(float2*)(b)     = *(const float2*)(&Bs[k][tx * 6]);
            *(float2*)(b + 2) = *(const float2*)(&Bs[k][tx * 6 + 2]);
            *(float2*)(b + 4) = *(const float2*)(&Bs[k][tx * 6 + 4]);
#pragma unroll
            for (int r = 0; r < 4; r++)
#pragma unroll
                for (int j = 0; j < 6; j++)
                    acc[r][j] = fmaf(a[r], b[j], acc[r][j]);
        }
        __syncthreads();
    }
    float* out = P + (size_t)kc * BLROWS * 96;
#pragma unroll
    for (int r = 0; r < 4; r++) {
        int m = m0 + ty * 4 + r;
#pragma unroll
        for (int j = 0; j < 6; j++)
            out[(size_t)m * 96 + tx * 6 + j] = acc[r][j];
    }
}

__global__ __launch_bounds__(256) void gemm_n96_reduce(
    const float* __restrict__ P, float* __restrict__ C)
{
    size_t i = ((size_t)blockIdx.x * blockDim.x + threadIdx.x) * 4;
    const size_t S = (size_t)BLROWS * 96;
    float4 s = *(const float4*)(P + i);
#pragma unroll
    for (int kc = 1; kc < 8; kc++) {
        float4 v = *(const float4*)(P + kc * S + i);
        s.x += v.x; s.y += v.y; s.z += v.z; s.w += v.w;
    }
    *(float4*)(C + i) = s;
}

// ---------------------------------------------------------------------------
// Chunked parallel scan (R10-proven, unchanged)
// ---------------------------------------------------------------------------
__global__ __launch_bounds__(256) void scan_pass1(
    const float* __restrict__ delta, const float* __restrict__ u,
    const float* __restrict__ dbc, const float* __restrict__ A_log,
    float* __restrict__ P, float* __restrict__ H)
{
    const int tid  = threadIdx.x;
    const int lane = tid & 31;
    const int w    = tid >> 5;
    const int ng   = lane & 3;
    const int dl   = lane >> 2;
    const int d    = blockIdx.x * 64 + w * 8 + dl;
    const int c    = blockIdx.y;
    const int b    = blockIdx.z;

    float4 al = *(const float4*)(A_log + d * DSTATE + ng * 4);
    const float a0 = -__expf(al.x), a1 = -__expf(al.y);
    const float a2 = -__expf(al.z), a3 = -__expf(al.w);

    const size_t trow = (size_t)b * LSEQ + (size_t)c * TC;
    const float* dp  = delta + trow * DINNER + d;
    const float* up  = u     + trow * DINNER + d;
    const float* bcp = dbc   + trow * 96 + DTRANK + ng * 4;

    float h0 = 0.f, h1 = 0.f, h2 = 0.f, h3 = 0.f;
    float p0 = 1.f, p1 = 1.f, p2 = 1.f, p3 = 1.f;
    for (int t = 0; t < TC; t++) {
        float de = dp[(size_t)t * DINNER];
        float uu = up[(size_t)t * DINNER];
        float4 Bv = *(const float4*)(bcp + t * 96);
        float dA0 = __expf(de * a0), dA1 = __expf(de * a1);
        float dA2 = __expf(de * a2), dA3 = __expf(de * a3);
        float du = de * uu;
        p0 *= dA0; p1 *= dA1; p2 *= dA2; p3 *= dA3;
        h0 = fmaf(dA0, h0, du * Bv.x);
        h1 = fmaf(dA1, h1, du * Bv.y);
        h2 = fmaf(dA2, h2, du * Bv.z);
        h3 = fmaf(dA3, h3, du * Bv.w);
    }
    size_t o = (((size_t)b * NCH + c) * DINNER + d) * DSTATE + ng * 4;
    *(float4*)(P + o) = make_float4(p0, p1, p2, p3);
    *(float4*)(H + o) = make_float4(h0, h1, h2, h3);
}

__global__ __launch_bounds__(256) void scan_pass2(
    const float* __restrict__ P, const float* __restrict__ H,
    float* __restrict__ HIN)
{
    int idx = blockIdx.x * blockDim.x + threadIdx.x;
    int n = idx & 15;
    int d = (idx >> 4) & (DINNER - 1);
    int b = idx >> 15;
    float hin = 0.f;
#pragma unroll
    for (int c = 0; c < NCH; c++) {
        size_t o = (((size_t)b * NCH + c) * DINNER + d) * DSTATE + n;
        HIN[o] = hin;
        hin = fmaf(P[o], hin, H[o]);
    }
}

__global__ __launch_bounds__(256) void scan_pass3(
    const float* __restrict__ delta, const float* __restrict__ u,
    const float* __restrict__ dbc, const float* __restrict__ A_log,
    const float* __restrict__ Dp, const float* __restrict__ sres,
    const float* __restrict__ HIN, float* __restrict__ Y)
{
    const int tid  = threadIdx.x;
    const int lane = tid & 31;
    const int w    = tid >> 5;
    const int ng   = lane & 3;
    const int dl   = lane >> 2;
    const int d    = blockIdx.x * 64 + w * 8 + dl;
    const int c    = blockIdx.y;
    const int b    = blockIdx.z;

    float4 al = *(const float4*)(A_log + d * DSTATE + ng * 4);
    const float a0 = -__expf(al.x), a1 = -__expf(al.y);
    const float a2 = -__expf(al.z), a3 = -__expf(al.w);
    const float Dd = Dp[d];

    const size_t trow = (size_t)b * LSEQ + (size_t)c * TC;
    const float* dp  = delta + trow * DINNER + d;
    const float* up  = u     + trow * DINNER + d;
    const float* rp  = sres  + trow * DINNER + d;
    const float* bcp = dbc   + trow * 96 + DTRANK + ng * 4;
    float*       yp  = Y     + trow * DINNER + d;

    size_t o = (((size_t)b * NCH + c) * DINNER + d) * DSTATE + ng * 4;
    float4 hv = *(const float4*)(HIN + o);
    float h0 = hv.x, h1 = hv.y, h2 = hv.z, h3 = hv.w;

    for (int t = 0; t < TC; t++) {
        float de = dp[(size_t)t * DINNER];
        float uu = up[(size_t)t * DINNER];
        float4 Bv = *(const float4*)(bcp + t * 96);
        float4 Cv = *(const float4*)(bcp + t * 96 + DSTATE);
        float dA0 = __expf(de * a0), dA1 = __expf(de * a1);
        float dA2 = __expf(de * a2), dA3 = __expf(de * a3);
        float du = de * uu;
        h0 = fmaf(dA0, h0, du * Bv.x);
        h1 = fmaf(dA1, h1, du * Bv.y);
        h2 = fmaf(dA2, h2, du * Bv.z);
        h3 = fmaf(dA3, h3, du * Bv.w);
        float pp = h0 * Cv.x + h1 * Cv.y + h2 * Cv.z + h3 * Cv.w;
        pp += __shfl_xor_sync(0xffffffffu, pp, 1);
        pp += __shfl_xor_sync(0xffffffffu, pp, 2);
        if (ng == 0)
            yp[(size_t)t * DINNER] = fmaf(uu, Dd, pp) * rp[(size_t)t * DINNER];
    }
}

// ---------------------------------------------------------------------------
// Launch
// ---------------------------------------------------------------------------
extern "C" void kernel_launch(void* const* d_in, const int* in_sizes, int n_in,
                              void* d_out, int out_size)
{
    (void)in_sizes; (void)n_in; (void)out_size;
    const float* x      = (const float*)d_in[0];
    const float* W_in   = (const float*)d_in[1];
    const float* conv_k = (const float*)d_in[2];
    const float* conv_b = (const float*)d_in[3];
    const float* W_x    = (const float*)d_in[4];
    const float* W_dt   = (const float*)d_in[5];
    const float* b_dt   = (const float*)d_in[6];
    const float* A_log  = (const float*)d_in[7];
    const float* Dvec   = (const float*)d_in[8];
    const float* W_out  = (const float*)d_in[9];
    float* out = (float*)d_out;

    h16 *xh16, *xsh, *convTf, *winT, *woutT;
    float *sres, *u, *dbc, *dbcp, *delta, *y, *wdtT;
    float *scP, *scH, *scHi;
    cudaGetSymbolAddress((void**)&xh16,  g_xh16);
    cudaGetSymbolAddress((void**)&xsh,   g_xsh);
    cudaGetSymbolAddress((void**)&sres,  g_sres);
    cudaGetSymbolAddress((void**)&u,     g_u);
    cudaGetSymbolAddress((void**)&dbc,   g_dbc);
    cudaGetSymbolAddress((void**)&dbcp,  g_dbc_part);
    cudaGetSymbolAddress((void**)&delta, g_delta);
    cudaGetSymbolAddress((void**)&y,     g_y);
    cudaGetSymbolAddress((void**)&winT,  g_WinT);
    cudaGetSymbolAddress((void**)&convTf, g_convTf);
    cudaGetSymbolAddress((void**)&woutT, g_WoutT);
    cudaGetSymbolAddress((void**)&wdtT,  g_WdtT);
    cudaGetSymbolAddress((void**)&scP,   g_scanP);
    cudaGetSymbolAddress((void**)&scH,   g_scanH);
    cudaGetSymbolAddress((void**)&scHi,  g_scanHi);

    cudaFuncSetAttribute(conv_halo, cudaFuncAttributeMaxDynamicSharedMemorySize, CONV_SMEM);

    // 0) weight preprocessing + x fp16 conversion
    fused_transpose<<<dim3(128, 64, 7), dim3(32, 8)>>>(
        W_in, conv_k, W_out, W_dt, winT, convTf, woutT, wdtT);
    convert_x_kernel<<<(BLROWS * DMODEL / 8) / 256, 256>>>(x, xh16);

    // 1) GEMM1 (fp16 single, fp16 inputs): xs -> fp16, silu(res) -> sres
    mma_gemm<3, 2, 1, 1><<<dim3(32, 32), 256>>>(
        xh16, DMODEL, winT, DMODEL, sres, DINNER, DMODEL, nullptr, xsh);

    // 2) halo-fused grouped causal conv (fp16 single, 128x64 tiles, occ 2)
    conv_halo<<<dim3(32, 32), 256, CONV_SMEM>>>(
        xsh, convTf, conv_b, u);

    // 3) dbc = u @ W_x
    gemm_n96_partial<<<dim3(64, 8), 256>>>(u, W_x, dbcp);
    gemm_n96_reduce<<<(BLROWS * 96 / 4) / 256, 256>>>(dbcp, dbc);

    // 4) delta = clip(softplus(dt_raw @ W_dt + b_dt))  (bf16x3, exact)
    mma_gemm<1, 0, 0, 0><<<dim3(16, 32), 256>>>(
        dbc, 96, wdtT, DTRANK, delta, DINNER, DTRANK, b_dt, nullptr);

    // 5) chunked parallel scan (+ fused gate) -> y fp32
    scan_pass1<<<dim3(32, NCH, 2), 256>>>(delta, u, dbc, A_log, scP, scH);
    scan_pass2<<<256, 256>>>(scP, scH, scHi);
    scan_pass3<<<dim3(32, NCH, 2), 256>>>(delta, u, dbc, A_log, Dvec, sres, scHi, y);

    // 6) out = y @ W_out  (fp16 single; A fp32 y, B fp16)
    mma_gemm<0, 2, 0, 1><<<dim3(8, 32), 256>>>(
        y, DINNER, woutT, DINNER, out, DMODEL, DINNER, nullptr, nullptr);
}